// round 15
// baseline (speedup 1.0000x reference)
#include <cuda_runtime.h>
#include <cuda_bf16.h>
#include <cstdint>

// ---------------- problem constants ----------------
#define NB   8
#define NT   336
#define NN   1024
#define FREQ 42
#define SEG  8
#define TREC 41
#define NSTEP 12
#define MAXK 11
#define ALPHA 0.05f
#define BETA  0.95f

// ---------------- scratch layout (floats) ----------------
static const size_t OFF_BSUM = 0;                         // 64
static const size_t OFF_EB   = 64;                        // 64
static const size_t OFF_A1H  = 128;
static const size_t OFF_A1L  = OFF_A1H  + 524288;
static const size_t OFF_A2H  = OFF_A1L  + 524288;
static const size_t OFF_A2L  = OFF_A2H  + 524288;
static const size_t OFF_A1TH = OFF_A2L  + 524288;
static const size_t OFF_A1TL = OFF_A1TH + 524288;
static const size_t OFF_A2TH = OFF_A1TL + 524288;
static const size_t OFF_A2TL = OFF_A2TH + 524288;
static const size_t OFF_Q1H  = OFF_A2TL + 524288;
static const size_t OFF_Q1L  = OFF_Q1H  + 524288;
static const size_t OFF_Q2H  = OFF_Q1L  + 524288;
static const size_t OFF_Q2L  = OFF_Q2H  + 524288;
static const size_t OFF_RES  = OFF_Q2L  + 524288;        // fp32 8*42*1024*64
static const size_t OFF_STOUT= OFF_RES  + 22020096;      // fp32 8*41*1024*64
static const size_t OFF_CUR  = OFF_STOUT+ 21495808;      // fp32 8*23*1024*64
static const size_t OFF_RESBH= OFF_CUR  + 12058624;      // bf16 8*42*1024*64
static const size_t OFF_RESBL= OFF_RESBH+ 11010048;
static const size_t OFF_CVBH = OFF_RESBL+ 11010048;      // bf16 rm 328*1024*64
static const size_t OFF_CVBL = OFF_CVBH + 10747904;
static const size_t OFF_CTH  = OFF_CVBL + 10747904;      // bf16 T 328*64*1024
static const size_t OFF_CTL  = OFF_CTH  + 10747904;
static const size_t OFF_RS1H = OFF_CTL  + 10747904;      // rec prop outs bf16 rm
static const size_t OFF_RS1L = OFF_RS1H + 10747904;
static const size_t OFF_RS2H = OFF_RS1L + 10747904;
static const size_t OFF_RS2L = OFF_RS2H + 10747904;
static const size_t OFF_RT1H = OFF_RS2L + 10747904;
static const size_t OFF_RT1L = OFF_RT1H + 10747904;
static const size_t OFF_RT2H = OFF_RT1L + 10747904;
static const size_t OFF_RT2L = OFF_RT2H + 10747904;
static const size_t OFF_TCTH = OFF_RT2L + 10747904;      // AR tcl T-planes
static const size_t OFF_TCTL = OFF_TCTH + 262144;
static const size_t OFF_ECTH = OFF_TCTL + 262144;
static const size_t OFF_ECTL = OFF_ECTH + 10240;
static const size_t OFF_WCTBH= OFF_ECTL + 10240;
static const size_t OFF_WCTBL= OFF_WCTBH+ 22528;
static const size_t OFF_CURBH= OFF_WCTBL+ 22528;
static const size_t OFF_CURBL= OFF_CURBH+ 6029312;
static const size_t OFF_XOH  = OFF_CURBL+ 6029312;
static const size_t OFF_XOL  = OFF_XOH  + 262144;
static const size_t OFF_S1H  = OFF_XOL  + 262144;
static const size_t OFF_S1L  = OFF_S1H  + 262144;
static const size_t OFF_S2H  = OFF_S1L  + 262144;
static const size_t OFF_S2L  = OFF_S2H  + 262144;
static const size_t OFF_T1H  = OFF_S2L  + 262144;
static const size_t OFF_T1L  = OFF_T1H  + 262144;
static const size_t OFF_T2H  = OFF_T1L  + 262144;
static const size_t OFF_T2L  = OFF_T2H  + 262144;
static const size_t SCRATCH_TOTAL = OFF_T2L + 262144;

__device__ float g_scratch[SCRATCH_TOTAL];

// ================= mma.sync helpers =================
__device__ __forceinline__ uint32_t smem_u32(const void* p) {
    uint32_t a;
    asm("{ .reg .u64 t; cvta.to.shared.u64 t, %1; cvt.u32.u64 %0, t; }" : "=r"(a) : "l"(p));
    return a;
}
__device__ __forceinline__ void mma16816(float* c, const uint32_t* a, const uint32_t* b) {
    asm volatile("mma.sync.aligned.m16n8k16.row.col.f32.bf16.bf16.f32 "
        "{%0,%1,%2,%3}, {%4,%5,%6,%7}, {%8,%9}, {%0,%1,%2,%3};"
        : "+f"(c[0]), "+f"(c[1]), "+f"(c[2]), "+f"(c[3])
        : "r"(a[0]), "r"(a[1]), "r"(a[2]), "r"(a[3]), "r"(b[0]), "r"(b[1]));
}
__device__ __forceinline__ void ldsm4(uint32_t* r, uint32_t addr) {
    asm volatile("ldmatrix.sync.aligned.m8n8.x4.shared.b16 {%0,%1,%2,%3}, [%4];"
        : "=r"(r[0]), "=r"(r[1]), "=r"(r[2]), "=r"(r[3]) : "r"(addr));
}
__device__ __forceinline__ void cpasync16(uint32_t dst, const void* src) {
    asm volatile("cp.async.cg.shared.global [%0], [%1], 16;" :: "r"(dst), "l"(src));
}
#define SAS 72
#define STG_AL 18432u
#define STG_BH 36864u
#define STG_BL 46080u
#define STG_SZ 55296u
// paired-prop stage offsets
#define P2_AL  18432u
#define P2_B0H 36864u
#define P2_B0L 46080u
#define P2_B1H 55296u
#define P2_B1L 64512u
#define P2_SZ  73728u
// quad-prop stage offsets
#define P4_AL  18432u
#define P4_B0  36864u      // each B pair: hi at +0, lo at +9216
#define P4_BSTEP 18432u
#define P4_SZ  110592u

// load A fragments (af[2][4][4] must be in scope)
#define MMA_ALOAD(AA) do {                                                     \
    _Pragma("unroll")                                                          \
    for (int mi = 0; mi < 2; mi++)                                             \
        _Pragma("unroll")                                                      \
        for (int kk = 0; kk < 4; kk++)                                         \
            ldsm4(af[mi][kk],                                                  \
                  (AA) + (uint32_t)(((wm * 32 + mi * 16 + lr) * SAS            \
                                     + kk * 16 + lc) * 2));                    \
} while (0)

// one B pass: load B fragments from AB and mma into ACC
#define MMA_BPASS(AB, ACC) do {                                                \
    uint32_t bfr[4][4][2];                                                     \
    _Pragma("unroll")                                                          \
    for (int np = 0; np < 2; np++)                                             \
        _Pragma("unroll")                                                      \
        for (int kk = 0; kk < 4; kk++) {                                       \
            uint32_t r[4];                                                     \
            ldsm4(r, (AB) + (uint32_t)(((wn * 32 + np * 16 + lr) * SAS         \
                                        + kk * 16 + lc) * 2));                 \
            bfr[2*np][kk][0]   = r[0]; bfr[2*np][kk][1]   = r[2];              \
            bfr[2*np+1][kk][0] = r[1]; bfr[2*np+1][kk][1] = r[3];              \
        }                                                                      \
    _Pragma("unroll")                                                          \
    for (int mi = 0; mi < 2; mi++)                                             \
        _Pragma("unroll")                                                      \
        for (int nf = 0; nf < 4; nf++)                                         \
            _Pragma("unroll")                                                  \
            for (int kk = 0; kk < 4; kk++)                                     \
                mma16816((ACC)[mi][nf], af[mi][kk], bfr[nf][kk]);              \
} while (0)

// B pass that also saves fragments into BSV[4][4][2]
#define MMA_BPASS_SAVE(AB, ACC, BSV) do {                                      \
    _Pragma("unroll")                                                          \
    for (int np = 0; np < 2; np++)                                             \
        _Pragma("unroll")                                                      \
        for (int kk = 0; kk < 4; kk++) {                                       \
            uint32_t r[4];                                                     \
            ldsm4(r, (AB) + (uint32_t)(((wn * 32 + np * 16 + lr) * SAS         \
                                        + kk * 16 + lc) * 2));                 \
            (BSV)[2*np][kk][0]   = r[0]; (BSV)[2*np][kk][1]   = r[2];          \
            (BSV)[2*np+1][kk][0] = r[1]; (BSV)[2*np+1][kk][1] = r[3];          \
        }                                                                      \
    _Pragma("unroll")                                                          \
    for (int mi = 0; mi < 2; mi++)                                             \
        _Pragma("unroll")                                                      \
        for (int nf = 0; nf < 4; nf++)                                         \
            _Pragma("unroll")                                                  \
            for (int kk = 0; kk < 4; kk++)                                     \
                mma16816((ACC)[mi][nf], af[mi][kk], (BSV)[nf][kk]);            \
} while (0)

// mma with previously saved B fragments
#define MMA_BREUSE(BSV, ACC) do {                                              \
    _Pragma("unroll")                                                          \
    for (int mi = 0; mi < 2; mi++)                                             \
        _Pragma("unroll")                                                      \
        for (int nf = 0; nf < 4; nf++)                                         \
            _Pragma("unroll")                                                  \
            for (int kk = 0; kk < 4; kk++)                                     \
                mma16816((ACC)[mi][nf], af[mi][kk], (BSV)[nf][kk]);            \
} while (0)

// hi/lo 3-pass mma over one 64-K chunk (A + Bh fragment reuse)
#define MMA_CHUNK3() do {                                                      \
    uint32_t af[2][4][4];                                                      \
    uint32_t bsv[4][4][2];                                                     \
    MMA_ALOAD(aAh);                                                            \
    MMA_BPASS_SAVE(aBh, acc, bsv);                                             \
    MMA_BPASS(aBl, acc);                                                       \
    MMA_ALOAD(aAl);                                                            \
    MMA_BREUSE(bsv, acc);                                                      \
} while (0)

// K=1024 pipelined issue (A row stride NN)
#define PIPE_ISSUE(K0, STB) do {                                               \
    _Pragma("unroll")                                                          \
    for (int it_ = 0; it_ < 4; it_++) {                                        \
        int li_ = tid + it_ * 256;                                             \
        int row_ = li_ >> 3, c8_ = li_ & 7;                                    \
        uint32_t da_ = (STB) + (uint32_t)(row_ * SAS + c8_ * 8) * 2;           \
        cpasync16(da_,          &Ah[(size_t)(m0 + row_) * NN + (K0) + c8_ * 8]);\
        cpasync16(da_ + STG_AL, &Al[(size_t)(m0 + row_) * NN + (K0) + c8_ * 8]);\
    }                                                                          \
    _Pragma("unroll")                                                          \
    for (int it_ = 0; it_ < 2; it_++) {                                        \
        int li_ = tid + it_ * 256;                                             \
        int row_ = li_ >> 3, c8_ = li_ & 7;                                    \
        uint32_t db_ = (STB) + STG_BH + (uint32_t)(row_ * SAS + c8_ * 8) * 2;  \
        cpasync16(db_,                    &Bh[(size_t)row_ * NN + (K0) + c8_ * 8]); \
        cpasync16(db_ + (STG_BL - STG_BH), &Bl[(size_t)row_ * NN + (K0) + c8_ * 8]); \
    }                                                                          \
    asm volatile("cp.async.commit_group;");                                    \
} while (0)

// small-K (64) issue: A/B row stride 64
__device__ __forceinline__ void sk_issue(const __nv_bfloat16* AH, const __nv_bfloat16* AL,
                                         const __nv_bfloat16* BH, const __nv_bfloat16* BL,
                                         uint32_t stb, int tid, bool withA) {
    if (withA) {
#pragma unroll
        for (int it = 0; it < 4; it++) {
            int li = tid + it * 256;
            int row = li >> 3, c8 = li & 7;
            uint32_t da = stb + (uint32_t)(row * SAS + c8 * 8) * 2;
            cpasync16(da,          &AH[row * 64 + c8 * 8]);
            cpasync16(da + STG_AL, &AL[row * 64 + c8 * 8]);
        }
    }
#pragma unroll
    for (int it = 0; it < 2; it++) {
        int li = tid + it * 256;
        int row = li >> 3, c8 = li & 7;
        uint32_t db = stb + STG_BH + (uint32_t)(row * SAS + c8 * 8) * 2;
        cpasync16(db,                     &BH[row * 64 + c8 * 8]);
        cpasync16(db + (STG_BL - STG_BH), &BL[row * 64 + c8 * 8]);
    }
    asm volatile("cp.async.commit_group;");
}

// paired-prop issue: A + 2 B-tiles (both row stride NN)
__device__ __forceinline__ void p2_issue(
        const __nv_bfloat16* Ah, const __nv_bfloat16* Al,
        const __nv_bfloat16* B0h, const __nv_bfloat16* B0l,
        const __nv_bfloat16* B1h, const __nv_bfloat16* B1l,
        int m0, int k0, uint32_t stb, int tid) {
#pragma unroll
    for (int it = 0; it < 4; it++) {
        int li = tid + it * 256;
        int row = li >> 3, c8 = li & 7;
        uint32_t da = stb + (uint32_t)(row * SAS + c8 * 8) * 2;
        cpasync16(da,         &Ah[(size_t)(m0 + row) * NN + k0 + c8 * 8]);
        cpasync16(da + P2_AL, &Al[(size_t)(m0 + row) * NN + k0 + c8 * 8]);
    }
#pragma unroll
    for (int it = 0; it < 2; it++) {
        int li = tid + it * 256;
        int row = li >> 3, c8 = li & 7;
        uint32_t db = stb + (uint32_t)(row * SAS + c8 * 8) * 2;
        cpasync16(db + P2_B0H, &B0h[(size_t)row * NN + k0 + c8 * 8]);
        cpasync16(db + P2_B0L, &B0l[(size_t)row * NN + k0 + c8 * 8]);
        cpasync16(db + P2_B1H, &B1h[(size_t)row * NN + k0 + c8 * 8]);
        cpasync16(db + P2_B1L, &B1l[(size_t)row * NN + k0 + c8 * 8]);
    }
    asm volatile("cp.async.commit_group;");
}

// quad-prop issue: A + 4 B-tiles (row stride NN). B pair i at P4_B0 + i*P4_BSTEP
// (hi at +0, lo at +9216).
__device__ __forceinline__ void p4_issue(
        const __nv_bfloat16* Ah, const __nv_bfloat16* Al,
        const __nv_bfloat16* const* Bhp, const __nv_bfloat16* const* Blp,
        int m0, int k0, uint32_t stb, int tid) {
#pragma unroll
    for (int it = 0; it < 4; it++) {
        int li = tid + it * 256;
        int row = li >> 3, c8 = li & 7;
        uint32_t da = stb + (uint32_t)(row * SAS + c8 * 8) * 2;
        cpasync16(da,         &Ah[(size_t)(m0 + row) * NN + k0 + c8 * 8]);
        cpasync16(da + P4_AL, &Al[(size_t)(m0 + row) * NN + k0 + c8 * 8]);
    }
#pragma unroll
    for (int it = 0; it < 2; it++) {
        int li = tid + it * 256;
        int row = li >> 3, c8 = li & 7;
        uint32_t db = stb + P4_B0 + (uint32_t)(row * SAS + c8 * 8) * 2;
#pragma unroll
        for (int i = 0; i < 4; i++) {
            cpasync16(db + (uint32_t)i * P4_BSTEP,
                      &Bhp[i][(size_t)row * NN + k0 + c8 * 8]);
            cpasync16(db + (uint32_t)i * P4_BSTEP + 9216u,
                      &Blp[i][(size_t)row * NN + k0 + c8 * 8]);
        }
    }
    asm volatile("cp.async.commit_group;");
}

#define MMA_MAINLOOP_PIPE() do {                                               \
    uint32_t sbase_ = smem_u32(sb);                                            \
    uint32_t stb_[2] = {sbase_, sbase_ + STG_SZ};                              \
    PIPE_ISSUE(0, stb_[0]);                                                    \
    for (int c_ = 0; c_ < 16; c_++) {                                          \
        if (c_ + 1 < 16) {                                                     \
            PIPE_ISSUE((c_ + 1) * 64, stb_[(c_ + 1) & 1]);                     \
            asm volatile("cp.async.wait_group 1;");                            \
        } else {                                                               \
            asm volatile("cp.async.wait_group 0;");                            \
        }                                                                      \
        __syncthreads();                                                       \
        uint32_t aAh = stb_[c_ & 1];                                           \
        uint32_t aAl = aAh + STG_AL;                                           \
        uint32_t aBh = aAh + STG_BH;                                           \
        uint32_t aBl = aAh + STG_BL;                                           \
        MMA_CHUNK3();                                                          \
        __syncthreads();                                                       \
    }                                                                          \
} while (0)

// variable-NC chunk-table pipelined loop (A always present)
#define MMA_CHUNKLOOP(NCV) do {                                                \
    sk_issue(cah[0], cal[0], cbh[0], cbl[0], stb[0], tid, true);               \
    for (int c = 0; c < (NCV); c++) {                                          \
        if (c + 1 < (NCV)) {                                                   \
            sk_issue(cah[c+1], cal[c+1], cbh[c+1], cbl[c+1],                   \
                     stb[(c+1) & 1], tid, true);                               \
            asm volatile("cp.async.wait_group 1;");                            \
        } else {                                                               \
            asm volatile("cp.async.wait_group 0;");                            \
        }                                                                      \
        __syncthreads();                                                       \
        uint32_t aAh = stb[c & 1];                                             \
        uint32_t aAl = aAh + STG_AL;                                           \
        uint32_t aBh = aAh + STG_BH;                                           \
        uint32_t aBl = aAh + STG_BL;                                           \
        MMA_CHUNK3();                                                          \
        __syncthreads();                                                       \
    }                                                                          \
} while (0)

// pointer T-plane writer (tbuf stride 65 floats)
#define TPLANE_WRITE_PTR(TB, OH, OL) do {                                      \
    int d_ = tid >> 2, nc_ = (tid & 3) * 32;                                   \
    size_t ob_ = (size_t)d_ * NN + m0 + nc_;                                   \
    _Pragma("unroll")                                                          \
    for (int q_ = 0; q_ < 32; q_ += 2) {                                       \
        float v0_ = (TB)[(nc_ + q_) * 65 + d_];                                \
        float v1_ = (TB)[(nc_ + q_ + 1) * 65 + d_];                            \
        __nv_bfloat16 h0_ = __float2bfloat16(v0_);                             \
        __nv_bfloat16 h1_ = __float2bfloat16(v1_);                             \
        __nv_bfloat16 l0_ = __float2bfloat16(v0_ - __bfloat162float(h0_));     \
        __nv_bfloat16 l1_ = __float2bfloat16(v1_ - __bfloat162float(h1_));     \
        *(__nv_bfloat162*)&(OH)[ob_ + q_] = __halves2bfloat162(h0_, h1_);      \
        *(__nv_bfloat162*)&(OL)[ob_ + q_] = __halves2bfloat162(l0_, l1_);      \
    }                                                                          \
} while (0)

// prop epilogue: acc -> bf16 hi/lo row-major
#define PROP_EPI(ACC, OH, OL) do {                                             \
    _Pragma("unroll")                                                          \
    for (int mi = 0; mi < 2; mi++) {                                           \
        int r0 = m0 + wm * 32 + mi * 16 + (lane >> 2);                         \
        _Pragma("unroll")                                                      \
        for (int nf = 0; nf < 4; nf++) {                                       \
            int d0 = wn * 32 + nf * 8 + (lane & 3) * 2;                        \
            _Pragma("unroll")                                                  \
            for (int half = 0; half < 2; half++) {                             \
                int r = r0 + half * 8;                                         \
                float v0 = (ACC)[mi][nf][half * 2];                            \
                float v1 = (ACC)[mi][nf][half * 2 + 1];                        \
                __nv_bfloat16 h0 = __float2bfloat16(v0);                       \
                __nv_bfloat16 h1 = __float2bfloat16(v1);                       \
                __nv_bfloat16 l0 = __float2bfloat16(v0 - __bfloat162float(h0));\
                __nv_bfloat16 l1 = __float2bfloat16(v1 - __bfloat162float(h1));\
                *(__nv_bfloat162*)&(OH)[(size_t)r * 64 + d0] =                 \
                    __halves2bfloat162(h0, h1);                                \
                *(__nv_bfloat162*)&(OL)[(size_t)r * 64 + d0] =                 \
                    __halves2bfloat162(l0, l1);                                \
            }                                                                  \
        }                                                                      \
    }                                                                          \
} while (0)

// ================= adjacency normalization =================
__global__ void k_norm_adj(const float* __restrict__ adj,
        __nv_bfloat16* __restrict__ a1h, __nv_bfloat16* __restrict__ a1l,
        __nv_bfloat16* __restrict__ a2h, __nv_bfloat16* __restrict__ a2l) {
    int v = blockIdx.x;
    int tid = threadIdx.x;
    __shared__ float r1[256], r2[256];
    float s1 = 0.f, s2 = 0.f;
    for (int n = tid; n < NN; n += 256) {
        s1 += adj[(size_t)v * NN + n];
        s2 += adj[(size_t)n * NN + v];
    }
    r1[tid] = s1; r2[tid] = s2;
    __syncthreads();
    for (int off = 128; off > 0; off >>= 1) {
        if (tid < off) { r1[tid] += r1[tid + off]; r2[tid] += r2[tid + off]; }
        __syncthreads();
    }
    float inv1 = 1.f / (r1[0] + 1.f);
    float inv2 = 1.f / (r2[0] + 1.f);
    for (int n = tid; n < NN; n += 256) {
        float d = (n == v) ? 1.f : 0.f;
        float v1 = (adj[(size_t)v * NN + n] + d) * inv1;
        float v2 = (adj[(size_t)n * NN + v] + d) * inv2;
        __nv_bfloat16 h1 = __float2bfloat16(v1);
        __nv_bfloat16 h2 = __float2bfloat16(v2);
        a1h[(size_t)v * NN + n] = h1;
        a1l[(size_t)v * NN + n] = __float2bfloat16(v1 - __bfloat162float(h1));
        a2h[(size_t)v * NN + n] = h2;
        a2l[(size_t)v * NN + n] = __float2bfloat16(v2 - __bfloat162float(h2));
    }
}

// ================= bf16 plane transpose =================
__global__ void __launch_bounds__(256) k_btrans(
        const __nv_bfloat16* __restrict__ i0, __nv_bfloat16* __restrict__ o0,
        const __nv_bfloat16* __restrict__ i1, __nv_bfloat16* __restrict__ o1,
        const __nv_bfloat16* __restrict__ i2, __nv_bfloat16* __restrict__ o2,
        const __nv_bfloat16* __restrict__ i3, __nv_bfloat16* __restrict__ o3) {
    const __nv_bfloat16* in;
    __nv_bfloat16* out;
    switch (blockIdx.z) {
        case 0: in = i0; out = o0; break;
        case 1: in = i1; out = o1; break;
        case 2: in = i2; out = o2; break;
        default: in = i3; out = o3; break;
    }
    int c0 = blockIdx.x * 64, r0 = blockIdx.y * 64;
    __shared__ __nv_bfloat16 t[64][72];
    int tid = threadIdx.x;
#pragma unroll
    for (int it = 0; it < 2; it++) {
        int li = tid + it * 256;
        int row = li >> 3, c8 = (li & 7) * 8;
        *(uint4*)&t[row][c8] = *(const uint4*)&in[(size_t)(r0 + row) * NN + c0 + c8];
    }
    __syncthreads();
#pragma unroll
    for (int it = 0; it < 2; it++) {
        int li = tid + it * 256;
        int c = li >> 3, r8 = (li & 7) * 8;
        __nv_bfloat16 v[8];
#pragma unroll
        for (int q = 0; q < 8; q++) v[q] = t[r8 + q][c];
        *(uint4*)&out[(size_t)(c0 + c) * NN + r0 + r8] = *(uint4*)v;
    }
}

// ================= A^2 precompute =================
__global__ void __launch_bounds__(256)
k_asq(const __nv_bfloat16* __restrict__ a1h, const __nv_bfloat16* __restrict__ a1l,
      const __nv_bfloat16* __restrict__ a1th, const __nv_bfloat16* __restrict__ a1tl,
      const __nv_bfloat16* __restrict__ a2h, const __nv_bfloat16* __restrict__ a2l,
      const __nv_bfloat16* __restrict__ a2th, const __nv_bfloat16* __restrict__ a2tl,
      __nv_bfloat16* __restrict__ q1h, __nv_bfloat16* __restrict__ q1l,
      __nv_bfloat16* __restrict__ q2h, __nv_bfloat16* __restrict__ q2l) {
    int m0 = blockIdx.x * 128;
    int n0 = blockIdx.y * 64;
    int mat = blockIdx.z;
    const __nv_bfloat16* Ah = mat ? a2h : a1h;
    const __nv_bfloat16* Al = mat ? a2l : a1l;
    const __nv_bfloat16* Bh = (mat ? a2th : a1th) + (size_t)n0 * NN;
    const __nv_bfloat16* Bl = (mat ? a2tl : a1tl) + (size_t)n0 * NN;
    __nv_bfloat16* qh = mat ? q2h : q1h;
    __nv_bfloat16* ql = mat ? q2l : q1l;

    extern __shared__ __nv_bfloat16 sb[];
    int tid = threadIdx.x, lane = tid & 31, wid = tid >> 5;
    int wm = wid >> 1, wn = wid & 1;
    int lr = lane & 15, lc = (lane >> 4) * 8;

    float acc[2][4][4];
#pragma unroll
    for (int i = 0; i < 2; i++)
#pragma unroll
        for (int j = 0; j < 4; j++)
#pragma unroll
            for (int q = 0; q < 4; q++) acc[i][j][q] = 0.f;

    MMA_MAINLOOP_PIPE();

#pragma unroll
    for (int mi = 0; mi < 2; mi++) {
        int r0 = m0 + wm * 32 + mi * 16 + (lane >> 2);
#pragma unroll
        for (int nf = 0; nf < 4; nf++) {
            int d0 = n0 + wn * 32 + nf * 8 + (lane & 3) * 2;
#pragma unroll
            for (int half = 0; half < 2; half++) {
                int rr = r0 + half * 8;
                float v0 = acc[mi][nf][half * 2], v1 = acc[mi][nf][half * 2 + 1];
                __nv_bfloat16 h0 = __float2bfloat16(v0), h1 = __float2bfloat16(v1);
                __nv_bfloat16 l0 = __float2bfloat16(v0 - __bfloat162float(h0));
                __nv_bfloat16 l1 = __float2bfloat16(v1 - __bfloat162float(h1));
                *(__nv_bfloat162*)&qh[(size_t)rr * NN + d0] = __halves2bfloat162(h0, h1);
                *(__nv_bfloat162*)&ql[(size_t)rr * NN + d0] = __halves2bfloat162(l0, l1);
            }
        }
    }
}

// ================= quad 4-way mma prop (4 bt per block, rec path) =============
__global__ void __launch_bounds__(256, 1)
k_prop4q(const __nv_bfloat16* __restrict__ a1h, const __nv_bfloat16* __restrict__ a1l,
         const __nv_bfloat16* __restrict__ q1h, const __nv_bfloat16* __restrict__ q1l,
         const __nv_bfloat16* __restrict__ a2h, const __nv_bfloat16* __restrict__ a2l,
         const __nv_bfloat16* __restrict__ q2h, const __nv_bfloat16* __restrict__ q2l,
         const __nv_bfloat16* __restrict__ bTh, const __nv_bfloat16* __restrict__ bTl,
         __nv_bfloat16* __restrict__ s1h, __nv_bfloat16* __restrict__ s1l,
         __nv_bfloat16* __restrict__ s2h, __nv_bfloat16* __restrict__ s2l,
         __nv_bfloat16* __restrict__ t1h, __nv_bfloat16* __restrict__ t1l,
         __nv_bfloat16* __restrict__ t2h, __nv_bfloat16* __restrict__ t2l) {
    int m0 = blockIdx.x * 128;
    int g0 = blockIdx.y * 4;
    int z  = blockIdx.z;
    const __nv_bfloat16 *Ah, *Al;
    __nv_bfloat16 *ohb, *olb;
    if (z == 0)      { Ah = a1h; Al = a1l; ohb = s1h; olb = s1l; }
    else if (z == 1) { Ah = q1h; Al = q1l; ohb = s2h; olb = s2l; }
    else if (z == 2) { Ah = a2h; Al = a2l; ohb = t1h; olb = t1l; }
    else             { Ah = q2h; Al = q2l; ohb = t2h; olb = t2l; }
    const __nv_bfloat16* Bhp[4];
    const __nv_bfloat16* Blp[4];
#pragma unroll
    for (int i = 0; i < 4; i++) {
        Bhp[i] = bTh + (size_t)(g0 + i) * 65536;
        Blp[i] = bTl + (size_t)(g0 + i) * 65536;
    }

    extern __shared__ __nv_bfloat16 sb[];
    uint32_t sbase = smem_u32(sb);
    uint32_t stb[2] = {sbase, sbase + P4_SZ};
    int tid = threadIdx.x, lane = tid & 31, wid = tid >> 5;
    int wm = wid >> 1, wn = wid & 1;
    int lr = lane & 15, lc = (lane >> 4) * 8;

    float accq[4][2][4][4];
#pragma unroll
    for (int g = 0; g < 4; g++)
#pragma unroll
        for (int i = 0; i < 2; i++)
#pragma unroll
            for (int j = 0; j < 4; j++)
#pragma unroll
                for (int q = 0; q < 4; q++) accq[g][i][j][q] = 0.f;

    p4_issue(Ah, Al, Bhp, Blp, m0, 0, stb[0], tid);
    for (int c = 0; c < 16; c++) {
        if (c + 1 < 16) {
            p4_issue(Ah, Al, Bhp, Blp, m0, (c + 1) * 64, stb[(c + 1) & 1], tid);
            asm volatile("cp.async.wait_group 1;");
        } else {
            asm volatile("cp.async.wait_group 0;");
        }
        __syncthreads();
        uint32_t s = stb[c & 1];
        uint32_t aAh = s, aAl = s + P4_AL;
        {
            uint32_t af[2][4][4];
            MMA_ALOAD(aAh);
#pragma unroll
            for (int g = 0; g < 4; g++)
                MMA_BPASS(s + P4_B0 + (uint32_t)g * P4_BSTEP, accq[g]);
#pragma unroll
            for (int g = 0; g < 4; g++)
                MMA_BPASS(s + P4_B0 + (uint32_t)g * P4_BSTEP + 9216u, accq[g]);
            MMA_ALOAD(aAl);
#pragma unroll
            for (int g = 0; g < 4; g++)
                MMA_BPASS(s + P4_B0 + (uint32_t)g * P4_BSTEP, accq[g]);
        }
        __syncthreads();
    }
#pragma unroll
    for (int g = 0; g < 4; g++) {
        __nv_bfloat16* oh = ohb + (size_t)(g0 + g) * 65536;
        __nv_bfloat16* ol = olb + (size_t)(g0 + g) * 65536;
        PROP_EPI(accq[g], oh, ol);
    }
}

// ================= paired 4-way mma prop (2 bt per block, AR path) ============
__global__ void __launch_bounds__(256)
k_prop4p(const __nv_bfloat16* __restrict__ a1h, const __nv_bfloat16* __restrict__ a1l,
         const __nv_bfloat16* __restrict__ q1h, const __nv_bfloat16* __restrict__ q1l,
         const __nv_bfloat16* __restrict__ a2h, const __nv_bfloat16* __restrict__ a2l,
         const __nv_bfloat16* __restrict__ q2h, const __nv_bfloat16* __restrict__ q2l,
         const __nv_bfloat16* __restrict__ bTh, const __nv_bfloat16* __restrict__ bTl,
         __nv_bfloat16* __restrict__ s1h, __nv_bfloat16* __restrict__ s1l,
         __nv_bfloat16* __restrict__ s2h, __nv_bfloat16* __restrict__ s2l,
         __nv_bfloat16* __restrict__ t1h, __nv_bfloat16* __restrict__ t1l,
         __nv_bfloat16* __restrict__ t2h, __nv_bfloat16* __restrict__ t2l) {
    int m0 = blockIdx.x * 128;
    int g0 = blockIdx.y * 2;
    int z  = blockIdx.z;
    const __nv_bfloat16 *Ah, *Al;
    __nv_bfloat16 *ohb, *olb;
    if (z == 0)      { Ah = a1h; Al = a1l; ohb = s1h; olb = s1l; }
    else if (z == 1) { Ah = q1h; Al = q1l; ohb = s2h; olb = s2l; }
    else if (z == 2) { Ah = a2h; Al = a2l; ohb = t1h; olb = t1l; }
    else             { Ah = q2h; Al = q2l; ohb = t2h; olb = t2l; }
    const __nv_bfloat16* B0h = bTh + (size_t)g0 * 65536;
    const __nv_bfloat16* B0l = bTl + (size_t)g0 * 65536;
    const __nv_bfloat16* B1h = B0h + 65536;
    const __nv_bfloat16* B1l = B0l + 65536;

    extern __shared__ __nv_bfloat16 sb[];
    uint32_t sbase = smem_u32(sb);
    uint32_t stb[2] = {sbase, sbase + P2_SZ};
    int tid = threadIdx.x, lane = tid & 31, wid = tid >> 5;
    int wm = wid >> 1, wn = wid & 1;
    int lr = lane & 15, lc = (lane >> 4) * 8;

    float acc0[2][4][4], acc1[2][4][4];
#pragma unroll
    for (int i = 0; i < 2; i++)
#pragma unroll
        for (int j = 0; j < 4; j++)
#pragma unroll
            for (int q = 0; q < 4; q++) { acc0[i][j][q] = 0.f; acc1[i][j][q] = 0.f; }

    p2_issue(Ah, Al, B0h, B0l, B1h, B1l, m0, 0, stb[0], tid);
    for (int c = 0; c < 16; c++) {
        if (c + 1 < 16) {
            p2_issue(Ah, Al, B0h, B0l, B1h, B1l, m0, (c + 1) * 64,
                     stb[(c + 1) & 1], tid);
            asm volatile("cp.async.wait_group 1;");
        } else {
            asm volatile("cp.async.wait_group 0;");
        }
        __syncthreads();
        uint32_t s = stb[c & 1];
        uint32_t aAh = s, aAl = s + P2_AL;
        uint32_t aB0h = s + P2_B0H, aB0l = s + P2_B0L;
        uint32_t aB1h = s + P2_B1H, aB1l = s + P2_B1L;
        {
            uint32_t af[2][4][4];
            MMA_ALOAD(aAh);
            MMA_BPASS(aB0h, acc0);
            MMA_BPASS(aB1h, acc1);
            MMA_BPASS(aB0l, acc0);
            MMA_BPASS(aB1l, acc1);
            MMA_ALOAD(aAl);
            MMA_BPASS(aB0h, acc0);
            MMA_BPASS(aB1h, acc1);
        }
        __syncthreads();
    }
    __nv_bfloat16* oh0 = ohb + (size_t)g0 * 65536;
    __nv_bfloat16* ol0 = olb + (size_t)g0 * 65536;
    __nv_bfloat16* oh1 = oh0 + 65536;
    __nv_bfloat16* ol1 = ol0 + 65536;
    PROP_EPI(acc0, oh0, ol0);
    PROP_EPI(acc1, oh1, ol1);
}

// ================= combine conv weights (bsum + transposed bf16) ==============
__global__ void k_comb_w(const float* w0, const float* w1, const float* w2,
                         const float* w3, const float* w4, const float* w5,
                         const float* cb0, const float* cb1, const float* cb2,
                         const float* cb3, const float* cb4, const float* cb5,
                         float* __restrict__ bsum,
                         __nv_bfloat16* __restrict__ wctbh,
                         __nv_bfloat16* __restrict__ wctbl) {
    int idx = blockIdx.x * 256 + threadIdx.x;
    if (idx >= 11 * 64 * 64) return;
    int o = idx & 63;
    int c = (idx >> 6) & 63;
    int dt = idx >> 12;
    int dv = dt - 5;
    int ad = dv < 0 ? -dv : dv;
    const float* ws[6] = {w0, w1, w2, w3, w4, w5};
    float acc = 0.f;
    for (int i = ad; i < 6; i++) {
        int K = 2 * i + 1;
        acc += ws[i][(size_t)(o * 64 + c) * K + (dv + i)];
    }
    __nv_bfloat16 h = __float2bfloat16(acc);
    wctbh[(size_t)dt * 4096 + o * 64 + c] = h;
    wctbl[(size_t)dt * 4096 + o * 64 + c] =
        __float2bfloat16(acc - __bfloat162float(h));
    if (dt == 0 && c == 0)
        bsum[o] = cb0[o] + cb1[o] + cb2[o] + cb3[o] + cb4[o] + cb5[o];
}

// ================= combine mixprop weights (eb + transposed bf16) =============
__global__ void k_comb_g(const float* __restrict__ g1w, const float* __restrict__ g1b,
                         const float* __restrict__ g2w, const float* __restrict__ g2b,
                         float* __restrict__ eb,
                         __nv_bfloat16* __restrict__ ecth,
                         __nv_bfloat16* __restrict__ ectl) {
    int idx = blockIdx.x * 256 + threadIdx.x;
    if (idx >= 5 * 4096) return;
    int term = idx >> 12;
    int co = idx & 4095;
    int c = co >> 6, o = co & 63;
    float v;
    if (term == 0) {
        v = g1w[co] + ALPHA * (g1w[4096 + co] + g1w[8192 + co])
          + g2w[co] + ALPHA * (g2w[4096 + co] + g2w[8192 + co]);
    } else if (term == 1) {
        v = BETA * g1w[4096 + co] + ALPHA * BETA * g1w[8192 + co];
    } else if (term == 2) {
        v = BETA * BETA * g1w[8192 + co];
    } else if (term == 3) {
        v = BETA * g2w[4096 + co] + ALPHA * BETA * g2w[8192 + co];
    } else {
        v = BETA * BETA * g2w[8192 + co];
    }
    __nv_bfloat16 h = __float2bfloat16(v);
    ecth[(size_t)term * 4096 + o * 64 + c] = h;
    ectl[(size_t)term * 4096 + o * 64 + c] =
        __float2bfloat16(v - __bfloat162float(h));
    if (idx < 64) eb[idx] = g1b[idx] + g2b[idx];
}

// ================= encoder MLP (emits fp32 res + bf16 hi/lo mirror) ============
__global__ void __launch_bounds__(256) k_enc2(const float* __restrict__ x,
        const float* __restrict__ w1, const float* __restrict__ b1,
        const float* __restrict__ w2, const float* __restrict__ b2,
        float* __restrict__ out,
        __nv_bfloat16* __restrict__ resbh, __nv_bfloat16* __restrict__ resbl) {
    extern __shared__ float sm[];
    float* xst = sm;
    float* w1s = xst + 8 * 132;
    float* hst = w1s + 1024;
    float* Bs  = hst + 128 * 132;
    int n0 = blockIdx.x * 128;
    int f  = blockIdx.y;
    int b  = blockIdx.z;
    int tid = threadIdx.x, tx = tid & 15, ty = tid >> 4;

#pragma unroll
    for (int it = 0; it < 4; it++) {
        int li = tid + it * 256;
        int s = li >> 7, m = li & 127;
        xst[s * 132 + m] = x[((size_t)b * NT + f * SEG + s) * NN + n0 + m];
        w1s[li] = w1[li];
    }
    __syncthreads();

    float acc1[8][8] = {};
#pragma unroll
    for (int k = 0; k < 8; k++) {
        float a_[8], b_[8];
        *(float4*)&a_[0] = *(const float4*)&w1s[k * 128 + ty * 4];
        *(float4*)&a_[4] = *(const float4*)&w1s[k * 128 + 64 + ty * 4];
        *(float4*)&b_[0] = *(const float4*)&xst[k * 132 + tx * 4];
        *(float4*)&b_[4] = *(const float4*)&xst[k * 132 + 64 + tx * 4];
#pragma unroll
        for (int i = 0; i < 8; i++)
#pragma unroll
            for (int j = 0; j < 8; j++)
                acc1[i][j] = fmaf(a_[i], b_[j], acc1[i][j]);
    }
#pragma unroll
    for (int i = 0; i < 8; i++) {
        int j = (i < 4) ? ty * 4 + i : 64 + ty * 4 + (i - 4);
        float bb = b1[j];
        float4 v0, v1;
        v0.x = fmaxf(acc1[i][0] + bb, 0.f); v0.y = fmaxf(acc1[i][1] + bb, 0.f);
        v0.z = fmaxf(acc1[i][2] + bb, 0.f); v0.w = fmaxf(acc1[i][3] + bb, 0.f);
        v1.x = fmaxf(acc1[i][4] + bb, 0.f); v1.y = fmaxf(acc1[i][5] + bb, 0.f);
        v1.z = fmaxf(acc1[i][6] + bb, 0.f); v1.w = fmaxf(acc1[i][7] + bb, 0.f);
        *(float4*)&hst[j * 132 + tx * 4]      = v0;
        *(float4*)&hst[j * 132 + 64 + tx * 4] = v1;
    }
    __syncthreads();

    float acc2[8][4] = {};
    for (int k0 = 0; k0 < 128; k0 += 16) {
        {
            int kk = tid >> 4, n4 = (tid & 15) * 4;
            *(float4*)&Bs[kk * 68 + n4] = *(const float4*)&w2[(size_t)(k0 + kk) * 64 + n4];
        }
        __syncthreads();
#pragma unroll
        for (int k = 0; k < 16; k++) {
            float a_[8], b_[4];
            *(float4*)&a_[0] = *(const float4*)&hst[(k0 + k) * 132 + ty * 4];
            *(float4*)&a_[4] = *(const float4*)&hst[(k0 + k) * 132 + 64 + ty * 4];
            *(float4*)&b_[0] = *(const float4*)&Bs[k * 68 + tx * 4];
#pragma unroll
            for (int i = 0; i < 8; i++)
#pragma unroll
                for (int j = 0; j < 4; j++)
                    acc2[i][j] = fmaf(a_[i], b_[j], acc2[i][j]);
        }
        __syncthreads();
    }
    float4 b2v = *(const float4*)&b2[tx * 4];
#pragma unroll
    for (int i = 0; i < 8; i++) {
        int m = n0 + ((i < 4) ? ty * 4 + i : 64 + ty * 4 + (i - 4));
        float va[4];
        va[0] = acc2[i][0] + b2v.x; va[1] = acc2[i][1] + b2v.y;
        va[2] = acc2[i][2] + b2v.z; va[3] = acc2[i][3] + b2v.w;
        size_t ri = (((size_t)b * FREQ + f) * NN + m) * 64 + tx * 4;
        *(float4*)&out[ri] = make_float4(va[0], va[1], va[2], va[3]);
        __nv_bfloat16 hh[4], ll[4];
#pragma unroll
        for (int q = 0; q < 4; q++) {
            hh[q] = __float2bfloat16(va[q]);
            ll[q] = __float2bfloat16(va[q] - __bfloat162float(hh[q]));
        }
        *(uint2*)&resbh[ri] = *(uint2*)hh;
        *(uint2*)&resbl[ri] = *(uint2*)ll;
    }
}

// ================= decoder MLP stage macros =================
#define DEC_STAGE1(SRC) do {                                                   \
    float acc1[8][8] = {};                                                     \
    for (int k0 = 0; k0 < 64; k0 += 16) {                                      \
        _Pragma("unroll")                                                      \
        for (int it = 0; it < 2; it++) {                                       \
            int f4 = tid + it * 256;                                           \
            int kk = f4 >> 5, j4 = (f4 & 31) * 4;                              \
            *(float4*)&As1[kk * 132 + j4] =                                    \
                *(const float4*)&w1[(size_t)(k0 + kk) * 128 + j4];             \
        }                                                                      \
        _Pragma("unroll")                                                      \
        for (int it = 0; it < 2; it++) {                                       \
            int li = tid + it * 256;                                           \
            int m = li & 127, k4 = li >> 7;                                    \
            float4 v = *(const float4*)&(SRC)[(size_t)m * 64 + k0 + k4 * 4];   \
            Bs1[(k4*4+0)*132 + m] = v.x; Bs1[(k4*4+1)*132 + m] = v.y;          \
            Bs1[(k4*4+2)*132 + m] = v.z; Bs1[(k4*4+3)*132 + m] = v.w;          \
        }                                                                      \
        __syncthreads();                                                       \
        _Pragma("unroll")                                                      \
        for (int k = 0; k < 16; k++) {                                         \
            float a_[8], b_[8];                                                \
            *(float4*)&a_[0] = *(const float4*)&As1[k * 132 + ty * 4];         \
            *(float4*)&a_[4] = *(const float4*)&As1[k * 132 + 64 + ty * 4];    \
            *(float4*)&b_[0] = *(const float4*)&Bs1[k * 132 + tx * 4];         \
            *(float4*)&b_[4] = *(const float4*)&Bs1[k * 132 + 64 + tx * 4];    \
            _Pragma("unroll")                                                  \
            for (int i = 0; i < 8; i++)                                        \
                _Pragma("unroll")                                              \
                for (int j = 0; j < 8; j++)                                    \
                    acc1[i][j] = fmaf(a_[i], b_[j], acc1[i][j]);               \
        }                                                                      \
        __syncthreads();                                                       \
    }                                                                          \
    _Pragma("unroll")                                                          \
    for (int i = 0; i < 8; i++) {                                              \
        int j = (i < 4) ? ty * 4 + i : 64 + ty * 4 + (i - 4);                  \
        float bb = b1[j];                                                      \
        float4 v0, v1;                                                         \
        v0.x = fmaxf(acc1[i][0] + bb, 0.f); v0.y = fmaxf(acc1[i][1] + bb, 0.f);\
        v0.z = fmaxf(acc1[i][2] + bb, 0.f); v0.w = fmaxf(acc1[i][3] + bb, 0.f);\
        v1.x = fmaxf(acc1[i][4] + bb, 0.f); v1.y = fmaxf(acc1[i][5] + bb, 0.f);\
        v1.z = fmaxf(acc1[i][6] + bb, 0.f); v1.w = fmaxf(acc1[i][7] + bb, 0.f);\
        *(float4*)&hst[j * 132 + tx * 4]      = v0;                            \
        *(float4*)&hst[j * 132 + 64 + tx * 4] = v1;                            \
    }                                                                          \
    __syncthreads();                                                           \
} while (0)

#define DEC_STAGE2(A4, M_, SG_) do {                                           \
    M_ = tid >> 1; SG_ = tid & 1;                                              \
    A4[0] = b2[SG_ * 4 + 0]; A4[1] = b2[SG_ * 4 + 1];                          \
    A4[2] = b2[SG_ * 4 + 2]; A4[3] = b2[SG_ * 4 + 3];                          \
    _Pragma("unroll 4")                                                        \
    for (int j = 0; j < 128; j++) {                                            \
        float h = hst[j * 132 + M_];                                           \
        float4 w = *(const float4*)&w2s[j * 8 + SG_ * 4];                      \
        A4[0] = fmaf(h, w.x, A4[0]); A4[1] = fmaf(h, w.y, A4[1]);              \
        A4[2] = fmaf(h, w.z, A4[2]); A4[3] = fmaf(h, w.w, A4[3]);              \
    }                                                                          \
} while (0)

// ================= decoder MLP for rec =================
__global__ void __launch_bounds__(256) k_dec_rec2(const float* __restrict__ res,
        const float* __restrict__ stout,
        const float* __restrict__ w1, const float* __restrict__ b1,
        const float* __restrict__ w2, const float* __restrict__ b2,
        float* __restrict__ out) {
    extern __shared__ float sm[];
    float* As1 = sm;
    float* Bs1 = As1 + 16 * 132;
    float* hst = Bs1 + 16 * 132;
    float* w2s = hst + 128 * 132;
    int n0 = blockIdx.x * 128;
    int f  = blockIdx.y;
    int b  = blockIdx.z;
    int tid = threadIdx.x, tx = tid & 15, ty = tid >> 4;
    const float* src = (f == 0)
        ? &res[(((size_t)b * FREQ) * NN + n0) * 64]
        : &stout[(((size_t)b * TREC + f - 1) * NN + n0) * 64];
#pragma unroll
    for (int it = 0; it < 4; it++) w2s[tid + it * 256] = w2[tid + it * 256];
    DEC_STAGE1(src);
    float a4[4];
    int m, sg;
    DEC_STAGE2(a4, m, sg);
#pragma unroll
    for (int q = 0; q < 4; q++) {
        int s = sg * 4 + q;
        out[((size_t)b * NT + f * SEG + s) * NN + n0 + m] = a4[q];
    }
}

// ================= decoder MLP for pred =================
__global__ void __launch_bounds__(256) k_dec_pred2(const float* __restrict__ cur,
        const float* __restrict__ w1, const float* __restrict__ b1,
        const float* __restrict__ w2, const float* __restrict__ b2,
        float* __restrict__ out) {
    extern __shared__ float sm[];
    float* As1 = sm;
    float* Bs1 = As1 + 16 * 132;
    float* hst = Bs1 + 16 * 132;
    float* w2s = hst + 128 * 132;
    int n0 = blockIdx.x * 128;
    int t  = blockIdx.y;
    int b  = blockIdx.z;
    int tid = threadIdx.x, tx = tid & 15, ty = tid >> 4;
    const float* src = &cur[(((size_t)b * 23 + MAXK + t) * NN + n0) * 64];
#pragma unroll
    for (int it = 0; it < 4; it++) w2s[tid + it * 256] = w2[tid + it * 256];
    DEC_STAGE1(src);
    float a4[4];
    int m, sg;
    DEC_STAGE2(a4, m, sg);
    float4 v = make_float4(a4[0], a4[1], a4[2], a4[3]);
    *(float4*)&out[(size_t)b * (NSTEP * SEG * NN) + (size_t)t * 8192
                   + (size_t)(n0 + m) * 8 + sg * 4] = v;
}

// ================= t_inception rec (mma, bf16 in/out) =================
__global__ void __launch_bounds__(256)
k_tconv_mma(const __nv_bfloat16* __restrict__ resbh, const __nv_bfloat16* __restrict__ resbl,
            const __nv_bfloat16* __restrict__ wctbh, const __nv_bfloat16* __restrict__ wctbl,
            const float* __restrict__ bsum,
            __nv_bfloat16* __restrict__ cvbh, __nv_bfloat16* __restrict__ cvbl,
            __nv_bfloat16* __restrict__ cth, __nv_bfloat16* __restrict__ ctl) {
    int m0 = blockIdx.x * 128;
    int bt = blockIdx.y;
    int b = bt / TREC, t = bt % TREC;
    extern __shared__ char dsm[];
    uint32_t sbase = smem_u32(dsm);
    uint32_t stb[2] = {sbase, sbase + STG_SZ};
    float* tbuf = (float*)dsm;          // reuses stage region after mainloop
    int tid = threadIdx.x, lane = tid & 31, wid = tid >> 5;
    int wm = wid >> 1, wn = wid & 1;
    int lr = lane & 15, lc = (lane >> 4) * 8;

    float acc[2][4][4];
#pragma unroll
    for (int i = 0; i < 2; i++)
#pragma unroll
        for (int j = 0; j < 4; j++)
#pragma unroll
            for (int q = 0; q < 4; q++) acc[i][j][q] = 0.f;

    const __nv_bfloat16 *cah[MAXK], *cal[MAXK], *cbh[MAXK], *cbl[MAXK];
    int NC = 0;
    for (int dt = 0; dt < MAXK; dt++) {
        int ts = t + dt - 5;
        if (ts < 0 || ts >= TREC) continue;
        size_t off = (((size_t)b * FREQ + ts) * NN + m0) * 64;
        cah[NC] = resbh + off;
        cal[NC] = resbl + off;
        cbh[NC] = wctbh + (size_t)dt * 4096;
        cbl[NC] = wctbl + (size_t)dt * 4096;
        NC++;
    }
    MMA_CHUNKLOOP(NC);

    const float inv6 = 1.f / 6.f;
    __nv_bfloat16* oh = cvbh + (size_t)bt * 65536;
    __nv_bfloat16* ol = cvbl + (size_t)bt * 65536;
#pragma unroll
    for (int mi = 0; mi < 2; mi++) {
        int rl0 = wm * 32 + mi * 16 + (lane >> 2);
#pragma unroll
        for (int nf = 0; nf < 4; nf++) {
            int d0 = wn * 32 + nf * 8 + (lane & 3) * 2;
            float bs0 = bsum[d0], bs1 = bsum[d0 + 1];
#pragma unroll
            for (int half = 0; half < 2; half++) {
                int rl = rl0 + half * 8;
                float v0 = (acc[mi][nf][half * 2]     + bs0) * inv6;
                float v1 = (acc[mi][nf][half * 2 + 1] + bs1) * inv6;
                tbuf[rl * 65 + d0] = v0; tbuf[rl * 65 + d0 + 1] = v1;
                __nv_bfloat16 h0 = __float2bfloat16(v0);
                __nv_bfloat16 h1 = __float2bfloat16(v1);
                __nv_bfloat16 l0 = __float2bfloat16(v0 - __bfloat162float(h0));
                __nv_bfloat16 l1 = __float2bfloat16(v1 - __bfloat162float(h1));
                size_t oi = (size_t)(m0 + rl) * 64 + d0;
                *(__nv_bfloat162*)&oh[oi] = __halves2bfloat162(h0, h1);
                *(__nv_bfloat162*)&ol[oi] = __halves2bfloat162(l0, l1);
            }
        }
    }
    __syncthreads();
    __nv_bfloat16* toh = cth + (size_t)bt * 65536;
    __nv_bfloat16* tol = ctl + (size_t)bt * 65536;
    TPLANE_WRITE_PTR(tbuf, toh, tol);
}

// ================= combine rec (mma) =================
__global__ void __launch_bounds__(256)
k_combine_mma(const __nv_bfloat16* __restrict__ xh, const __nv_bfloat16* __restrict__ xl,
              const __nv_bfloat16* __restrict__ s1h, const __nv_bfloat16* __restrict__ s1l,
              const __nv_bfloat16* __restrict__ s2h, const __nv_bfloat16* __restrict__ s2l,
              const __nv_bfloat16* __restrict__ t1h, const __nv_bfloat16* __restrict__ t1l,
              const __nv_bfloat16* __restrict__ t2h, const __nv_bfloat16* __restrict__ t2l,
              const __nv_bfloat16* __restrict__ ecth, const __nv_bfloat16* __restrict__ ectl,
              const float* __restrict__ eb,
              const float* __restrict__ res, float* __restrict__ stout) {
    int m0 = blockIdx.x * 128;
    int bt = blockIdx.y;
    extern __shared__ char dsm[];
    uint32_t sbase = smem_u32(dsm);
    uint32_t stb[2] = {sbase, sbase + STG_SZ};
    int tid = threadIdx.x, lane = tid & 31, wid = tid >> 5;
    int wm = wid >> 1, wn = wid & 1;
    int lr = lane & 15, lc = (lane >> 4) * 8;

    float acc[2][4][4];
#pragma unroll
    for (int i = 0; i < 2; i++)
#pragma unroll
        for (int j = 0; j < 4; j++)
#pragma unroll
            for (int q = 0; q < 4; q++) acc[i][j][q] = 0.f;

    const __nv_bfloat16 *cah[5], *cal[5], *cbh[5], *cbl[5];
    size_t xb = ((size_t)bt * NN + m0) * 64;
    cah[0] = xh  + xb; cal[0] = xl  + xb;
    cah[1] = s1h + xb; cal[1] = s1l + xb;
    cah[2] = s2h + xb; cal[2] = s2l + xb;
    cah[3] = t1h + xb; cal[3] = t1l + xb;
    cah[4] = t2h + xb; cal[4] = t2l + xb;
#pragma unroll
    for (int j = 0; j < 5; j++) {
        cbh[j] = ecth + (size_t)j * 4096;
        cbl[j] = ectl + (size_t)j * 4096;
    }
    MMA_CHUNKLOOP(5);

    int rrow = (bt / TREC) * FREQ + (bt % TREC);   // resid row = b*42 + t
#pragma unroll
    for (int mi = 0; mi < 2; mi++) {
        int rl0 = wm * 32 + mi * 16 + (lane >> 2);
#pragma unroll
        for (int nf = 0; nf < 4; nf++) {
            int d0 = wn * 32 + nf * 8 + (lane & 3) * 2;
            float e0 = eb[d0], e1 = eb[d0 + 1];
#pragma unroll
            for (int half = 0; half < 2; half++) {
                int m = m0 + rl0 + half * 8;
                float2 rv = *(const float2*)&res[((size_t)rrow * NN + m) * 64 + d0];
                float v0 = acc[mi][nf][half * 2]     + e0 + rv.x;
                float v1 = acc[mi][nf][half * 2 + 1] + e1 + rv.y;
                *(float2*)&stout[((size_t)bt * NN + m) * 64 + d0] = make_float2(v0, v1);
            }
        }
    }
}

// ===== shared epilogue2 for mma tcl =====
#define TCL_EPI2() do {                                                        \
    const float inv6_ = 1.f / 6.f;                                             \
    __nv_bfloat16* xho_ = xoh + (size_t)b * 65536;                             \
    __nv_bfloat16* xlo_ = xol + (size_t)b * 65536;                             \
    _Pragma("unroll")                                                          \
    for (int mi = 0; mi < 2; mi++) {                                           \
        int rl0 = wm * 32 + mi * 16 + (lane >> 2);                             \
        _Pragma("unroll")                                                      \
        for (int nf = 0; nf < 4; nf++) {                                       \
            int d0 = wn * 32 + nf * 8 + (lane & 3) * 2;                        \
            float bs0 = bsum[d0], bs1 = bsum[d0 + 1];                          \
            _Pragma("unroll")                                                  \
            for (int half = 0; half < 2; half++) {                             \
                int rl = rl0 + half * 8;                                       \
                float v0 = (acc[mi][nf][half * 2]     + bs0) * inv6_;          \
                float v1 = (acc[mi][nf][half * 2 + 1] + bs1) * inv6_;          \
                tbuf[rl * 65 + d0] = v0; tbuf[rl * 65 + d0 + 1] = v1;          \
                __nv_bfloat16 h0 = __float2bfloat16(v0);                       \
                __nv_bfloat16 h1 = __float2bfloat16(v1);                       \
                __nv_bfloat16 l0 = __float2bfloat16(v0 - __bfloat162float(h0));\
                __nv_bfloat16 l1 = __float2bfloat16(v1 - __bfloat162float(h1));\
                size_t oi = (size_t)(m0 + rl) * 64 + d0;                       \
                *(__nv_bfloat162*)&xho_[oi] = __halves2bfloat162(h0, h1);      \
                *(__nv_bfloat162*)&xlo_[oi] = __halves2bfloat162(l0, l1);      \
            }                                                                  \
        }                                                                      \
    }                                                                          \
    __syncthreads();                                                           \
    __nv_bfloat16* toh_ = tclth + (size_t)b * 65536;                           \
    __nv_bfloat16* tol_ = tcltl + (size_t)b * 65536;                           \
    TPLANE_WRITE_PTR(tbuf, toh_, tol_);                                        \
} while (0)

// ================= AR tcl step 0 (mma) =================
__global__ void __launch_bounds__(256)
k_tcl0_mma(const __nv_bfloat16* __restrict__ curbh, const __nv_bfloat16* __restrict__ curbl,
           const __nv_bfloat16* __restrict__ wctbh, const __nv_bfloat16* __restrict__ wctbl,
           const float* __restrict__ bsum,
           __nv_bfloat16* __restrict__ tclth, __nv_bfloat16* __restrict__ tcltl,
           __nv_bfloat16* __restrict__ xoh, __nv_bfloat16* __restrict__ xol) {
    int m0 = blockIdx.x * 128;
    int b  = blockIdx.y;
    extern __shared__ char dsm[];
    uint32_t sbase = smem_u32(dsm);
    uint32_t stb[2] = {sbase, sbase + STG_SZ};
    float* tbuf = (float*)dsm;
    int tid = threadIdx.x, lane = tid & 31, wid = tid >> 5;
    int wm = wid >> 1, wn = wid & 1;
    int lr = lane & 15, lc = (lane >> 4) * 8;

    float acc[2][4][4];
#pragma unroll
    for (int i = 0; i < 2; i++)
#pragma unroll
        for (int j = 0; j < 4; j++)
#pragma unroll
            for (int q = 0; q < 4; q++) acc[i][j][q] = 0.f;

    const __nv_bfloat16 *cah[6], *cal[6], *cbh[6], *cbl[6];
#pragma unroll
    for (int j = 0; j < 6; j++) {
        size_t off = ((size_t)(b * 23 + 5 + j) * NN + m0) * 64;
        cah[j] = curbh + off;
        cal[j] = curbl + off;
        cbh[j] = wctbh + (size_t)j * 4096;
        cbl[j] = wctbl + (size_t)j * 4096;
    }
    MMA_CHUNKLOOP(6);
    TCL_EPI2();
}

// ================= fused AR combine(step s) + tcl(step s+1) (mma) =============
__global__ void __launch_bounds__(256)
k_comb_tcl_mma(const __nv_bfloat16* __restrict__ xh, const __nv_bfloat16* __restrict__ xl,
               const __nv_bfloat16* __restrict__ s1h, const __nv_bfloat16* __restrict__ s1l,
               const __nv_bfloat16* __restrict__ s2h, const __nv_bfloat16* __restrict__ s2l,
               const __nv_bfloat16* __restrict__ t1h, const __nv_bfloat16* __restrict__ t1l,
               const __nv_bfloat16* __restrict__ t2h, const __nv_bfloat16* __restrict__ t2l,
               const __nv_bfloat16* __restrict__ ecth, const __nv_bfloat16* __restrict__ ectl,
               const float* __restrict__ eb,
               const __nv_bfloat16* __restrict__ wctbh, const __nv_bfloat16* __restrict__ wctbl,
               const float* __restrict__ bsum,
               float* __restrict__ cur,
               __nv_bfloat16* __restrict__ curbh, __nv_bfloat16* __restrict__ curbl,
               __nv_bfloat16* __restrict__ tclth, __nv_bfloat16* __restrict__ tcltl,
               __nv_bfloat16* __restrict__ xoh, __nv_bfloat16* __restrict__ xol,
               int s) {
    int m0 = blockIdx.x * 128;
    int b  = blockIdx.y;
    extern __shared__ char dsm[];
    uint32_t sbase = smem_u32(dsm);
    uint32_t stb[2] = {sbase, sbase + STG_SZ};
    __nv_bfloat16* xsh = (__nv_bfloat16*)(dsm + 2 * STG_SZ);
    __nv_bfloat16* xsl = (__nv_bfloat16*)(dsm + 2 * STG_SZ + 18432);
    uint32_t axsh = sbase + 2 * STG_SZ;
    uint32_t axsl = axsh + 18432;
    float* tbuf = (float*)dsm;           // reuse stage region after mainloop
    int tid = threadIdx.x, lane = tid & 31, wid = tid >> 5;
    int wm = wid >> 1, wn = wid & 1;
    int lr = lane & 15, lc = (lane >> 4) * 8;

    float acc[2][4][4];
#pragma unroll
    for (int i = 0; i < 2; i++)
#pragma unroll
        for (int j = 0; j < 4; j++)
#pragma unroll
            for (int q = 0; q < 4; q++) acc[i][j][q] = 0.f;

    const __nv_bfloat16* cah[10];
    const __nv_bfloat16* cal[10];
    size_t xb = ((size_t)b * NN + m0) * 64;
    cah[0] = xh  + xb; cal[0] = xl  + xb;
    cah[1] = s1h + xb; cal[1] = s1l + xb;
    cah[2] = s2h + xb; cal[2] = s2l + xb;
    cah[3] = t1h + xb; cal[3] = t1l + xb;
    cah[4] = t2h + xb; cal[4] = t2l + xb;
#pragma unroll
    for (int j = 0; j < 5; j++) {
        size_t off = ((size_t)(b * 23 + s + 6 + j) * NN + m0) * 64;
        cah[5 + j] = curbh + off;
        cal[5 + j] = curbl + off;
    }
    const int NC = (s == NSTEP - 1) ? 5 : 11;

    sk_issue(cah[0], cal[0], ecth, ectl, stb[0], tid, true);
    for (int c = 0; c < NC; c++) {
        if (c + 1 < NC) {
            const __nv_bfloat16 *nbh, *nbl;
            int cn = c + 1;
            if (cn < 5) { nbh = ecth + (size_t)cn * 4096; nbl = ectl + (size_t)cn * 4096; }
            else        { nbh = wctbh + (size_t)(cn - 5) * 4096; nbl = wctbl + (size_t)(cn - 5) * 4096; }
            bool withA = (cn != 10);
            sk_issue(withA ? cah[cn] : cah[0], withA ? cal[cn] : cal[0],
                     nbh, nbl, stb[cn & 1], tid, withA);
            asm volatile("cp.async.wait_group 1;");
        } else {
            asm volatile("cp.async.wait_group 0;");
        }
        __syncthreads();
        uint32_t aAh = (c == 10) ? axsh : stb[c & 1];
        uint32_t aAl = (c == 10) ? axsl : (stb[c & 1] + STG_AL);
        uint32_t aBh = stb[c & 1] + STG_BH;
        uint32_t aBl = stb[c & 1] + STG_BL;
        MMA_CHUNK3();
        __syncthreads();
        if (c == 4) {
            const float* curr = cur + (size_t)(b * 23 + s + 10) * NN * 64;
            float* curw = cur + (size_t)(b * 23 + s + 11) * NN * 64;
            __nv_bfloat16* cbh2 = curbh + (size_t)(b * 23 + s + 11) * NN * 64;
            __nv_bfloat16* cbl2 = curbl + (size_t)(b * 23 + s + 11) * NN * 64;
#pragma unroll
            for (int mi = 0; mi < 2; mi++) {
                int rl0 = wm * 32 + mi * 16 + (lane >> 2);
#pragma unroll
                for (int nf = 0; nf < 4; nf++) {
                    int d0 = wn * 32 + nf * 8 + (lane & 3) * 2;
                    float e0 = eb[d0], e1 = eb[d0 + 1];
#pragma unroll
                    for (int half = 0; half < 2; half++) {
                        int rl = rl0 + half * 8;
                        int m = m0 + rl;
                        float2 rv = *(const float2*)&curr[(size_t)m * 64 + d0];
                        float v0 = acc[mi][nf][half * 2]     + e0 + rv.x;
                        float v1 = acc[mi][nf][half * 2 + 1] + e1 + rv.y;
                        *(float2*)&curw[(size_t)m * 64 + d0] = make_float2(v0, v1);
                        __nv_bfloat16 h0 = __float2bfloat16(v0);
                        __nv_bfloat16 h1 = __float2bfloat16(v1);
                        __nv_bfloat16 l0 = __float2bfloat16(v0 - __bfloat162float(h0));
                        __nv_bfloat16 l1 = __float2bfloat16(v1 - __bfloat162float(h1));
                        *(__nv_bfloat162*)&cbh2[(size_t)m * 64 + d0] = __halves2bfloat162(h0, h1);
                        *(__nv_bfloat162*)&cbl2[(size_t)m * 64 + d0] = __halves2bfloat162(l0, l1);
                        *(__nv_bfloat162*)&xsh[rl * SAS + d0] = __halves2bfloat162(h0, h1);
                        *(__nv_bfloat162*)&xsl[rl * SAS + d0] = __halves2bfloat162(l0, l1);
                    }
                }
            }
#pragma unroll
            for (int i = 0; i < 2; i++)
#pragma unroll
                for (int j = 0; j < 4; j++)
#pragma unroll
                    for (int q = 0; q < 4; q++) acc[i][j][q] = 0.f;
            __syncthreads();
        }
    }
    if (NC == 11) {
        TCL_EPI2();
    }
}

// ================= AR cur-buffer init (+ bf16 mirror) =================
__global__ void k_cur_init(const float* __restrict__ res, float* __restrict__ cur,
                           __nv_bfloat16* __restrict__ curbh,
                           __nv_bfloat16* __restrict__ curbl) {
    size_t total = (size_t)NB * MAXK * NN * 64;
    for (size_t idx = (size_t)blockIdx.x * blockDim.x + threadIdx.x; idx < total;
         idx += (size_t)gridDim.x * blockDim.x) {
        int d = idx & 63;
        int n = (idx >> 6) & 1023;
        int j = (int)((idx >> 16) % MAXK);
        int b = (int)(idx / ((size_t)MAXK << 16));
        float v = res[(((size_t)b * FREQ + 31 + j) * NN + n) * 64 + d];
        size_t dst = (((size_t)b * 23 + j) * NN + n) * 64 + d;
        cur[dst] = v;
        __nv_bfloat16 h = __float2bfloat16(v);
        curbh[dst] = h;
        curbl[dst] = __float2bfloat16(v - __bfloat162float(h));
    }
}

// ================= host launcher =================
extern "C" void kernel_launch(void* const* d_in, const int* in_sizes, int n_in,
                              void* d_out, int out_size) {
    (void)in_sizes; (void)n_in; (void)out_size;
    const float* x_diff = (const float*)d_in[0];
    const float* adj    = (const float*)d_in[1];
    const float* enc_w1 = (const float*)d_in[2];
    const float* enc_b1 = (const float*)d_in[3];
    const float* enc_w2 = (const float*)d_in[4];
    const float* enc_b2 = (const float*)d_in[5];
    const float* dec_w1 = (const float*)d_in[6];
    const float* dec_b1 = (const float*)d_in[7];
    const float* dec_w2 = (const float*)d_in[8];
    const float* dec_b2 = (const float*)d_in[9];
    const float* g1_w   = (const float*)d_in[10];
    const float* g1_b   = (const float*)d_in[11];
    const float* g2_w   = (const float*)d_in[12];
    const float* g2_b   = (const float*)d_in[13];
    const float* cw[6], *cb[6];
    for (int i = 0; i < 6; i++) {
        cw[i] = (const float*)d_in[14 + 2 * i];
        cb[i] = (const float*)d_in[15 + 2 * i];
    }

    float* scratch = nullptr;
    cudaGetSymbolAddress((void**)&scratch, g_scratch);
    float* bsum  = scratch + OFF_BSUM;
    float* eb    = scratch + OFF_EB;
    __nv_bfloat16* a1h  = (__nv_bfloat16*)(scratch + OFF_A1H);
    __nv_bfloat16* a1l  = (__nv_bfloat16*)(scratch + OFF_A1L);
    __nv_bfloat16* a2h  = (__nv_bfloat16*)(scratch + OFF_A2H);
    __nv_bfloat16* a2l  = (__nv_bfloat16*)(scratch + OFF_A2L);
    __nv_bfloat16* a1th = (__nv_bfloat16*)(scratch + OFF_A1TH);
    __nv_bfloat16* a1tl = (__nv_bfloat16*)(scratch + OFF_A1TL);
    __nv_bfloat16* a2th = (__nv_bfloat16*)(scratch + OFF_A2TH);
    __nv_bfloat16* a2tl = (__nv_bfloat16*)(scratch + OFF_A2TL);
    __nv_bfloat16* q1h  = (__nv_bfloat16*)(scratch + OFF_Q1H);
    __nv_bfloat16* q1l  = (__nv_bfloat16*)(scratch + OFF_Q1L);
    __nv_bfloat16* q2h  = (__nv_bfloat16*)(scratch + OFF_Q2H);
    __nv_bfloat16* q2l  = (__nv_bfloat16*)(scratch + OFF_Q2L);
    float* res   = scratch + OFF_RES;
    float* stout = scratch + OFF_STOUT;
    float* cur   = scratch + OFF_CUR;
    __nv_bfloat16* resbh = (__nv_bfloat16*)(scratch + OFF_RESBH);
    __nv_bfloat16* resbl = (__nv_bfloat16*)(scratch + OFF_RESBL);
    __nv_bfloat16* cvbh  = (__nv_bfloat16*)(scratch + OFF_CVBH);
    __nv_bfloat16* cvbl  = (__nv_bfloat16*)(scratch + OFF_CVBL);
    __nv_bfloat16* cth   = (__nv_bfloat16*)(scratch + OFF_CTH);
    __nv_bfloat16* ctl   = (__nv_bfloat16*)(scratch + OFF_CTL);
    __nv_bfloat16* rs1h  = (__nv_bfloat16*)(scratch + OFF_RS1H);
    __nv_bfloat16* rs1l  = (__nv_bfloat16*)(scratch + OFF_RS1L);
    __nv_bfloat16* rs2h  = (__nv_bfloat16*)(scratch + OFF_RS2H);
    __nv_bfloat16* rs2l  = (__nv_bfloat16*)(scratch + OFF_RS2L);
    __nv_bfloat16* rt1h  = (__nv_bfloat16*)(scratch + OFF_RT1H);
    __nv_bfloat16* rt1l  = (__nv_bfloat16*)(scratch + OFF_RT1L);
    __nv_bfloat16* rt2h  = (__nv_bfloat16*)(scratch + OFF_RT2H);
    __nv_bfloat16* rt2l  = (__nv_bfloat16*)(scratch + OFF_RT2L);
    __nv_bfloat16* tclth = (__nv_bfloat16*)(scratch + OFF_TCTH);
    __nv_bfloat16* tcltl = (__nv_bfloat16*)(scratch + OFF_TCTL);
    __nv_bfloat16* ecth  = (__nv_bfloat16*)(scratch + OFF_ECTH);
    __nv_bfloat16* ectl  = (__nv_bfloat16*)(scratch + OFF_ECTL);
    __nv_bfloat16* wctbh = (__nv_bfloat16*)(scratch + OFF_WCTBH);
    __nv_bfloat16* wctbl = (__nv_bfloat16*)(scratch + OFF_WCTBL);
    __nv_bfloat16* curbh = (__nv_bfloat16*)(scratch + OFF_CURBH);
    __nv_bfloat16* curbl = (__nv_bfloat16*)(scratch + OFF_CURBL);
    __nv_bfloat16* xoh   = (__nv_bfloat16*)(scratch + OFF_XOH);
    __nv_bfloat16* xol   = (__nv_bfloat16*)(scratch + OFF_XOL);
    __nv_bfloat16* s1h   = (__nv_bfloat16*)(scratch + OFF_S1H);
    __nv_bfloat16* s1l   = (__nv_bfloat16*)(scratch + OFF_S1L);
    __nv_bfloat16* s2h   = (__nv_bfloat16*)(scratch + OFF_S2H);
    __nv_bfloat16* s2l   = (__nv_bfloat16*)(scratch + OFF_S2L);
    __nv_bfloat16* t1h   = (__nv_bfloat16*)(scratch + OFF_T1H);
    __nv_bfloat16* t1l   = (__nv_bfloat16*)(scratch + OFF_T1L);
    __nv_bfloat16* t2h   = (__nv_bfloat16*)(scratch + OFF_T2H);
    __nv_bfloat16* t2l   = (__nv_bfloat16*)(scratch + OFF_T2L);

    float* rec_out  = (float*)d_out;
    float* pred_out = rec_out + (size_t)NB * NT * NN;

    const int ENC_SMEM = (8 * 132 + 1024 + 128 * 132 + 16 * 68) * 4;
    const int DEC_SMEM = (16 * 132 * 2 + 128 * 132 + 128 * 8) * 4;
    const int MMA_SMEM = 2 * STG_SZ;                 // 110592
    const int P2_SMEM  = 2 * P2_SZ;                  // 147456 (AR paired prop)
    const int P4_SMEM  = 2 * P4_SZ;                  // 221184 (rec quad prop)
    const int CT_SMEM  = 2 * STG_SZ + 36864;         // 147456 (comb_tcl)
    cudaFuncSetAttribute(k_enc2, cudaFuncAttributeMaxDynamicSharedMemorySize, ENC_SMEM);
    cudaFuncSetAttribute(k_dec_rec2, cudaFuncAttributeMaxDynamicSharedMemorySize, DEC_SMEM);
    cudaFuncSetAttribute(k_dec_pred2, cudaFuncAttributeMaxDynamicSharedMemorySize, DEC_SMEM);
    cudaFuncSetAttribute(k_prop4p, cudaFuncAttributeMaxDynamicSharedMemorySize, P2_SMEM);
    cudaFuncSetAttribute(k_prop4q, cudaFuncAttributeMaxDynamicSharedMemorySize, P4_SMEM);
    cudaFuncSetAttribute(k_asq, cudaFuncAttributeMaxDynamicSharedMemorySize, MMA_SMEM);
    cudaFuncSetAttribute(k_tconv_mma, cudaFuncAttributeMaxDynamicSharedMemorySize, MMA_SMEM);
    cudaFuncSetAttribute(k_combine_mma, cudaFuncAttributeMaxDynamicSharedMemorySize, MMA_SMEM);
    cudaFuncSetAttribute(k_tcl0_mma, cudaFuncAttributeMaxDynamicSharedMemorySize, MMA_SMEM);
    cudaFuncSetAttribute(k_comb_tcl_mma, cudaFuncAttributeMaxDynamicSharedMemorySize, CT_SMEM);

    // ---- preprocessing ----
    k_norm_adj<<<NN, 256>>>(adj, a1h, a1l, a2h, a2l);
    k_btrans<<<dim3(16, 16, 4), 256>>>(a1h, a1th, a1l, a1tl, a2h, a2th, a2l, a2tl);
    k_comb_w<<<(11 * 64 * 64 + 255) / 256, 256>>>(cw[0], cw[1], cw[2], cw[3], cw[4], cw[5],
                                                  cb[0], cb[1], cb[2], cb[3], cb[4], cb[5],
                                                  bsum, wctbh, wctbl);
    k_comb_g<<<80, 256>>>(g1_w, g1_b, g2_w, g2_b, eb, ecth, ectl);
    k_asq<<<dim3(8, 16, 2), 256, MMA_SMEM>>>(a1h, a1l, a1th, a1tl,
                                             a2h, a2l, a2th, a2tl,
                                             q1h, q1l, q2h, q2l);

    // ---- encoder ----
    k_enc2<<<dim3(8, FREQ, NB), 256, ENC_SMEM>>>(x_diff, enc_w1, enc_b1, enc_w2, enc_b2,
                                                 res, resbh, resbl);

    // ---- rec-path stconv (all mma) ----
    k_tconv_mma<<<dim3(8, NB * TREC), 256, MMA_SMEM>>>(resbh, resbl, wctbh, wctbl, bsum,
                                                       cvbh, cvbl, cth, ctl);
    k_prop4q<<<dim3(8, NB * TREC / 4, 4), 256, P4_SMEM>>>(
        a1h, a1l, q1h, q1l, a2h, a2l, q2h, q2l,
        cth, ctl, rs1h, rs1l, rs2h, rs2l, rt1h, rt1l, rt2h, rt2l);
    k_combine_mma<<<dim3(8, NB * TREC), 256, MMA_SMEM>>>(
        cvbh, cvbl, rs1h, rs1l, rs2h, rs2l, rt1h, rt1l, rt2h, rt2l,
        ecth, ectl, eb, res, stout);
    // ---- rec decoder ----
    k_dec_rec2<<<dim3(8, FREQ, NB), 256, DEC_SMEM>>>(res, stout, dec_w1, dec_b1,
                                                     dec_w2, dec_b2, rec_out);

    // ---- autoregressive loop ----
    k_cur_init<<<4096, 256>>>(res, cur, curbh, curbl);
    k_tcl0_mma<<<dim3(8, NB), 256, MMA_SMEM>>>(curbh, curbl, wctbh, wctbl, bsum,
                                               tclth, tcltl, xoh, xol);
    for (int s = 0; s < NSTEP; s++) {
        k_prop4p<<<dim3(8, NB / 2, 4), 256, P2_SMEM>>>(
            a1h, a1l, q1h, q1l, a2h, a2l, q2h, q2l,
            tclth, tcltl, s1h, s1l, s2h, s2l, t1h, t1l, t2h, t2l);
        k_comb_tcl_mma<<<dim3(8, NB), 256, CT_SMEM>>>(
            xoh, xol, s1h, s1l, s2h, s2l, t1h, t1l, t2h, t2l,
            ecth, ectl, eb, wctbh, wctbl, bsum,
            cur, curbh, curbl, tclth, tcltl, xoh, xol, s);
    }
    // ---- pred decoder ----
    k_dec_pred2<<<dim3(8, NSTEP, NB), 256, DEC_SMEM>>>(cur, dec_w1, dec_b1,
                                                       dec_w2, dec_b2, pred_out);
}

// round 16
// speedup vs baseline: 1.0110x; 1.0110x over previous
#include <cuda_runtime.h>
#include <cuda_bf16.h>
#include <cstdint>

// ---------------- problem constants ----------------
#define NB   8
#define NT   336
#define NN   1024
#define FREQ 42
#define SEG  8
#define TREC 41
#define NSTEP 12
#define MAXK 11
#define ALPHA 0.05f
#define BETA  0.95f

// ---------------- scratch layout (floats) ----------------
static const size_t OFF_BSUM = 0;                         // 64
static const size_t OFF_EB   = 64;                        // 64
static const size_t OFF_A1H  = 128;
static const size_t OFF_A1L  = OFF_A1H  + 524288;
static const size_t OFF_A2H  = OFF_A1L  + 524288;
static const size_t OFF_A2L  = OFF_A2H  + 524288;
static const size_t OFF_A1TH = OFF_A2L  + 524288;
static const size_t OFF_A1TL = OFF_A1TH + 524288;
static const size_t OFF_A2TH = OFF_A1TL + 524288;
static const size_t OFF_A2TL = OFF_A2TH + 524288;
static const size_t OFF_Q1H  = OFF_A2TL + 524288;
static const size_t OFF_Q1L  = OFF_Q1H  + 524288;
static const size_t OFF_Q2H  = OFF_Q1L  + 524288;
static const size_t OFF_Q2L  = OFF_Q2H  + 524288;
static const size_t OFF_RES  = OFF_Q2L  + 524288;        // fp32 8*42*1024*64
static const size_t OFF_STOUT= OFF_RES  + 22020096;      // fp32 8*41*1024*64
static const size_t OFF_CUR  = OFF_STOUT+ 21495808;      // fp32 8*23*1024*64
static const size_t OFF_RESBH= OFF_CUR  + 12058624;      // bf16 8*42*1024*64
static const size_t OFF_RESBL= OFF_RESBH+ 11010048;
static const size_t OFF_CVBH = OFF_RESBL+ 11010048;      // bf16 rm 328*1024*64
static const size_t OFF_CVBL = OFF_CVBH + 10747904;
static const size_t OFF_CTH  = OFF_CVBL + 10747904;      // bf16 T 328*64*1024
static const size_t OFF_CTL  = OFF_CTH  + 10747904;
static const size_t OFF_RS1H = OFF_CTL  + 10747904;      // rec prop outs bf16 rm
static const size_t OFF_RS1L = OFF_RS1H + 10747904;
static const size_t OFF_RS2H = OFF_RS1L + 10747904;
static const size_t OFF_RS2L = OFF_RS2H + 10747904;
static const size_t OFF_RT1H = OFF_RS2L + 10747904;
static const size_t OFF_RT1L = OFF_RT1H + 10747904;
static const size_t OFF_RT2H = OFF_RT1L + 10747904;
static const size_t OFF_RT2L = OFF_RT2H + 10747904;
static const size_t OFF_TCTH = OFF_RT2L + 10747904;      // AR tcl T-planes
static const size_t OFF_TCTL = OFF_TCTH + 262144;
static const size_t OFF_ECTH = OFF_TCTL + 262144;
static const size_t OFF_ECTL = OFF_ECTH + 10240;
static const size_t OFF_WCTBH= OFF_ECTL + 10240;
static const size_t OFF_WCTBL= OFF_WCTBH+ 22528;
static const size_t OFF_CURBH= OFF_WCTBL+ 22528;
static const size_t OFF_CURBL= OFF_CURBH+ 6029312;
static const size_t OFF_XOH  = OFF_CURBL+ 6029312;
static const size_t OFF_XOL  = OFF_XOH  + 262144;
static const size_t OFF_S1H  = OFF_XOL  + 262144;
static const size_t OFF_S1L  = OFF_S1H  + 262144;
static const size_t OFF_S2H  = OFF_S1L  + 262144;
static const size_t OFF_S2L  = OFF_S2H  + 262144;
static const size_t OFF_T1H  = OFF_S2L  + 262144;
static const size_t OFF_T1L  = OFF_T1H  + 262144;
static const size_t OFF_T2H  = OFF_T1L  + 262144;
static const size_t OFF_T2L  = OFF_T2H  + 262144;
static const size_t SCRATCH_TOTAL = OFF_T2L + 262144;

__device__ float g_scratch[SCRATCH_TOTAL];

// ================= mma.sync helpers =================
__device__ __forceinline__ uint32_t smem_u32(const void* p) {
    uint32_t a;
    asm("{ .reg .u64 t; cvta.to.shared.u64 t, %1; cvt.u32.u64 %0, t; }" : "=r"(a) : "l"(p));
    return a;
}
__device__ __forceinline__ void mma16816(float* c, const uint32_t* a, const uint32_t* b) {
    asm volatile("mma.sync.aligned.m16n8k16.row.col.f32.bf16.bf16.f32 "
        "{%0,%1,%2,%3}, {%4,%5,%6,%7}, {%8,%9}, {%0,%1,%2,%3};"
        : "+f"(c[0]), "+f"(c[1]), "+f"(c[2]), "+f"(c[3])
        : "r"(a[0]), "r"(a[1]), "r"(a[2]), "r"(a[3]), "r"(b[0]), "r"(b[1]));
}
__device__ __forceinline__ void ldsm4(uint32_t* r, uint32_t addr) {
    asm volatile("ldmatrix.sync.aligned.m8n8.x4.shared.b16 {%0,%1,%2,%3}, [%4];"
        : "=r"(r[0]), "=r"(r[1]), "=r"(r[2]), "=r"(r[3]) : "r"(addr));
}
__device__ __forceinline__ void cpasync16(uint32_t dst, const void* src) {
    asm volatile("cp.async.cg.shared.global [%0], [%1], 16;" :: "r"(dst), "l"(src));
}
#define SAS 72
#define STG_AL 18432u
#define STG_BH 36864u
#define STG_BL 46080u
#define STG_SZ 55296u
// paired-prop stage offsets
#define P2_AL  18432u
#define P2_B0H 36864u
#define P2_B0L 46080u
#define P2_B1H 55296u
#define P2_B1L 64512u
#define P2_SZ  73728u

// load A fragments (af[2][4][4] must be in scope)
#define MMA_ALOAD(AA) do {                                                     \
    _Pragma("unroll")                                                          \
    for (int mi = 0; mi < 2; mi++)                                             \
        _Pragma("unroll")                                                      \
        for (int kk = 0; kk < 4; kk++)                                         \
            ldsm4(af[mi][kk],                                                  \
                  (AA) + (uint32_t)(((wm * 32 + mi * 16 + lr) * SAS            \
                                     + kk * 16 + lc) * 2));                    \
} while (0)

// one B pass: load B fragments from AB and mma into ACC
#define MMA_BPASS(AB, ACC) do {                                                \
    uint32_t bfr[4][4][2];                                                     \
    _Pragma("unroll")                                                          \
    for (int np = 0; np < 2; np++)                                             \
        _Pragma("unroll")                                                      \
        for (int kk = 0; kk < 4; kk++) {                                       \
            uint32_t r[4];                                                     \
            ldsm4(r, (AB) + (uint32_t)(((wn * 32 + np * 16 + lr) * SAS         \
                                        + kk * 16 + lc) * 2));                 \
            bfr[2*np][kk][0]   = r[0]; bfr[2*np][kk][1]   = r[2];              \
            bfr[2*np+1][kk][0] = r[1]; bfr[2*np+1][kk][1] = r[3];              \
        }                                                                      \
    _Pragma("unroll")                                                          \
    for (int mi = 0; mi < 2; mi++)                                             \
        _Pragma("unroll")                                                      \
        for (int nf = 0; nf < 4; nf++)                                         \
            _Pragma("unroll")                                                  \
            for (int kk = 0; kk < 4; kk++)                                     \
                mma16816((ACC)[mi][nf], af[mi][kk], bfr[nf][kk]);              \
} while (0)

// B pass that also saves fragments into BSV[4][4][2]
#define MMA_BPASS_SAVE(AB, ACC, BSV) do {                                      \
    _Pragma("unroll")                                                          \
    for (int np = 0; np < 2; np++)                                             \
        _Pragma("unroll")                                                      \
        for (int kk = 0; kk < 4; kk++) {                                       \
            uint32_t r[4];                                                     \
            ldsm4(r, (AB) + (uint32_t)(((wn * 32 + np * 16 + lr) * SAS         \
                                        + kk * 16 + lc) * 2));                 \
            (BSV)[2*np][kk][0]   = r[0]; (BSV)[2*np][kk][1]   = r[2];          \
            (BSV)[2*np+1][kk][0] = r[1]; (BSV)[2*np+1][kk][1] = r[3];          \
        }                                                                      \
    _Pragma("unroll")                                                          \
    for (int mi = 0; mi < 2; mi++)                                             \
        _Pragma("unroll")                                                      \
        for (int nf = 0; nf < 4; nf++)                                         \
            _Pragma("unroll")                                                  \
            for (int kk = 0; kk < 4; kk++)                                     \
                mma16816((ACC)[mi][nf], af[mi][kk], (BSV)[nf][kk]);            \
} while (0)

// mma with previously saved B fragments
#define MMA_BREUSE(BSV, ACC) do {                                              \
    _Pragma("unroll")                                                          \
    for (int mi = 0; mi < 2; mi++)                                             \
        _Pragma("unroll")                                                      \
        for (int nf = 0; nf < 4; nf++)                                         \
            _Pragma("unroll")                                                  \
            for (int kk = 0; kk < 4; kk++)                                     \
                mma16816((ACC)[mi][nf], af[mi][kk], (BSV)[nf][kk]);            \
} while (0)

// hi/lo 3-pass mma over one 64-K chunk (A + Bh fragment reuse)
#define MMA_CHUNK3() do {                                                      \
    uint32_t af[2][4][4];                                                      \
    uint32_t bsv[4][4][2];                                                     \
    MMA_ALOAD(aAh);                                                            \
    MMA_BPASS_SAVE(aBh, acc, bsv);                                             \
    MMA_BPASS(aBl, acc);                                                       \
    MMA_ALOAD(aAl);                                                            \
    MMA_BREUSE(bsv, acc);                                                      \
} while (0)

// K=1024 pipelined issue (A row stride NN)
#define PIPE_ISSUE(K0, STB) do {                                               \
    _Pragma("unroll")                                                          \
    for (int it_ = 0; it_ < 4; it_++) {                                        \
        int li_ = tid + it_ * 256;                                             \
        int row_ = li_ >> 3, c8_ = li_ & 7;                                    \
        uint32_t da_ = (STB) + (uint32_t)(row_ * SAS + c8_ * 8) * 2;           \
        cpasync16(da_,          &Ah[(size_t)(m0 + row_) * NN + (K0) + c8_ * 8]);\
        cpasync16(da_ + STG_AL, &Al[(size_t)(m0 + row_) * NN + (K0) + c8_ * 8]);\
    }                                                                          \
    _Pragma("unroll")                                                          \
    for (int it_ = 0; it_ < 2; it_++) {                                        \
        int li_ = tid + it_ * 256;                                             \
        int row_ = li_ >> 3, c8_ = li_ & 7;                                    \
        uint32_t db_ = (STB) + STG_BH + (uint32_t)(row_ * SAS + c8_ * 8) * 2;  \
        cpasync16(db_,                    &Bh[(size_t)row_ * NN + (K0) + c8_ * 8]); \
        cpasync16(db_ + (STG_BL - STG_BH), &Bl[(size_t)row_ * NN + (K0) + c8_ * 8]); \
    }                                                                          \
    asm volatile("cp.async.commit_group;");                                    \
} while (0)

// small-K (64) issue: A/B row stride 64
__device__ __forceinline__ void sk_issue(const __nv_bfloat16* AH, const __nv_bfloat16* AL,
                                         const __nv_bfloat16* BH, const __nv_bfloat16* BL,
                                         uint32_t stb, int tid, bool withA) {
    if (withA) {
#pragma unroll
        for (int it = 0; it < 4; it++) {
            int li = tid + it * 256;
            int row = li >> 3, c8 = li & 7;
            uint32_t da = stb + (uint32_t)(row * SAS + c8 * 8) * 2;
            cpasync16(da,          &AH[row * 64 + c8 * 8]);
            cpasync16(da + STG_AL, &AL[row * 64 + c8 * 8]);
        }
    }
#pragma unroll
    for (int it = 0; it < 2; it++) {
        int li = tid + it * 256;
        int row = li >> 3, c8 = li & 7;
        uint32_t db = stb + STG_BH + (uint32_t)(row * SAS + c8 * 8) * 2;
        cpasync16(db,                     &BH[row * 64 + c8 * 8]);
        cpasync16(db + (STG_BL - STG_BH), &BL[row * 64 + c8 * 8]);
    }
    asm volatile("cp.async.commit_group;");
}

// paired-prop issue: A + 2 B-tiles (both row stride NN)
__device__ __forceinline__ void p2_issue(
        const __nv_bfloat16* Ah, const __nv_bfloat16* Al,
        const __nv_bfloat16* B0h, const __nv_bfloat16* B0l,
        const __nv_bfloat16* B1h, const __nv_bfloat16* B1l,
        int m0, int k0, uint32_t stb, int tid) {
#pragma unroll
    for (int it = 0; it < 4; it++) {
        int li = tid + it * 256;
        int row = li >> 3, c8 = li & 7;
        uint32_t da = stb + (uint32_t)(row * SAS + c8 * 8) * 2;
        cpasync16(da,         &Ah[(size_t)(m0 + row) * NN + k0 + c8 * 8]);
        cpasync16(da + P2_AL, &Al[(size_t)(m0 + row) * NN + k0 + c8 * 8]);
    }
#pragma unroll
    for (int it = 0; it < 2; it++) {
        int li = tid + it * 256;
        int row = li >> 3, c8 = li & 7;
        uint32_t db = stb + (uint32_t)(row * SAS + c8 * 8) * 2;
        cpasync16(db + P2_B0H, &B0h[(size_t)row * NN + k0 + c8 * 8]);
        cpasync16(db + P2_B0L, &B0l[(size_t)row * NN + k0 + c8 * 8]);
        cpasync16(db + P2_B1H, &B1h[(size_t)row * NN + k0 + c8 * 8]);
        cpasync16(db + P2_B1L, &B1l[(size_t)row * NN + k0 + c8 * 8]);
    }
    asm volatile("cp.async.commit_group;");
}

// variable-NC chunk-table pipelined loop (A always present)
#define MMA_CHUNKLOOP(NCV) do {                                                \
    sk_issue(cah[0], cal[0], cbh[0], cbl[0], stb[0], tid, true);               \
    for (int c = 0; c < (NCV); c++) {                                          \
        if (c + 1 < (NCV)) {                                                   \
            sk_issue(cah[c+1], cal[c+1], cbh[c+1], cbl[c+1],                   \
                     stb[(c+1) & 1], tid, true);                               \
            asm volatile("cp.async.wait_group 1;");                            \
        } else {                                                               \
            asm volatile("cp.async.wait_group 0;");                            \
        }                                                                      \
        __syncthreads();                                                       \
        uint32_t aAh = stb[c & 1];                                             \
        uint32_t aAl = aAh + STG_AL;                                           \
        uint32_t aBh = aAh + STG_BH;                                           \
        uint32_t aBl = aAh + STG_BL;                                           \
        MMA_CHUNK3();                                                          \
        __syncthreads();                                                       \
    }                                                                          \
} while (0)

// pointer T-plane writer (tbuf stride 65 floats)
#define TPLANE_WRITE_PTR(TB, OH, OL) do {                                      \
    int d_ = tid >> 2, nc_ = (tid & 3) * 32;                                   \
    size_t ob_ = (size_t)d_ * NN + m0 + nc_;                                   \
    _Pragma("unroll")                                                          \
    for (int q_ = 0; q_ < 32; q_ += 2) {                                       \
        float v0_ = (TB)[(nc_ + q_) * 65 + d_];                                \
        float v1_ = (TB)[(nc_ + q_ + 1) * 65 + d_];                            \
        __nv_bfloat16 h0_ = __float2bfloat16(v0_);                             \
        __nv_bfloat16 h1_ = __float2bfloat16(v1_);                             \
        __nv_bfloat16 l0_ = __float2bfloat16(v0_ - __bfloat162float(h0_));     \
        __nv_bfloat16 l1_ = __float2bfloat16(v1_ - __bfloat162float(h1_));     \
        *(__nv_bfloat162*)&(OH)[ob_ + q_] = __halves2bfloat162(h0_, h1_);      \
        *(__nv_bfloat162*)&(OL)[ob_ + q_] = __halves2bfloat162(l0_, l1_);      \
    }                                                                          \
} while (0)

// prop epilogue: acc -> bf16 hi/lo row-major
#define PROP_EPI(ACC, OH, OL) do {                                             \
    _Pragma("unroll")                                                          \
    for (int mi = 0; mi < 2; mi++) {                                           \
        int r0 = m0 + wm * 32 + mi * 16 + (lane >> 2);                         \
        _Pragma("unroll")                                                      \
        for (int nf = 0; nf < 4; nf++) {                                       \
            int d0 = wn * 32 + nf * 8 + (lane & 3) * 2;                        \
            _Pragma("unroll")                                                  \
            for (int half = 0; half < 2; half++) {                             \
                int r = r0 + half * 8;                                         \
                float v0 = (ACC)[mi][nf][half * 2];                            \
                float v1 = (ACC)[mi][nf][half * 2 + 1];                        \
                __nv_bfloat16 h0 = __float2bfloat16(v0);                       \
                __nv_bfloat16 h1 = __float2bfloat16(v1);                       \
                __nv_bfloat16 l0 = __float2bfloat16(v0 - __bfloat162float(h0));\
                __nv_bfloat16 l1 = __float2bfloat16(v1 - __bfloat162float(h1));\
                *(__nv_bfloat162*)&(OH)[(size_t)r * 64 + d0] =                 \
                    __halves2bfloat162(h0, h1);                                \
                *(__nv_bfloat162*)&(OL)[(size_t)r * 64 + d0] =                 \
                    __halves2bfloat162(l0, l1);                                \
            }                                                                  \
        }                                                                      \
    }                                                                          \
} while (0)

// ================= adjacency normalization =================
__global__ void k_norm_adj(const float* __restrict__ adj,
        __nv_bfloat16* __restrict__ a1h, __nv_bfloat16* __restrict__ a1l,
        __nv_bfloat16* __restrict__ a2h, __nv_bfloat16* __restrict__ a2l) {
    int v = blockIdx.x;
    int tid = threadIdx.x;
    __shared__ float r1[256], r2[256];
    float s1 = 0.f, s2 = 0.f;
    for (int n = tid; n < NN; n += 256) {
        s1 += adj[(size_t)v * NN + n];
        s2 += adj[(size_t)n * NN + v];
    }
    r1[tid] = s1; r2[tid] = s2;
    __syncthreads();
    for (int off = 128; off > 0; off >>= 1) {
        if (tid < off) { r1[tid] += r1[tid + off]; r2[tid] += r2[tid + off]; }
        __syncthreads();
    }
    float inv1 = 1.f / (r1[0] + 1.f);
    float inv2 = 1.f / (r2[0] + 1.f);
    for (int n = tid; n < NN; n += 256) {
        float d = (n == v) ? 1.f : 0.f;
        float v1 = (adj[(size_t)v * NN + n] + d) * inv1;
        float v2 = (adj[(size_t)n * NN + v] + d) * inv2;
        __nv_bfloat16 h1 = __float2bfloat16(v1);
        __nv_bfloat16 h2 = __float2bfloat16(v2);
        a1h[(size_t)v * NN + n] = h1;
        a1l[(size_t)v * NN + n] = __float2bfloat16(v1 - __bfloat162float(h1));
        a2h[(size_t)v * NN + n] = h2;
        a2l[(size_t)v * NN + n] = __float2bfloat16(v2 - __bfloat162float(h2));
    }
}

// ================= bf16 plane transpose =================
__global__ void __launch_bounds__(256) k_btrans(
        const __nv_bfloat16* __restrict__ i0, __nv_bfloat16* __restrict__ o0,
        const __nv_bfloat16* __restrict__ i1, __nv_bfloat16* __restrict__ o1,
        const __nv_bfloat16* __restrict__ i2, __nv_bfloat16* __restrict__ o2,
        const __nv_bfloat16* __restrict__ i3, __nv_bfloat16* __restrict__ o3) {
    const __nv_bfloat16* in;
    __nv_bfloat16* out;
    switch (blockIdx.z) {
        case 0: in = i0; out = o0; break;
        case 1: in = i1; out = o1; break;
        case 2: in = i2; out = o2; break;
        default: in = i3; out = o3; break;
    }
    int c0 = blockIdx.x * 64, r0 = blockIdx.y * 64;
    __shared__ __nv_bfloat16 t[64][72];
    int tid = threadIdx.x;
#pragma unroll
    for (int it = 0; it < 2; it++) {
        int li = tid + it * 256;
        int row = li >> 3, c8 = (li & 7) * 8;
        *(uint4*)&t[row][c8] = *(const uint4*)&in[(size_t)(r0 + row) * NN + c0 + c8];
    }
    __syncthreads();
#pragma unroll
    for (int it = 0; it < 2; it++) {
        int li = tid + it * 256;
        int c = li >> 3, r8 = (li & 7) * 8;
        __nv_bfloat16 v[8];
#pragma unroll
        for (int q = 0; q < 8; q++) v[q] = t[r8 + q][c];
        *(uint4*)&out[(size_t)(c0 + c) * NN + r0 + r8] = *(uint4*)v;
    }
}

// ================= A^2 precompute =================
__global__ void __launch_bounds__(256)
k_asq(const __nv_bfloat16* __restrict__ a1h, const __nv_bfloat16* __restrict__ a1l,
      const __nv_bfloat16* __restrict__ a1th, const __nv_bfloat16* __restrict__ a1tl,
      const __nv_bfloat16* __restrict__ a2h, const __nv_bfloat16* __restrict__ a2l,
      const __nv_bfloat16* __restrict__ a2th, const __nv_bfloat16* __restrict__ a2tl,
      __nv_bfloat16* __restrict__ q1h, __nv_bfloat16* __restrict__ q1l,
      __nv_bfloat16* __restrict__ q2h, __nv_bfloat16* __restrict__ q2l) {
    int m0 = blockIdx.x * 128;
    int n0 = blockIdx.y * 64;
    int mat = blockIdx.z;
    const __nv_bfloat16* Ah = mat ? a2h : a1h;
    const __nv_bfloat16* Al = mat ? a2l : a1l;
    const __nv_bfloat16* Bh = (mat ? a2th : a1th) + (size_t)n0 * NN;
    const __nv_bfloat16* Bl = (mat ? a2tl : a1tl) + (size_t)n0 * NN;
    __nv_bfloat16* qh = mat ? q2h : q1h;
    __nv_bfloat16* ql = mat ? q2l : q1l;

    extern __shared__ __nv_bfloat16 sb[];
    uint32_t sbase_ = smem_u32(sb);
    uint32_t stb_[2] = {sbase_, sbase_ + STG_SZ};
    int tid = threadIdx.x, lane = tid & 31, wid = tid >> 5;
    int wm = wid >> 1, wn = wid & 1;
    int lr = lane & 15, lc = (lane >> 4) * 8;

    float acc[2][4][4];
#pragma unroll
    for (int i = 0; i < 2; i++)
#pragma unroll
        for (int j = 0; j < 4; j++)
#pragma unroll
            for (int q = 0; q < 4; q++) acc[i][j][q] = 0.f;

    PIPE_ISSUE(0, stb_[0]);
    for (int c_ = 0; c_ < 16; c_++) {
        if (c_ + 1 < 16) {
            PIPE_ISSUE((c_ + 1) * 64, stb_[(c_ + 1) & 1]);
            asm volatile("cp.async.wait_group 1;");
        } else {
            asm volatile("cp.async.wait_group 0;");
        }
        __syncthreads();
        uint32_t aAh = stb_[c_ & 1];
        uint32_t aAl = aAh + STG_AL;
        uint32_t aBh = aAh + STG_BH;
        uint32_t aBl = aAh + STG_BL;
        MMA_CHUNK3();
        __syncthreads();
    }

#pragma unroll
    for (int mi = 0; mi < 2; mi++) {
        int r0 = m0 + wm * 32 + mi * 16 + (lane >> 2);
#pragma unroll
        for (int nf = 0; nf < 4; nf++) {
            int d0 = n0 + wn * 32 + nf * 8 + (lane & 3) * 2;
#pragma unroll
            for (int half = 0; half < 2; half++) {
                int rr = r0 + half * 8;
                float v0 = acc[mi][nf][half * 2], v1 = acc[mi][nf][half * 2 + 1];
                __nv_bfloat16 h0 = __float2bfloat16(v0), h1 = __float2bfloat16(v1);
                __nv_bfloat16 l0 = __float2bfloat16(v0 - __bfloat162float(h0));
                __nv_bfloat16 l1 = __float2bfloat16(v1 - __bfloat162float(h1));
                *(__nv_bfloat162*)&qh[(size_t)rr * NN + d0] = __halves2bfloat162(h0, h1);
                *(__nv_bfloat162*)&ql[(size_t)rr * NN + d0] = __halves2bfloat162(l0, l1);
            }
        }
    }
}

// ================= paired 4-way mma prop (2 bt per block; rec & AR) ===========
__global__ void __launch_bounds__(256)
k_prop4p(const __nv_bfloat16* __restrict__ a1h, const __nv_bfloat16* __restrict__ a1l,
         const __nv_bfloat16* __restrict__ q1h, const __nv_bfloat16* __restrict__ q1l,
         const __nv_bfloat16* __restrict__ a2h, const __nv_bfloat16* __restrict__ a2l,
         const __nv_bfloat16* __restrict__ q2h, const __nv_bfloat16* __restrict__ q2l,
         const __nv_bfloat16* __restrict__ bTh, const __nv_bfloat16* __restrict__ bTl,
         __nv_bfloat16* __restrict__ s1h, __nv_bfloat16* __restrict__ s1l,
         __nv_bfloat16* __restrict__ s2h, __nv_bfloat16* __restrict__ s2l,
         __nv_bfloat16* __restrict__ t1h, __nv_bfloat16* __restrict__ t1l,
         __nv_bfloat16* __restrict__ t2h, __nv_bfloat16* __restrict__ t2l) {
    int m0 = blockIdx.x * 128;
    int g0 = blockIdx.y * 2;
    int z  = blockIdx.z;
    const __nv_bfloat16 *Ah, *Al;
    __nv_bfloat16 *ohb, *olb;
    if (z == 0)      { Ah = a1h; Al = a1l; ohb = s1h; olb = s1l; }
    else if (z == 1) { Ah = q1h; Al = q1l; ohb = s2h; olb = s2l; }
    else if (z == 2) { Ah = a2h; Al = a2l; ohb = t1h; olb = t1l; }
    else             { Ah = q2h; Al = q2l; ohb = t2h; olb = t2l; }
    const __nv_bfloat16* B0h = bTh + (size_t)g0 * 65536;
    const __nv_bfloat16* B0l = bTl + (size_t)g0 * 65536;
    const __nv_bfloat16* B1h = B0h + 65536;
    const __nv_bfloat16* B1l = B0l + 65536;

    extern __shared__ __nv_bfloat16 sb[];
    uint32_t sbase = smem_u32(sb);
    uint32_t stb[2] = {sbase, sbase + P2_SZ};
    int tid = threadIdx.x, lane = tid & 31, wid = tid >> 5;
    int wm = wid >> 1, wn = wid & 1;
    int lr = lane & 15, lc = (lane >> 4) * 8;

    float acc0[2][4][4], acc1[2][4][4];
#pragma unroll
    for (int i = 0; i < 2; i++)
#pragma unroll
        for (int j = 0; j < 4; j++)
#pragma unroll
            for (int q = 0; q < 4; q++) { acc0[i][j][q] = 0.f; acc1[i][j][q] = 0.f; }

    p2_issue(Ah, Al, B0h, B0l, B1h, B1l, m0, 0, stb[0], tid);
    for (int c = 0; c < 16; c++) {
        if (c + 1 < 16) {
            p2_issue(Ah, Al, B0h, B0l, B1h, B1l, m0, (c + 1) * 64,
                     stb[(c + 1) & 1], tid);
            asm volatile("cp.async.wait_group 1;");
        } else {
            asm volatile("cp.async.wait_group 0;");
        }
        __syncthreads();
        uint32_t s = stb[c & 1];
        uint32_t aAh = s, aAl = s + P2_AL;
        uint32_t aB0h = s + P2_B0H, aB0l = s + P2_B0L;
        uint32_t aB1h = s + P2_B1H, aB1l = s + P2_B1L;
        {
            uint32_t af[2][4][4];
            MMA_ALOAD(aAh);
            MMA_BPASS(aB0h, acc0);
            MMA_BPASS(aB1h, acc1);
            MMA_BPASS(aB0l, acc0);
            MMA_BPASS(aB1l, acc1);
            MMA_ALOAD(aAl);
            MMA_BPASS(aB0h, acc0);
            MMA_BPASS(aB1h, acc1);
        }
        __syncthreads();
    }
    __nv_bfloat16* oh0 = ohb + (size_t)g0 * 65536;
    __nv_bfloat16* ol0 = olb + (size_t)g0 * 65536;
    __nv_bfloat16* oh1 = oh0 + 65536;
    __nv_bfloat16* ol1 = ol0 + 65536;
    PROP_EPI(acc0, oh0, ol0);
    PROP_EPI(acc1, oh1, ol1);
}

// ================= combine conv weights (bsum + transposed bf16) ==============
__global__ void k_comb_w(const float* w0, const float* w1, const float* w2,
                         const float* w3, const float* w4, const float* w5,
                         const float* cb0, const float* cb1, const float* cb2,
                         const float* cb3, const float* cb4, const float* cb5,
                         float* __restrict__ bsum,
                         __nv_bfloat16* __restrict__ wctbh,
                         __nv_bfloat16* __restrict__ wctbl) {
    int idx = blockIdx.x * 256 + threadIdx.x;
    if (idx >= 11 * 64 * 64) return;
    int o = idx & 63;
    int c = (idx >> 6) & 63;
    int dt = idx >> 12;
    int dv = dt - 5;
    int ad = dv < 0 ? -dv : dv;
    const float* ws[6] = {w0, w1, w2, w3, w4, w5};
    float acc = 0.f;
    for (int i = ad; i < 6; i++) {
        int K = 2 * i + 1;
        acc += ws[i][(size_t)(o * 64 + c) * K + (dv + i)];
    }
    __nv_bfloat16 h = __float2bfloat16(acc);
    wctbh[(size_t)dt * 4096 + o * 64 + c] = h;
    wctbl[(size_t)dt * 4096 + o * 64 + c] =
        __float2bfloat16(acc - __bfloat162float(h));
    if (dt == 0 && c == 0)
        bsum[o] = cb0[o] + cb1[o] + cb2[o] + cb3[o] + cb4[o] + cb5[o];
}

// ================= combine mixprop weights (eb + transposed bf16) =============
__global__ void k_comb_g(const float* __restrict__ g1w, const float* __restrict__ g1b,
                         const float* __restrict__ g2w, const float* __restrict__ g2b,
                         float* __restrict__ eb,
                         __nv_bfloat16* __restrict__ ecth,
                         __nv_bfloat16* __restrict__ ectl) {
    int idx = blockIdx.x * 256 + threadIdx.x;
    if (idx >= 5 * 4096) return;
    int term = idx >> 12;
    int co = idx & 4095;
    int c = co >> 6, o = co & 63;
    float v;
    if (term == 0) {
        v = g1w[co] + ALPHA * (g1w[4096 + co] + g1w[8192 + co])
          + g2w[co] + ALPHA * (g2w[4096 + co] + g2w[8192 + co]);
    } else if (term == 1) {
        v = BETA * g1w[4096 + co] + ALPHA * BETA * g1w[8192 + co];
    } else if (term == 2) {
        v = BETA * BETA * g1w[8192 + co];
    } else if (term == 3) {
        v = BETA * g2w[4096 + co] + ALPHA * BETA * g2w[8192 + co];
    } else {
        v = BETA * BETA * g2w[8192 + co];
    }
    __nv_bfloat16 h = __float2bfloat16(v);
    ecth[(size_t)term * 4096 + o * 64 + c] = h;
    ectl[(size_t)term * 4096 + o * 64 + c] =
        __float2bfloat16(v - __bfloat162float(h));
    if (idx < 64) eb[idx] = g1b[idx] + g2b[idx];
}

// ================= encoder MLP (emits fp32 res + bf16 hi/lo mirror) ============
__global__ void __launch_bounds__(256) k_enc2(const float* __restrict__ x,
        const float* __restrict__ w1, const float* __restrict__ b1,
        const float* __restrict__ w2, const float* __restrict__ b2,
        float* __restrict__ out,
        __nv_bfloat16* __restrict__ resbh, __nv_bfloat16* __restrict__ resbl) {
    extern __shared__ float sm[];
    float* xst = sm;
    float* w1s = xst + 8 * 132;
    float* hst = w1s + 1024;
    float* Bs  = hst + 128 * 132;
    int n0 = blockIdx.x * 128;
    int f  = blockIdx.y;
    int b  = blockIdx.z;
    int tid = threadIdx.x, tx = tid & 15, ty = tid >> 4;

#pragma unroll
    for (int it = 0; it < 4; it++) {
        int li = tid + it * 256;
        int s = li >> 7, m = li & 127;
        xst[s * 132 + m] = x[((size_t)b * NT + f * SEG + s) * NN + n0 + m];
        w1s[li] = w1[li];
    }
    __syncthreads();

    float acc1[8][8] = {};
#pragma unroll
    for (int k = 0; k < 8; k++) {
        float a_[8], b_[8];
        *(float4*)&a_[0] = *(const float4*)&w1s[k * 128 + ty * 4];
        *(float4*)&a_[4] = *(const float4*)&w1s[k * 128 + 64 + ty * 4];
        *(float4*)&b_[0] = *(const float4*)&xst[k * 132 + tx * 4];
        *(float4*)&b_[4] = *(const float4*)&xst[k * 132 + 64 + tx * 4];
#pragma unroll
        for (int i = 0; i < 8; i++)
#pragma unroll
            for (int j = 0; j < 8; j++)
                acc1[i][j] = fmaf(a_[i], b_[j], acc1[i][j]);
    }
#pragma unroll
    for (int i = 0; i < 8; i++) {
        int j = (i < 4) ? ty * 4 + i : 64 + ty * 4 + (i - 4);
        float bb = b1[j];
        float4 v0, v1;
        v0.x = fmaxf(acc1[i][0] + bb, 0.f); v0.y = fmaxf(acc1[i][1] + bb, 0.f);
        v0.z = fmaxf(acc1[i][2] + bb, 0.f); v0.w = fmaxf(acc1[i][3] + bb, 0.f);
        v1.x = fmaxf(acc1[i][4] + bb, 0.f); v1.y = fmaxf(acc1[i][5] + bb, 0.f);
        v1.z = fmaxf(acc1[i][6] + bb, 0.f); v1.w = fmaxf(acc1[i][7] + bb, 0.f);
        *(float4*)&hst[j * 132 + tx * 4]      = v0;
        *(float4*)&hst[j * 132 + 64 + tx * 4] = v1;
    }
    __syncthreads();

    float acc2[8][4] = {};
    for (int k0 = 0; k0 < 128; k0 += 16) {
        {
            int kk = tid >> 4, n4 = (tid & 15) * 4;
            *(float4*)&Bs[kk * 68 + n4] = *(const float4*)&w2[(size_t)(k0 + kk) * 64 + n4];
        }
        __syncthreads();
#pragma unroll
        for (int k = 0; k < 16; k++) {
            float a_[8], b_[4];
            *(float4*)&a_[0] = *(const float4*)&hst[(k0 + k) * 132 + ty * 4];
            *(float4*)&a_[4] = *(const float4*)&hst[(k0 + k) * 132 + 64 + ty * 4];
            *(float4*)&b_[0] = *(const float4*)&Bs[k * 68 + tx * 4];
#pragma unroll
            for (int i = 0; i < 8; i++)
#pragma unroll
                for (int j = 0; j < 4; j++)
                    acc2[i][j] = fmaf(a_[i], b_[j], acc2[i][j]);
        }
        __syncthreads();
    }
    float4 b2v = *(const float4*)&b2[tx * 4];
#pragma unroll
    for (int i = 0; i < 8; i++) {
        int m = n0 + ((i < 4) ? ty * 4 + i : 64 + ty * 4 + (i - 4));
        float va[4];
        va[0] = acc2[i][0] + b2v.x; va[1] = acc2[i][1] + b2v.y;
        va[2] = acc2[i][2] + b2v.z; va[3] = acc2[i][3] + b2v.w;
        size_t ri = (((size_t)b * FREQ + f) * NN + m) * 64 + tx * 4;
        *(float4*)&out[ri] = make_float4(va[0], va[1], va[2], va[3]);
        __nv_bfloat16 hh[4], ll[4];
#pragma unroll
        for (int q = 0; q < 4; q++) {
            hh[q] = __float2bfloat16(va[q]);
            ll[q] = __float2bfloat16(va[q] - __bfloat162float(hh[q]));
        }
        *(uint2*)&resbh[ri] = *(uint2*)hh;
        *(uint2*)&resbl[ri] = *(uint2*)ll;
    }
}

// ================= decoder MLP stage macros =================
#define DEC_STAGE1(SRC) do {                                                   \
    float acc1[8][8] = {};                                                     \
    for (int k0 = 0; k0 < 64; k0 += 16) {                                      \
        _Pragma("unroll")                                                      \
        for (int it = 0; it < 2; it++) {                                       \
            int f4 = tid + it * 256;                                           \
            int kk = f4 >> 5, j4 = (f4 & 31) * 4;                              \
            *(float4*)&As1[kk * 132 + j4] =                                    \
                *(const float4*)&w1[(size_t)(k0 + kk) * 128 + j4];             \
        }                                                                      \
        _Pragma("unroll")                                                      \
        for (int it = 0; it < 2; it++) {                                       \
            int li = tid + it * 256;                                           \
            int m = li & 127, k4 = li >> 7;                                    \
            float4 v = *(const float4*)&(SRC)[(size_t)m * 64 + k0 + k4 * 4];   \
            Bs1[(k4*4+0)*132 + m] = v.x; Bs1[(k4*4+1)*132 + m] = v.y;          \
            Bs1[(k4*4+2)*132 + m] = v.z; Bs1[(k4*4+3)*132 + m] = v.w;          \
        }                                                                      \
        __syncthreads();                                                       \
        _Pragma("unroll")                                                      \
        for (int k = 0; k < 16; k++) {                                         \
            float a_[8], b_[8];                                                \
            *(float4*)&a_[0] = *(const float4*)&As1[k * 132 + ty * 4];         \
            *(float4*)&a_[4] = *(const float4*)&As1[k * 132 + 64 + ty * 4];    \
            *(float4*)&b_[0] = *(const float4*)&Bs1[k * 132 + tx * 4];         \
            *(float4*)&b_[4] = *(const float4*)&Bs1[k * 132 + 64 + tx * 4];    \
            _Pragma("unroll")                                                  \
            for (int i = 0; i < 8; i++)                                        \
                _Pragma("unroll")                                              \
                for (int j = 0; j < 8; j++)                                    \
                    acc1[i][j] = fmaf(a_[i], b_[j], acc1[i][j]);               \
        }                                                                      \
        __syncthreads();                                                       \
    }                                                                          \
    _Pragma("unroll")                                                          \
    for (int i = 0; i < 8; i++) {                                              \
        int j = (i < 4) ? ty * 4 + i : 64 + ty * 4 + (i - 4);                  \
        float bb = b1[j];                                                      \
        float4 v0, v1;                                                         \
        v0.x = fmaxf(acc1[i][0] + bb, 0.f); v0.y = fmaxf(acc1[i][1] + bb, 0.f);\
        v0.z = fmaxf(acc1[i][2] + bb, 0.f); v0.w = fmaxf(acc1[i][3] + bb, 0.f);\
        v1.x = fmaxf(acc1[i][4] + bb, 0.f); v1.y = fmaxf(acc1[i][5] + bb, 0.f);\
        v1.z = fmaxf(acc1[i][6] + bb, 0.f); v1.w = fmaxf(acc1[i][7] + bb, 0.f);\
        *(float4*)&hst[j * 132 + tx * 4]      = v0;                            \
        *(float4*)&hst[j * 132 + 64 + tx * 4] = v1;                            \
    }                                                                          \
    __syncthreads();                                                           \
} while (0)

#define DEC_STAGE2(A4, M_, SG_) do {                                           \
    M_ = tid >> 1; SG_ = tid & 1;                                              \
    A4[0] = b2[SG_ * 4 + 0]; A4[1] = b2[SG_ * 4 + 1];                          \
    A4[2] = b2[SG_ * 4 + 2]; A4[3] = b2[SG_ * 4 + 3];                          \
    _Pragma("unroll 4")                                                        \
    for (int j = 0; j < 128; j++) {                                            \
        float h = hst[j * 132 + M_];                                           \
        float4 w = *(const float4*)&w2s[j * 8 + SG_ * 4];                      \
        A4[0] = fmaf(h, w.x, A4[0]); A4[1] = fmaf(h, w.y, A4[1]);              \
        A4[2] = fmaf(h, w.z, A4[2]); A4[3] = fmaf(h, w.w, A4[3]);              \
    }                                                                          \
} while (0)

// ================= decoder MLP for rec =================
__global__ void __launch_bounds__(256) k_dec_rec2(const float* __restrict__ res,
        const float* __restrict__ stout,
        const float* __restrict__ w1, const float* __restrict__ b1,
        const float* __restrict__ w2, const float* __restrict__ b2,
        float* __restrict__ out) {
    extern __shared__ float sm[];
    float* As1 = sm;
    float* Bs1 = As1 + 16 * 132;
    float* hst = Bs1 + 16 * 132;
    float* w2s = hst + 128 * 132;
    int n0 = blockIdx.x * 128;
    int f  = blockIdx.y;
    int b  = blockIdx.z;
    int tid = threadIdx.x, tx = tid & 15, ty = tid >> 4;
    const float* src = (f == 0)
        ? &res[(((size_t)b * FREQ) * NN + n0) * 64]
        : &stout[(((size_t)b * TREC + f - 1) * NN + n0) * 64];
#pragma unroll
    for (int it = 0; it < 4; it++) w2s[tid + it * 256] = w2[tid + it * 256];
    DEC_STAGE1(src);
    float a4[4];
    int m, sg;
    DEC_STAGE2(a4, m, sg);
#pragma unroll
    for (int q = 0; q < 4; q++) {
        int s = sg * 4 + q;
        out[((size_t)b * NT + f * SEG + s) * NN + n0 + m] = a4[q];
    }
}

// ================= decoder MLP for pred =================
__global__ void __launch_bounds__(256) k_dec_pred2(const float* __restrict__ cur,
        const float* __restrict__ w1, const float* __restrict__ b1,
        const float* __restrict__ w2, const float* __restrict__ b2,
        float* __restrict__ out) {
    extern __shared__ float sm[];
    float* As1 = sm;
    float* Bs1 = As1 + 16 * 132;
    float* hst = Bs1 + 16 * 132;
    float* w2s = hst + 128 * 132;
    int n0 = blockIdx.x * 128;
    int t  = blockIdx.y;
    int b  = blockIdx.z;
    int tid = threadIdx.x, tx = tid & 15, ty = tid >> 4;
    const float* src = &cur[(((size_t)b * 23 + MAXK + t) * NN + n0) * 64];
#pragma unroll
    for (int it = 0; it < 4; it++) w2s[tid + it * 256] = w2[tid + it * 256];
    DEC_STAGE1(src);
    float a4[4];
    int m, sg;
    DEC_STAGE2(a4, m, sg);
    float4 v = make_float4(a4[0], a4[1], a4[2], a4[3]);
    *(float4*)&out[(size_t)b * (NSTEP * SEG * NN) + (size_t)t * 8192
                   + (size_t)(n0 + m) * 8 + sg * 4] = v;
}

// ================= t_inception rec (mma, bf16 in/out) =================
__global__ void __launch_bounds__(256)
k_tconv_mma(const __nv_bfloat16* __restrict__ resbh, const __nv_bfloat16* __restrict__ resbl,
            const __nv_bfloat16* __restrict__ wctbh, const __nv_bfloat16* __restrict__ wctbl,
            const float* __restrict__ bsum,
            __nv_bfloat16* __restrict__ cvbh, __nv_bfloat16* __restrict__ cvbl,
            __nv_bfloat16* __restrict__ cth, __nv_bfloat16* __restrict__ ctl) {
    int m0 = blockIdx.x * 128;
    int bt = blockIdx.y;
    int b = bt / TREC, t = bt % TREC;
    extern __shared__ char dsm[];
    uint32_t sbase = smem_u32(dsm);
    uint32_t stb[2] = {sbase, sbase + STG_SZ};
    float* tbuf = (float*)dsm;          // reuses stage region after mainloop
    int tid = threadIdx.x, lane = tid & 31, wid = tid >> 5;
    int wm = wid >> 1, wn = wid & 1;
    int lr = lane & 15, lc = (lane >> 4) * 8;

    float acc[2][4][4];
#pragma unroll
    for (int i = 0; i < 2; i++)
#pragma unroll
        for (int j = 0; j < 4; j++)
#pragma unroll
            for (int q = 0; q < 4; q++) acc[i][j][q] = 0.f;

    const __nv_bfloat16 *cah[MAXK], *cal[MAXK], *cbh[MAXK], *cbl[MAXK];
    int NC = 0;
    for (int dt = 0; dt < MAXK; dt++) {
        int ts = t + dt - 5;
        if (ts < 0 || ts >= TREC) continue;
        size_t off = (((size_t)b * FREQ + ts) * NN + m0) * 64;
        cah[NC] = resbh + off;
        cal[NC] = resbl + off;
        cbh[NC] = wctbh + (size_t)dt * 4096;
        cbl[NC] = wctbl + (size_t)dt * 4096;
        NC++;
    }
    MMA_CHUNKLOOP(NC);

    const float inv6 = 1.f / 6.f;
    __nv_bfloat16* oh = cvbh + (size_t)bt * 65536;
    __nv_bfloat16* ol = cvbl + (size_t)bt * 65536;
#pragma unroll
    for (int mi = 0; mi < 2; mi++) {
        int rl0 = wm * 32 + mi * 16 + (lane >> 2);
#pragma unroll
        for (int nf = 0; nf < 4; nf++) {
            int d0 = wn * 32 + nf * 8 + (lane & 3) * 2;
            float bs0 = bsum[d0], bs1 = bsum[d0 + 1];
#pragma unroll
            for (int half = 0; half < 2; half++) {
                int rl = rl0 + half * 8;
                float v0 = (acc[mi][nf][half * 2]     + bs0) * inv6;
                float v1 = (acc[mi][nf][half * 2 + 1] + bs1) * inv6;
                tbuf[rl * 65 + d0] = v0; tbuf[rl * 65 + d0 + 1] = v1;
                __nv_bfloat16 h0 = __float2bfloat16(v0);
                __nv_bfloat16 h1 = __float2bfloat16(v1);
                __nv_bfloat16 l0 = __float2bfloat16(v0 - __bfloat162float(h0));
                __nv_bfloat16 l1 = __float2bfloat16(v1 - __bfloat162float(h1));
                size_t oi = (size_t)(m0 + rl) * 64 + d0;
                *(__nv_bfloat162*)&oh[oi] = __halves2bfloat162(h0, h1);
                *(__nv_bfloat162*)&ol[oi] = __halves2bfloat162(l0, l1);
            }
        }
    }
    __syncthreads();
    __nv_bfloat16* toh = cth + (size_t)bt * 65536;
    __nv_bfloat16* tol = ctl + (size_t)bt * 65536;
    TPLANE_WRITE_PTR(tbuf, toh, tol);
}

// ================= combine rec (mma) =================
__global__ void __launch_bounds__(256)
k_combine_mma(const __nv_bfloat16* __restrict__ xh, const __nv_bfloat16* __restrict__ xl,
              const __nv_bfloat16* __restrict__ s1h, const __nv_bfloat16* __restrict__ s1l,
              const __nv_bfloat16* __restrict__ s2h, const __nv_bfloat16* __restrict__ s2l,
              const __nv_bfloat16* __restrict__ t1h, const __nv_bfloat16* __restrict__ t1l,
              const __nv_bfloat16* __restrict__ t2h, const __nv_bfloat16* __restrict__ t2l,
              const __nv_bfloat16* __restrict__ ecth, const __nv_bfloat16* __restrict__ ectl,
              const float* __restrict__ eb,
              const float* __restrict__ res, float* __restrict__ stout) {
    int m0 = blockIdx.x * 128;
    int bt = blockIdx.y;
    extern __shared__ char dsm[];
    uint32_t sbase = smem_u32(dsm);
    uint32_t stb[2] = {sbase, sbase + STG_SZ};
    int tid = threadIdx.x, lane = tid & 31, wid = tid >> 5;
    int wm = wid >> 1, wn = wid & 1;
    int lr = lane & 15, lc = (lane >> 4) * 8;

    float acc[2][4][4];
#pragma unroll
    for (int i = 0; i < 2; i++)
#pragma unroll
        for (int j = 0; j < 4; j++)
#pragma unroll
            for (int q = 0; q < 4; q++) acc[i][j][q] = 0.f;

    const __nv_bfloat16 *cah[5], *cal[5], *cbh[5], *cbl[5];
    size_t xb = ((size_t)bt * NN + m0) * 64;
    cah[0] = xh  + xb; cal[0] = xl  + xb;
    cah[1] = s1h + xb; cal[1] = s1l + xb;
    cah[2] = s2h + xb; cal[2] = s2l + xb;
    cah[3] = t1h + xb; cal[3] = t1l + xb;
    cah[4] = t2h + xb; cal[4] = t2l + xb;
#pragma unroll
    for (int j = 0; j < 5; j++) {
        cbh[j] = ecth + (size_t)j * 4096;
        cbl[j] = ectl + (size_t)j * 4096;
    }
    MMA_CHUNKLOOP(5);

    int rrow = (bt / TREC) * FREQ + (bt % TREC);   // resid row = b*42 + t
#pragma unroll
    for (int mi = 0; mi < 2; mi++) {
        int rl0 = wm * 32 + mi * 16 + (lane >> 2);
#pragma unroll
        for (int nf = 0; nf < 4; nf++) {
            int d0 = wn * 32 + nf * 8 + (lane & 3) * 2;
            float e0 = eb[d0], e1 = eb[d0 + 1];
#pragma unroll
            for (int half = 0; half < 2; half++) {
                int m = m0 + rl0 + half * 8;
                float2 rv = *(const float2*)&res[((size_t)rrow * NN + m) * 64 + d0];
                float v0 = acc[mi][nf][half * 2]     + e0 + rv.x;
                float v1 = acc[mi][nf][half * 2 + 1] + e1 + rv.y;
                *(float2*)&stout[((size_t)bt * NN + m) * 64 + d0] = make_float2(v0, v1);
            }
        }
    }
}

// ===== shared epilogue2 for mma tcl =====
#define TCL_EPI2() do {                                                        \
    const float inv6_ = 1.f / 6.f;                                             \
    __nv_bfloat16* xho_ = xoh + (size_t)b * 65536;                             \
    __nv_bfloat16* xlo_ = xol + (size_t)b * 65536;                             \
    _Pragma("unroll")                                                          \
    for (int mi = 0; mi < 2; mi++) {                                           \
        int rl0 = wm * 32 + mi * 16 + (lane >> 2);                             \
        _Pragma("unroll")                                                      \
        for (int nf = 0; nf < 4; nf++) {                                       \
            int d0 = wn * 32 + nf * 8 + (lane & 3) * 2;                        \
            float bs0 = bsum[d0], bs1 = bsum[d0 + 1];                          \
            _Pragma("unroll")                                                  \
            for (int half = 0; half < 2; half++) {                             \
                int rl = rl0 + half * 8;                                       \
                float v0 = (acc[mi][nf][half * 2]     + bs0) * inv6_;          \
                float v1 = (acc[mi][nf][half * 2 + 1] + bs1) * inv6_;          \
                tbuf[rl * 65 + d0] = v0; tbuf[rl * 65 + d0 + 1] = v1;          \
                __nv_bfloat16 h0 = __float2bfloat16(v0);                       \
                __nv_bfloat16 h1 = __float2bfloat16(v1);                       \
                __nv_bfloat16 l0 = __float2bfloat16(v0 - __bfloat162float(h0));\
                __nv_bfloat16 l1 = __float2bfloat16(v1 - __bfloat162float(h1));\
                size_t oi = (size_t)(m0 + rl) * 64 + d0;                       \
                *(__nv_bfloat162*)&xho_[oi] = __halves2bfloat162(h0, h1);      \
                *(__nv_bfloat162*)&xlo_[oi] = __halves2bfloat162(l0, l1);      \
            }                                                                  \
        }                                                                      \
    }                                                                          \
    __syncthreads();                                                           \
    __nv_bfloat16* toh_ = tclth + (size_t)b * 65536;                           \
    __nv_bfloat16* tol_ = tcltl + (size_t)b * 65536;                           \
    TPLANE_WRITE_PTR(tbuf, toh_, tol_);                                        \
} while (0)

// ================= AR tcl step 0 (mma) =================
__global__ void __launch_bounds__(256)
k_tcl0_mma(const __nv_bfloat16* __restrict__ curbh, const __nv_bfloat16* __restrict__ curbl,
           const __nv_bfloat16* __restrict__ wctbh, const __nv_bfloat16* __restrict__ wctbl,
           const float* __restrict__ bsum,
           __nv_bfloat16* __restrict__ tclth, __nv_bfloat16* __restrict__ tcltl,
           __nv_bfloat16* __restrict__ xoh, __nv_bfloat16* __restrict__ xol) {
    int m0 = blockIdx.x * 128;
    int b  = blockIdx.y;
    extern __shared__ char dsm[];
    uint32_t sbase = smem_u32(dsm);
    uint32_t stb[2] = {sbase, sbase + STG_SZ};
    float* tbuf = (float*)dsm;
    int tid = threadIdx.x, lane = tid & 31, wid = tid >> 5;
    int wm = wid >> 1, wn = wid & 1;
    int lr = lane & 15, lc = (lane >> 4) * 8;

    float acc[2][4][4];
#pragma unroll
    for (int i = 0; i < 2; i++)
#pragma unroll
        for (int j = 0; j < 4; j++)
#pragma unroll
            for (int q = 0; q < 4; q++) acc[i][j][q] = 0.f;

    const __nv_bfloat16 *cah[6], *cal[6], *cbh[6], *cbl[6];
#pragma unroll
    for (int j = 0; j < 6; j++) {
        size_t off = ((size_t)(b * 23 + 5 + j) * NN + m0) * 64;
        cah[j] = curbh + off;
        cal[j] = curbl + off;
        cbh[j] = wctbh + (size_t)j * 4096;
        cbl[j] = wctbl + (size_t)j * 4096;
    }
    MMA_CHUNKLOOP(6);
    TCL_EPI2();
}

// ================= fused AR combine(step s) + tcl(step s+1) (mma) =============
__global__ void __launch_bounds__(256)
k_comb_tcl_mma(const __nv_bfloat16* __restrict__ xh, const __nv_bfloat16* __restrict__ xl,
               const __nv_bfloat16* __restrict__ s1h, const __nv_bfloat16* __restrict__ s1l,
               const __nv_bfloat16* __restrict__ s2h, const __nv_bfloat16* __restrict__ s2l,
               const __nv_bfloat16* __restrict__ t1h, const __nv_bfloat16* __restrict__ t1l,
               const __nv_bfloat16* __restrict__ t2h, const __nv_bfloat16* __restrict__ t2l,
               const __nv_bfloat16* __restrict__ ecth, const __nv_bfloat16* __restrict__ ectl,
               const float* __restrict__ eb,
               const __nv_bfloat16* __restrict__ wctbh, const __nv_bfloat16* __restrict__ wctbl,
               const float* __restrict__ bsum,
               float* __restrict__ cur,
               __nv_bfloat16* __restrict__ curbh, __nv_bfloat16* __restrict__ curbl,
               __nv_bfloat16* __restrict__ tclth, __nv_bfloat16* __restrict__ tcltl,
               __nv_bfloat16* __restrict__ xoh, __nv_bfloat16* __restrict__ xol,
               int s) {
    int m0 = blockIdx.x * 128;
    int b  = blockIdx.y;
    extern __shared__ char dsm[];
    uint32_t sbase = smem_u32(dsm);
    uint32_t stb[2] = {sbase, sbase + STG_SZ};
    __nv_bfloat16* xsh = (__nv_bfloat16*)(dsm + 2 * STG_SZ);
    __nv_bfloat16* xsl = (__nv_bfloat16*)(dsm + 2 * STG_SZ + 18432);
    uint32_t axsh = sbase + 2 * STG_SZ;
    uint32_t axsl = axsh + 18432;
    float* tbuf = (float*)dsm;           // reuse stage region after mainloop
    int tid = threadIdx.x, lane = tid & 31, wid = tid >> 5;
    int wm = wid >> 1, wn = wid & 1;
    int lr = lane & 15, lc = (lane >> 4) * 8;

    float acc[2][4][4];
#pragma unroll
    for (int i = 0; i < 2; i++)
#pragma unroll
        for (int j = 0; j < 4; j++)
#pragma unroll
            for (int q = 0; q < 4; q++) acc[i][j][q] = 0.f;

    const __nv_bfloat16* cah[10];
    const __nv_bfloat16* cal[10];
    size_t xb = ((size_t)b * NN + m0) * 64;
    cah[0] = xh  + xb; cal[0] = xl  + xb;
    cah[1] = s1h + xb; cal[1] = s1l + xb;
    cah[2] = s2h + xb; cal[2] = s2l + xb;
    cah[3] = t1h + xb; cal[3] = t1l + xb;
    cah[4] = t2h + xb; cal[4] = t2l + xb;
#pragma unroll
    for (int j = 0; j < 5; j++) {
        size_t off = ((size_t)(b * 23 + s + 6 + j) * NN + m0) * 64;
        cah[5 + j] = curbh + off;
        cal[5 + j] = curbl + off;
    }
    const int NC = (s == NSTEP - 1) ? 5 : 11;

    sk_issue(cah[0], cal[0], ecth, ectl, stb[0], tid, true);
    for (int c = 0; c < NC; c++) {
        if (c + 1 < NC) {
            const __nv_bfloat16 *nbh, *nbl;
            int cn = c + 1;
            if (cn < 5) { nbh = ecth + (size_t)cn * 4096; nbl = ectl + (size_t)cn * 4096; }
            else        { nbh = wctbh + (size_t)(cn - 5) * 4096; nbl = wctbl + (size_t)(cn - 5) * 4096; }
            bool withA = (cn != 10);
            sk_issue(withA ? cah[cn] : cah[0], withA ? cal[cn] : cal[0],
                     nbh, nbl, stb[cn & 1], tid, withA);
            asm volatile("cp.async.wait_group 1;");
        } else {
            asm volatile("cp.async.wait_group 0;");
        }
        __syncthreads();
        uint32_t aAh = (c == 10) ? axsh : stb[c & 1];
        uint32_t aAl = (c == 10) ? axsl : (stb[c & 1] + STG_AL);
        uint32_t aBh = stb[c & 1] + STG_BH;
        uint32_t aBl = stb[c & 1] + STG_BL;
        MMA_CHUNK3();
        __syncthreads();
        if (c == 4) {
            const float* curr = cur + (size_t)(b * 23 + s + 10) * NN * 64;
            float* curw = cur + (size_t)(b * 23 + s + 11) * NN * 64;
            __nv_bfloat16* cbh2 = curbh + (size_t)(b * 23 + s + 11) * NN * 64;
            __nv_bfloat16* cbl2 = curbl + (size_t)(b * 23 + s + 11) * NN * 64;
#pragma unroll
            for (int mi = 0; mi < 2; mi++) {
                int rl0 = wm * 32 + mi * 16 + (lane >> 2);
#pragma unroll
                for (int nf = 0; nf < 4; nf++) {
                    int d0 = wn * 32 + nf * 8 + (lane & 3) * 2;
                    float e0 = eb[d0], e1 = eb[d0 + 1];
#pragma unroll
                    for (int half = 0; half < 2; half++) {
                        int rl = rl0 + half * 8;
                        int m = m0 + rl;
                        float2 rv = *(const float2*)&curr[(size_t)m * 64 + d0];
                        float v0 = acc[mi][nf][half * 2]     + e0 + rv.x;
                        float v1 = acc[mi][nf][half * 2 + 1] + e1 + rv.y;
                        *(float2*)&curw[(size_t)m * 64 + d0] = make_float2(v0, v1);
                        __nv_bfloat16 h0 = __float2bfloat16(v0);
                        __nv_bfloat16 h1 = __float2bfloat16(v1);
                        __nv_bfloat16 l0 = __float2bfloat16(v0 - __bfloat162float(h0));
                        __nv_bfloat16 l1 = __float2bfloat16(v1 - __bfloat162float(h1));
                        *(__nv_bfloat162*)&cbh2[(size_t)m * 64 + d0] = __halves2bfloat162(h0, h1);
                        *(__nv_bfloat162*)&cbl2[(size_t)m * 64 + d0] = __halves2bfloat162(l0, l1);
                        *(__nv_bfloat162*)&xsh[rl * SAS + d0] = __halves2bfloat162(h0, h1);
                        *(__nv_bfloat162*)&xsl[rl * SAS + d0] = __halves2bfloat162(l0, l1);
                    }
                }
            }
#pragma unroll
            for (int i = 0; i < 2; i++)
#pragma unroll
                for (int j = 0; j < 4; j++)
#pragma unroll
                    for (int q = 0; q < 4; q++) acc[i][j][q] = 0.f;
            __syncthreads();
        }
    }
    if (NC == 11) {
        TCL_EPI2();
    }
}

// ================= AR cur-buffer init (+ bf16 mirror) =================
__global__ void k_cur_init(const float* __restrict__ res, float* __restrict__ cur,
                           __nv_bfloat16* __restrict__ curbh,
                           __nv_bfloat16* __restrict__ curbl) {
    size_t total = (size_t)NB * MAXK * NN * 64;
    for (size_t idx = (size_t)blockIdx.x * blockDim.x + threadIdx.x; idx < total;
         idx += (size_t)gridDim.x * blockDim.x) {
        int d = idx & 63;
        int n = (idx >> 6) & 1023;
        int j = (int)((idx >> 16) % MAXK);
        int b = (int)(idx / ((size_t)MAXK << 16));
        float v = res[(((size_t)b * FREQ + 31 + j) * NN + n) * 64 + d];
        size_t dst = (((size_t)b * 23 + j) * NN + n) * 64 + d;
        cur[dst] = v;
        __nv_bfloat16 h = __float2bfloat16(v);
        curbh[dst] = h;
        curbl[dst] = __float2bfloat16(v - __bfloat162float(h));
    }
}

// ================= host launcher =================
extern "C" void kernel_launch(void* const* d_in, const int* in_sizes, int n_in,
                              void* d_out, int out_size) {
    (void)in_sizes; (void)n_in; (void)out_size;
    const float* x_diff = (const float*)d_in[0];
    const float* adj    = (const float*)d_in[1];
    const float* enc_w1 = (const float*)d_in[2];
    const float* enc_b1 = (const float*)d_in[3];
    const float* enc_w2 = (const float*)d_in[4];
    const float* enc_b2 = (const float*)d_in[5];
    const float* dec_w1 = (const float*)d_in[6];
    const float* dec_b1 = (const float*)d_in[7];
    const float* dec_w2 = (const float*)d_in[8];
    const float* dec_b2 = (const float*)d_in[9];
    const float* g1_w   = (const float*)d_in[10];
    const float* g1_b   = (const float*)d_in[11];
    const float* g2_w   = (const float*)d_in[12];
    const float* g2_b   = (const float*)d_in[13];
    const float* cw[6], *cb[6];
    for (int i = 0; i < 6; i++) {
        cw[i] = (const float*)d_in[14 + 2 * i];
        cb[i] = (const float*)d_in[15 + 2 * i];
    }

    float* scratch = nullptr;
    cudaGetSymbolAddress((void**)&scratch, g_scratch);
    float* bsum  = scratch + OFF_BSUM;
    float* eb    = scratch + OFF_EB;
    __nv_bfloat16* a1h  = (__nv_bfloat16*)(scratch + OFF_A1H);
    __nv_bfloat16* a1l  = (__nv_bfloat16*)(scratch + OFF_A1L);
    __nv_bfloat16* a2h  = (__nv_bfloat16*)(scratch + OFF_A2H);
    __nv_bfloat16* a2l  = (__nv_bfloat16*)(scratch + OFF_A2L);
    __nv_bfloat16* a1th = (__nv_bfloat16*)(scratch + OFF_A1TH);
    __nv_bfloat16* a1tl = (__nv_bfloat16*)(scratch + OFF_A1TL);
    __nv_bfloat16* a2th = (__nv_bfloat16*)(scratch + OFF_A2TH);
    __nv_bfloat16* a2tl = (__nv_bfloat16*)(scratch + OFF_A2TL);
    __nv_bfloat16* q1h  = (__nv_bfloat16*)(scratch + OFF_Q1H);
    __nv_bfloat16* q1l  = (__nv_bfloat16*)(scratch + OFF_Q1L);
    __nv_bfloat16* q2h  = (__nv_bfloat16*)(scratch + OFF_Q2H);
    __nv_bfloat16* q2l  = (__nv_bfloat16*)(scratch + OFF_Q2L);
    float* res   = scratch + OFF_RES;
    float* stout = scratch + OFF_STOUT;
    float* cur   = scratch + OFF_CUR;
    __nv_bfloat16* resbh = (__nv_bfloat16*)(scratch + OFF_RESBH);
    __nv_bfloat16* resbl = (__nv_bfloat16*)(scratch + OFF_RESBL);
    __nv_bfloat16* cvbh  = (__nv_bfloat16*)(scratch + OFF_CVBH);
    __nv_bfloat16* cvbl  = (__nv_bfloat16*)(scratch + OFF_CVBL);
    __nv_bfloat16* cth   = (__nv_bfloat16*)(scratch + OFF_CTH);
    __nv_bfloat16* ctl   = (__nv_bfloat16*)(scratch + OFF_CTL);
    __nv_bfloat16* rs1h  = (__nv_bfloat16*)(scratch + OFF_RS1H);
    __nv_bfloat16* rs1l  = (__nv_bfloat16*)(scratch + OFF_RS1L);
    __nv_bfloat16* rs2h  = (__nv_bfloat16*)(scratch + OFF_RS2H);
    __nv_bfloat16* rs2l  = (__nv_bfloat16*)(scratch + OFF_RS2L);
    __nv_bfloat16* rt1h  = (__nv_bfloat16*)(scratch + OFF_RT1H);
    __nv_bfloat16* rt1l  = (__nv_bfloat16*)(scratch + OFF_RT1L);
    __nv_bfloat16* rt2h  = (__nv_bfloat16*)(scratch + OFF_RT2H);
    __nv_bfloat16* rt2l  = (__nv_bfloat16*)(scratch + OFF_RT2L);
    __nv_bfloat16* tclth = (__nv_bfloat16*)(scratch + OFF_TCTH);
    __nv_bfloat16* tcltl = (__nv_bfloat16*)(scratch + OFF_TCTL);
    __nv_bfloat16* ecth  = (__nv_bfloat16*)(scratch + OFF_ECTH);
    __nv_bfloat16* ectl  = (__nv_bfloat16*)(scratch + OFF_ECTL);
    __nv_bfloat16* wctbh = (__nv_bfloat16*)(scratch + OFF_WCTBH);
    __nv_bfloat16* wctbl = (__nv_bfloat16*)(scratch + OFF_WCTBL);
    __nv_bfloat16* curbh = (__nv_bfloat16*)(scratch + OFF_CURBH);
    __nv_bfloat16* curbl = (__nv_bfloat16*)(scratch + OFF_CURBL);
    __nv_bfloat16* xoh   = (__nv_bfloat16*)(scratch + OFF_XOH);
    __nv_bfloat16* xol   = (__nv_bfloat16*)(scratch + OFF_XOL);
    __nv_bfloat16* s1h   = (__nv_bfloat16*)(scratch + OFF_S1H);
    __nv_bfloat16* s1l   = (__nv_bfloat16*)(scratch + OFF_S1L);
    __nv_bfloat16* s2h   = (__nv_bfloat16*)(scratch + OFF_S2H);
    __nv_bfloat16* s2l   = (__nv_bfloat16*)(scratch + OFF_S2L);
    __nv_bfloat16* t1h   = (__nv_bfloat16*)(scratch + OFF_T1H);
    __nv_bfloat16* t1l   = (__nv_bfloat16*)(scratch + OFF_T1L);
    __nv_bfloat16* t2h   = (__nv_bfloat16*)(scratch + OFF_T2H);
    __nv_bfloat16* t2l   = (__nv_bfloat16*)(scratch + OFF_T2L);

    float* rec_out  = (float*)d_out;
    float* pred_out = rec_out + (size_t)NB * NT * NN;

    const int ENC_SMEM = (8 * 132 + 1024 + 128 * 132 + 16 * 68) * 4;
    const int DEC_SMEM = (16 * 132 * 2 + 128 * 132 + 128 * 8) * 4;
    const int MMA_SMEM = 2 * STG_SZ;                 // 110592
    const int P2_SMEM  = 2 * P2_SZ;                  // 147456 (paired prop)
    const int CT_SMEM  = 2 * STG_SZ + 36864;         // 147456 (comb_tcl)
    cudaFuncSetAttribute(k_enc2, cudaFuncAttributeMaxDynamicSharedMemorySize, ENC_SMEM);
    cudaFuncSetAttribute(k_dec_rec2, cudaFuncAttributeMaxDynamicSharedMemorySize, DEC_SMEM);
    cudaFuncSetAttribute(k_dec_pred2, cudaFuncAttributeMaxDynamicSharedMemorySize, DEC_SMEM);
    cudaFuncSetAttribute(k_prop4p, cudaFuncAttributeMaxDynamicSharedMemorySize, P2_SMEM);
    cudaFuncSetAttribute(k_asq, cudaFuncAttributeMaxDynamicSharedMemorySize, MMA_SMEM);
    cudaFuncSetAttribute(k_tconv_mma, cudaFuncAttributeMaxDynamicSharedMemorySize, MMA_SMEM);
    cudaFuncSetAttribute(k_combine_mma, cudaFuncAttributeMaxDynamicSharedMemorySize, MMA_SMEM);
    cudaFuncSetAttribute(k_tcl0_mma, cudaFuncAttributeMaxDynamicSharedMemorySize, MMA_SMEM);
    cudaFuncSetAttribute(k_comb_tcl_mma, cudaFuncAttributeMaxDynamicSharedMemorySize, CT_SMEM);

    // ---- preprocessing ----
    k_norm_adj<<<NN, 256>>>(adj, a1h, a1l, a2h, a2l);
    k_btrans<<<dim3(16, 16, 4), 256>>>(a1h, a1th, a1l, a1tl, a2h, a2th, a2l, a2tl);
    k_comb_w<<<(11 * 64 * 64 + 255) / 256, 256>>>(cw[0], cw[1], cw[2], cw[3], cw[4], cw[5],
                                                  cb[0], cb[1], cb[2], cb[3], cb[4], cb[5],
                                                  bsum, wctbh, wctbl);
    k_comb_g<<<80, 256>>>(g1_w, g1_b, g2_w, g2_b, eb, ecth, ectl);
    k_asq<<<dim3(8, 16, 2), 256, MMA_SMEM>>>(a1h, a1l, a1th, a1tl,
                                             a2h, a2l, a2th, a2tl,
                                             q1h, q1l, q2h, q2l);

    // ---- encoder ----
    k_enc2<<<dim3(8, FREQ, NB), 256, ENC_SMEM>>>(x_diff, enc_w1, enc_b1, enc_w2, enc_b2,
                                                 res, resbh, resbl);

    // ---- rec-path stconv (all mma) ----
    k_tconv_mma<<<dim3(8, NB * TREC), 256, MMA_SMEM>>>(resbh, resbl, wctbh, wctbl, bsum,
                                                       cvbh, cvbl, cth, ctl);
    k_prop4p<<<dim3(8, NB * TREC / 2, 4), 256, P2_SMEM>>>(
        a1h, a1l, q1h, q1l, a2h, a2l, q2h, q2l,
        cth, ctl, rs1h, rs1l, rs2h, rs2l, rt1h, rt1l, rt2h, rt2l);
    k_combine_mma<<<dim3(8, NB * TREC), 256, MMA_SMEM>>>(
        cvbh, cvbl, rs1h, rs1l, rs2h, rs2l, rt1h, rt1l, rt2h, rt2l,
        ecth, ectl, eb, res, stout);
    // ---- rec decoder ----
    k_dec_rec2<<<dim3(8, FREQ, NB), 256, DEC_SMEM>>>(res, stout, dec_w1, dec_b1,
                                                     dec_w2, dec_b2, rec_out);

    // ---- autoregressive loop ----
    k_cur_init<<<4096, 256>>>(res, cur, curbh, curbl);
    k_tcl0_mma<<<dim3(8, NB), 256, MMA_SMEM>>>(curbh, curbl, wctbh, wctbl, bsum,
                                               tclth, tcltl, xoh, xol);
    for (int s = 0; s < NSTEP; s++) {
        k_prop4p<<<dim3(8, NB / 2, 4), 256, P2_SMEM>>>(
            a1h, a1l, q1h, q1l, a2h, a2l, q2h, q2l,
            tclth, tcltl, s1h, s1l, s2h, s2l, t1h, t1l, t2h, t2l);
        k_comb_tcl_mma<<<dim3(8, NB), 256, CT_SMEM>>>(
            xoh, xol, s1h, s1l, s2h, s2l, t1h, t1l, t2h, t2l,
            ecth, ectl, eb, wctbh, wctbl, bsum,
            cur, curbh, curbl, tclth, tcltl, xoh, xol, s);
    }
    // ---- pred decoder ----
    k_dec_pred2<<<dim3(8, NSTEP, NB), 256, DEC_SMEM>>>(cur, dec_w1, dec_b1,
                                                       dec_w2, dec_b2, pred_out);
}

// round 17
// speedup vs baseline: 1.0246x; 1.0134x over previous
#include <cuda_runtime.h>
#include <cuda_bf16.h>
#include <cstdint>

// ---------------- problem constants ----------------
#define NB   8
#define NT   336
#define NN   1024
#define FREQ 42
#define SEG  8
#define TREC 41
#define NSTEP 12
#define MAXK 11
#define ALPHA 0.05f
#define BETA  0.95f

// ---------------- scratch layout (floats) ----------------
static const size_t OFF_BSUM = 0;                         // 64
static const size_t OFF_EB   = 64;                        // 64
static const size_t OFF_A1H  = 128;
static const size_t OFF_A1L  = OFF_A1H  + 524288;
static const size_t OFF_A2H  = OFF_A1L  + 524288;
static const size_t OFF_A2L  = OFF_A2H  + 524288;
static const size_t OFF_A1TH = OFF_A2L  + 524288;
static const size_t OFF_A1TL = OFF_A1TH + 524288;
static const size_t OFF_A2TH = OFF_A1TL + 524288;
static const size_t OFF_A2TL = OFF_A2TH + 524288;
static const size_t OFF_Q1H  = OFF_A2TL + 524288;
static const size_t OFF_Q1L  = OFF_Q1H  + 524288;
static const size_t OFF_Q2H  = OFF_Q1L  + 524288;
static const size_t OFF_Q2L  = OFF_Q2H  + 524288;
static const size_t OFF_RES  = OFF_Q2L  + 524288;        // fp32 8*42*1024*64
static const size_t OFF_STOUT= OFF_RES  + 22020096;      // fp32 8*41*1024*64
static const size_t OFF_CUR  = OFF_STOUT+ 21495808;      // fp32 8*23*1024*64
static const size_t OFF_RESBH= OFF_CUR  + 12058624;      // bf16 8*42*1024*64
static const size_t OFF_RESBL= OFF_RESBH+ 11010048;
static const size_t OFF_CVBH = OFF_RESBL+ 11010048;      // bf16 rm 328*1024*64
static const size_t OFF_CVBL = OFF_CVBH + 10747904;
static const size_t OFF_CTH  = OFF_CVBL + 10747904;      // bf16 T 328*64*1024
static const size_t OFF_CTL  = OFF_CTH  + 10747904;
static const size_t OFF_RS1H = OFF_CTL  + 10747904;      // rec prop outs bf16 rm
static const size_t OFF_RS1L = OFF_RS1H + 10747904;
static const size_t OFF_RS2H = OFF_RS1L + 10747904;
static const size_t OFF_RS2L = OFF_RS2H + 10747904;
static const size_t OFF_RT1H = OFF_RS2L + 10747904;
static const size_t OFF_RT1L = OFF_RT1H + 10747904;
static const size_t OFF_RT2H = OFF_RT1L + 10747904;
static const size_t OFF_RT2L = OFF_RT2H + 10747904;
static const size_t OFF_TCTH = OFF_RT2L + 10747904;      // AR tcl T-planes
static const size_t OFF_TCTL = OFF_TCTH + 262144;
static const size_t OFF_ECTH = OFF_TCTL + 262144;
static const size_t OFF_ECTL = OFF_ECTH + 10240;
static const size_t OFF_WCTBH= OFF_ECTL + 10240;
static const size_t OFF_WCTBL= OFF_WCTBH+ 22528;
static const size_t OFF_CURBH= OFF_WCTBL+ 22528;
static const size_t OFF_CURBL= OFF_CURBH+ 6029312;
static const size_t OFF_XOH  = OFF_CURBL+ 6029312;
static const size_t OFF_XOL  = OFF_XOH  + 262144;
static const size_t OFF_S1H  = OFF_XOL  + 262144;
static const size_t OFF_S1L  = OFF_S1H  + 262144;
static const size_t OFF_S2H  = OFF_S1L  + 262144;
static const size_t OFF_S2L  = OFF_S2H  + 262144;
static const size_t OFF_T1H  = OFF_S2L  + 262144;
static const size_t OFF_T1L  = OFF_T1H  + 262144;
static const size_t OFF_T2H  = OFF_T1L  + 262144;
static const size_t OFF_T2L  = OFF_T2H  + 262144;
static const size_t OFF_STBH = OFF_T2L  + 262144;        // bf16 stout mirror
static const size_t OFF_STBL = OFF_STBH + 10747904;
static const size_t OFF_DW1H = OFF_STBL + 10747904;      // dec_w1^T bf16 128x64
static const size_t OFF_DW1L = OFF_DW1H + 4096;
static const size_t SCRATCH_TOTAL = OFF_DW1L + 4096;

__device__ float g_scratch[SCRATCH_TOTAL];

// ================= mma.sync helpers =================
__device__ __forceinline__ uint32_t smem_u32(const void* p) {
    uint32_t a;
    asm("{ .reg .u64 t; cvta.to.shared.u64 t, %1; cvt.u32.u64 %0, t; }" : "=r"(a) : "l"(p));
    return a;
}
__device__ __forceinline__ void mma16816(float* c, const uint32_t* a, const uint32_t* b) {
    asm volatile("mma.sync.aligned.m16n8k16.row.col.f32.bf16.bf16.f32 "
        "{%0,%1,%2,%3}, {%4,%5,%6,%7}, {%8,%9}, {%0,%1,%2,%3};"
        : "+f"(c[0]), "+f"(c[1]), "+f"(c[2]), "+f"(c[3])
        : "r"(a[0]), "r"(a[1]), "r"(a[2]), "r"(a[3]), "r"(b[0]), "r"(b[1]));
}
__device__ __forceinline__ void ldsm4(uint32_t* r, uint32_t addr) {
    asm volatile("ldmatrix.sync.aligned.m8n8.x4.shared.b16 {%0,%1,%2,%3}, [%4];"
        : "=r"(r[0]), "=r"(r[1]), "=r"(r[2]), "=r"(r[3]) : "r"(addr));
}
__device__ __forceinline__ void cpasync16(uint32_t dst, const void* src) {
    asm volatile("cp.async.cg.shared.global [%0], [%1], 16;" :: "r"(dst), "l"(src));
}
#define SAS 72
#define STG_AL 18432u
#define STG_BH 36864u
#define STG_BL 46080u
#define STG_SZ 55296u
// paired-prop stage offsets
#define P2_AL  18432u
#define P2_B0H 36864u
#define P2_B0L 46080u
#define P2_B1H 55296u
#define P2_B1L 64512u
#define P2_SZ  73728u

// load A fragments (af[2][4][4] must be in scope)
#define MMA_ALOAD(AA) do {                                                     \
    _Pragma("unroll")                                                          \
    for (int mi = 0; mi < 2; mi++)                                             \
        _Pragma("unroll")                                                      \
        for (int kk = 0; kk < 4; kk++)                                         \
            ldsm4(af[mi][kk],                                                  \
                  (AA) + (uint32_t)(((wm * 32 + mi * 16 + lr) * SAS            \
                                     + kk * 16 + lc) * 2));                    \
} while (0)

// one B pass: load B fragments from AB and mma into ACC
#define MMA_BPASS(AB, ACC) do {                                                \
    uint32_t bfr[4][4][2];                                                     \
    _Pragma("unroll")                                                          \
    for (int np = 0; np < 2; np++)                                             \
        _Pragma("unroll")                                                      \
        for (int kk = 0; kk < 4; kk++) {                                       \
            uint32_t r[4];                                                     \
            ldsm4(r, (AB) + (uint32_t)(((wn * 32 + np * 16 + lr) * SAS         \
                                        + kk * 16 + lc) * 2));                 \
            bfr[2*np][kk][0]   = r[0]; bfr[2*np][kk][1]   = r[2];              \
            bfr[2*np+1][kk][0] = r[1]; bfr[2*np+1][kk][1] = r[3];              \
        }                                                                      \
    _Pragma("unroll")                                                          \
    for (int mi = 0; mi < 2; mi++)                                             \
        _Pragma("unroll")                                                      \
        for (int nf = 0; nf < 4; nf++)                                         \
            _Pragma("unroll")                                                  \
            for (int kk = 0; kk < 4; kk++)                                     \
                mma16816((ACC)[mi][nf], af[mi][kk], bfr[nf][kk]);              \
} while (0)

// B pass that also saves fragments into BSV[4][4][2]
#define MMA_BPASS_SAVE(AB, ACC, BSV) do {                                      \
    _Pragma("unroll")                                                          \
    for (int np = 0; np < 2; np++)                                             \
        _Pragma("unroll")                                                      \
        for (int kk = 0; kk < 4; kk++) {                                       \
            uint32_t r[4];                                                     \
            ldsm4(r, (AB) + (uint32_t)(((wn * 32 + np * 16 + lr) * SAS         \
                                        + kk * 16 + lc) * 2));                 \
            (BSV)[2*np][kk][0]   = r[0]; (BSV)[2*np][kk][1]   = r[2];          \
            (BSV)[2*np+1][kk][0] = r[1]; (BSV)[2*np+1][kk][1] = r[3];          \
        }                                                                      \
    _Pragma("unroll")                                                          \
    for (int mi = 0; mi < 2; mi++)                                             \
        _Pragma("unroll")                                                      \
        for (int nf = 0; nf < 4; nf++)                                         \
            _Pragma("unroll")                                                  \
            for (int kk = 0; kk < 4; kk++)                                     \
                mma16816((ACC)[mi][nf], af[mi][kk], (BSV)[nf][kk]);            \
} while (0)

// mma with previously saved B fragments
#define MMA_BREUSE(BSV, ACC) do {                                              \
    _Pragma("unroll")                                                          \
    for (int mi = 0; mi < 2; mi++)                                             \
        _Pragma("unroll")                                                      \
        for (int nf = 0; nf < 4; nf++)                                         \
            _Pragma("unroll")                                                  \
            for (int kk = 0; kk < 4; kk++)                                     \
                mma16816((ACC)[mi][nf], af[mi][kk], (BSV)[nf][kk]);            \
} while (0)

// hi/lo 3-pass mma over one 64-K chunk (A + Bh fragment reuse)
#define MMA_CHUNK3() do {                                                      \
    uint32_t af[2][4][4];                                                      \
    uint32_t bsv[4][4][2];                                                     \
    MMA_ALOAD(aAh);                                                            \
    MMA_BPASS_SAVE(aBh, acc, bsv);                                             \
    MMA_BPASS(aBl, acc);                                                       \
    MMA_ALOAD(aAl);                                                            \
    MMA_BREUSE(bsv, acc);                                                      \
} while (0)

// K=1024 pipelined issue (A row stride NN)
#define PIPE_ISSUE(K0, STB) do {                                               \
    _Pragma("unroll")                                                          \
    for (int it_ = 0; it_ < 4; it_++) {                                        \
        int li_ = tid + it_ * 256;                                             \
        int row_ = li_ >> 3, c8_ = li_ & 7;                                    \
        uint32_t da_ = (STB) + (uint32_t)(row_ * SAS + c8_ * 8) * 2;           \
        cpasync16(da_,          &Ah[(size_t)(m0 + row_) * NN + (K0) + c8_ * 8]);\
        cpasync16(da_ + STG_AL, &Al[(size_t)(m0 + row_) * NN + (K0) + c8_ * 8]);\
    }                                                                          \
    _Pragma("unroll")                                                          \
    for (int it_ = 0; it_ < 2; it_++) {                                        \
        int li_ = tid + it_ * 256;                                             \
        int row_ = li_ >> 3, c8_ = li_ & 7;                                    \
        uint32_t db_ = (STB) + STG_BH + (uint32_t)(row_ * SAS + c8_ * 8) * 2;  \
        cpasync16(db_,                    &Bh[(size_t)row_ * NN + (K0) + c8_ * 8]); \
        cpasync16(db_ + (STG_BL - STG_BH), &Bl[(size_t)row_ * NN + (K0) + c8_ * 8]); \
    }                                                                          \
    asm volatile("cp.async.commit_group;");                                    \
} while (0)

// small-K (64) issue: A/B row stride 64
__device__ __forceinline__ void sk_issue(const __nv_bfloat16* AH, const __nv_bfloat16* AL,
                                         const __nv_bfloat16* BH, const __nv_bfloat16* BL,
                                         uint32_t stb, int tid, bool withA) {
    if (withA) {
#pragma unroll
        for (int it = 0; it < 4; it++) {
            int li = tid + it * 256;
            int row = li >> 3, c8 = li & 7;
            uint32_t da = stb + (uint32_t)(row * SAS + c8 * 8) * 2;
            cpasync16(da,          &AH[row * 64 + c8 * 8]);
            cpasync16(da + STG_AL, &AL[row * 64 + c8 * 8]);
        }
    }
#pragma unroll
    for (int it = 0; it < 2; it++) {
        int li = tid + it * 256;
        int row = li >> 3, c8 = li & 7;
        uint32_t db = stb + STG_BH + (uint32_t)(row * SAS + c8 * 8) * 2;
        cpasync16(db,                     &BH[row * 64 + c8 * 8]);
        cpasync16(db + (STG_BL - STG_BH), &BL[row * 64 + c8 * 8]);
    }
    asm volatile("cp.async.commit_group;");
}

// paired-prop issue: A + 2 B-tiles (both row stride NN)
__device__ __forceinline__ void p2_issue(
        const __nv_bfloat16* Ah, const __nv_bfloat16* Al,
        const __nv_bfloat16* B0h, const __nv_bfloat16* B0l,
        const __nv_bfloat16* B1h, const __nv_bfloat16* B1l,
        int m0, int k0, uint32_t stb, int tid) {
#pragma unroll
    for (int it = 0; it < 4; it++) {
        int li = tid + it * 256;
        int row = li >> 3, c8 = li & 7;
        uint32_t da = stb + (uint32_t)(row * SAS + c8 * 8) * 2;
        cpasync16(da,         &Ah[(size_t)(m0 + row) * NN + k0 + c8 * 8]);
        cpasync16(da + P2_AL, &Al[(size_t)(m0 + row) * NN + k0 + c8 * 8]);
    }
#pragma unroll
    for (int it = 0; it < 2; it++) {
        int li = tid + it * 256;
        int row = li >> 3, c8 = li & 7;
        uint32_t db = stb + (uint32_t)(row * SAS + c8 * 8) * 2;
        cpasync16(db + P2_B0H, &B0h[(size_t)row * NN + k0 + c8 * 8]);
        cpasync16(db + P2_B0L, &B0l[(size_t)row * NN + k0 + c8 * 8]);
        cpasync16(db + P2_B1H, &B1h[(size_t)row * NN + k0 + c8 * 8]);
        cpasync16(db + P2_B1L, &B1l[(size_t)row * NN + k0 + c8 * 8]);
    }
    asm volatile("cp.async.commit_group;");
}

// variable-NC chunk-table pipelined loop (A always present)
#define MMA_CHUNKLOOP(NCV) do {                                                \
    sk_issue(cah[0], cal[0], cbh[0], cbl[0], stb[0], tid, true);               \
    for (int c = 0; c < (NCV); c++) {                                          \
        if (c + 1 < (NCV)) {                                                   \
            sk_issue(cah[c+1], cal[c+1], cbh[c+1], cbl[c+1],                   \
                     stb[(c+1) & 1], tid, true);                               \
            asm volatile("cp.async.wait_group 1;");                            \
        } else {                                                               \
            asm volatile("cp.async.wait_group 0;");                            \
        }                                                                      \
        __syncthreads();                                                       \
        uint32_t aAh = stb[c & 1];                                             \
        uint32_t aAl = aAh + STG_AL;                                           \
        uint32_t aBh = aAh + STG_BH;                                           \
        uint32_t aBl = aAh + STG_BL;                                           \
        MMA_CHUNK3();                                                          \
        __syncthreads();                                                       \
    }                                                                          \
} while (0)

// pointer T-plane writer (tbuf stride 65 floats)
#define TPLANE_WRITE_PTR(TB, OH, OL) do {                                      \
    int d_ = tid >> 2, nc_ = (tid & 3) * 32;                                   \
    size_t ob_ = (size_t)d_ * NN + m0 + nc_;                                   \
    _Pragma("unroll")                                                          \
    for (int q_ = 0; q_ < 32; q_ += 2) {                                       \
        float v0_ = (TB)[(nc_ + q_) * 65 + d_];                                \
        float v1_ = (TB)[(nc_ + q_ + 1) * 65 + d_];                            \
        __nv_bfloat16 h0_ = __float2bfloat16(v0_);                             \
        __nv_bfloat16 h1_ = __float2bfloat16(v1_);                             \
        __nv_bfloat16 l0_ = __float2bfloat16(v0_ - __bfloat162float(h0_));     \
        __nv_bfloat16 l1_ = __float2bfloat16(v1_ - __bfloat162float(h1_));     \
        *(__nv_bfloat162*)&(OH)[ob_ + q_] = __halves2bfloat162(h0_, h1_);      \
        *(__nv_bfloat162*)&(OL)[ob_ + q_] = __halves2bfloat162(l0_, l1_);      \
    }                                                                          \
} while (0)

// prop epilogue: acc -> bf16 hi/lo row-major
#define PROP_EPI(ACC, OH, OL) do {                                             \
    _Pragma("unroll")                                                          \
    for (int mi = 0; mi < 2; mi++) {                                           \
        int r0 = m0 + wm * 32 + mi * 16 + (lane >> 2);                         \
        _Pragma("unroll")                                                      \
        for (int nf = 0; nf < 4; nf++) {                                       \
            int d0 = wn * 32 + nf * 8 + (lane & 3) * 2;                        \
            _Pragma("unroll")                                                  \
            for (int half = 0; half < 2; half++) {                             \
                int r = r0 + half * 8;                                         \
                float v0 = (ACC)[mi][nf][half * 2];                            \
                float v1 = (ACC)[mi][nf][half * 2 + 1];                        \
                __nv_bfloat16 h0 = __float2bfloat16(v0);                       \
                __nv_bfloat16 h1 = __float2bfloat16(v1);                       \
                __nv_bfloat16 l0 = __float2bfloat16(v0 - __bfloat162float(h0));\
                __nv_bfloat16 l1 = __float2bfloat16(v1 - __bfloat162float(h1));\
                *(__nv_bfloat162*)&(OH)[(size_t)r * 64 + d0] =                 \
                    __halves2bfloat162(h0, h1);                                \
                *(__nv_bfloat162*)&(OL)[(size_t)r * 64 + d0] =                 \
                    __halves2bfloat162(l0, l1);                                \
            }                                                                  \
        }                                                                      \
    }                                                                          \
} while (0)

// ================= adjacency normalization =================
__global__ void k_norm_adj(const float* __restrict__ adj,
        __nv_bfloat16* __restrict__ a1h, __nv_bfloat16* __restrict__ a1l,
        __nv_bfloat16* __restrict__ a2h, __nv_bfloat16* __restrict__ a2l) {
    int v = blockIdx.x;
    int tid = threadIdx.x;
    __shared__ float r1[256], r2[256];
    float s1 = 0.f, s2 = 0.f;
    for (int n = tid; n < NN; n += 256) {
        s1 += adj[(size_t)v * NN + n];
        s2 += adj[(size_t)n * NN + v];
    }
    r1[tid] = s1; r2[tid] = s2;
    __syncthreads();
    for (int off = 128; off > 0; off >>= 1) {
        if (tid < off) { r1[tid] += r1[tid + off]; r2[tid] += r2[tid + off]; }
        __syncthreads();
    }
    float inv1 = 1.f / (r1[0] + 1.f);
    float inv2 = 1.f / (r2[0] + 1.f);
    for (int n = tid; n < NN; n += 256) {
        float d = (n == v) ? 1.f : 0.f;
        float v1 = (adj[(size_t)v * NN + n] + d) * inv1;
        float v2 = (adj[(size_t)n * NN + v] + d) * inv2;
        __nv_bfloat16 h1 = __float2bfloat16(v1);
        __nv_bfloat16 h2 = __float2bfloat16(v2);
        a1h[(size_t)v * NN + n] = h1;
        a1l[(size_t)v * NN + n] = __float2bfloat16(v1 - __bfloat162float(h1));
        a2h[(size_t)v * NN + n] = h2;
        a2l[(size_t)v * NN + n] = __float2bfloat16(v2 - __bfloat162float(h2));
    }
}

// ================= bf16 plane transpose =================
__global__ void __launch_bounds__(256) k_btrans(
        const __nv_bfloat16* __restrict__ i0, __nv_bfloat16* __restrict__ o0,
        const __nv_bfloat16* __restrict__ i1, __nv_bfloat16* __restrict__ o1,
        const __nv_bfloat16* __restrict__ i2, __nv_bfloat16* __restrict__ o2,
        const __nv_bfloat16* __restrict__ i3, __nv_bfloat16* __restrict__ o3) {
    const __nv_bfloat16* in;
    __nv_bfloat16* out;
    switch (blockIdx.z) {
        case 0: in = i0; out = o0; break;
        case 1: in = i1; out = o1; break;
        case 2: in = i2; out = o2; break;
        default: in = i3; out = o3; break;
    }
    int c0 = blockIdx.x * 64, r0 = blockIdx.y * 64;
    __shared__ __nv_bfloat16 t[64][72];
    int tid = threadIdx.x;
#pragma unroll
    for (int it = 0; it < 2; it++) {
        int li = tid + it * 256;
        int row = li >> 3, c8 = (li & 7) * 8;
        *(uint4*)&t[row][c8] = *(const uint4*)&in[(size_t)(r0 + row) * NN + c0 + c8];
    }
    __syncthreads();
#pragma unroll
    for (int it = 0; it < 2; it++) {
        int li = tid + it * 256;
        int c = li >> 3, r8 = (li & 7) * 8;
        __nv_bfloat16 v[8];
#pragma unroll
        for (int q = 0; q < 8; q++) v[q] = t[r8 + q][c];
        *(uint4*)&out[(size_t)(c0 + c) * NN + r0 + r8] = *(uint4*)v;
    }
}

// ================= dec_w1 transpose -> bf16 hi/lo [j][c] =================
__global__ void k_dec_w1t(const float* __restrict__ w1,
                          __nv_bfloat16* __restrict__ dw1h,
                          __nv_bfloat16* __restrict__ dw1l) {
    int idx = blockIdx.x * 256 + threadIdx.x;
    if (idx >= 128 * 64) return;
    int j = idx >> 6, c = idx & 63;
    float v = w1[(size_t)c * 128 + j];
    __nv_bfloat16 h = __float2bfloat16(v);
    dw1h[idx] = h;
    dw1l[idx] = __float2bfloat16(v - __bfloat162float(h));
}

// ================= A^2 precompute =================
__global__ void __launch_bounds__(256)
k_asq(const __nv_bfloat16* __restrict__ a1h, const __nv_bfloat16* __restrict__ a1l,
      const __nv_bfloat16* __restrict__ a1th, const __nv_bfloat16* __restrict__ a1tl,
      const __nv_bfloat16* __restrict__ a2h, const __nv_bfloat16* __restrict__ a2l,
      const __nv_bfloat16* __restrict__ a2th, const __nv_bfloat16* __restrict__ a2tl,
      __nv_bfloat16* __restrict__ q1h, __nv_bfloat16* __restrict__ q1l,
      __nv_bfloat16* __restrict__ q2h, __nv_bfloat16* __restrict__ q2l) {
    int m0 = blockIdx.x * 128;
    int n0 = blockIdx.y * 64;
    int mat = blockIdx.z;
    const __nv_bfloat16* Ah = mat ? a2h : a1h;
    const __nv_bfloat16* Al = mat ? a2l : a1l;
    const __nv_bfloat16* Bh = (mat ? a2th : a1th) + (size_t)n0 * NN;
    const __nv_bfloat16* Bl = (mat ? a2tl : a1tl) + (size_t)n0 * NN;
    __nv_bfloat16* qh = mat ? q2h : q1h;
    __nv_bfloat16* ql = mat ? q2l : q1l;

    extern __shared__ __nv_bfloat16 sb[];
    uint32_t sbase_ = smem_u32(sb);
    uint32_t stb_[2] = {sbase_, sbase_ + STG_SZ};
    int tid = threadIdx.x, lane = tid & 31, wid = tid >> 5;
    int wm = wid >> 1, wn = wid & 1;
    int lr = lane & 15, lc = (lane >> 4) * 8;

    float acc[2][4][4];
#pragma unroll
    for (int i = 0; i < 2; i++)
#pragma unroll
        for (int j = 0; j < 4; j++)
#pragma unroll
            for (int q = 0; q < 4; q++) acc[i][j][q] = 0.f;

    PIPE_ISSUE(0, stb_[0]);
    for (int c_ = 0; c_ < 16; c_++) {
        if (c_ + 1 < 16) {
            PIPE_ISSUE((c_ + 1) * 64, stb_[(c_ + 1) & 1]);
            asm volatile("cp.async.wait_group 1;");
        } else {
            asm volatile("cp.async.wait_group 0;");
        }
        __syncthreads();
        uint32_t aAh = stb_[c_ & 1];
        uint32_t aAl = aAh + STG_AL;
        uint32_t aBh = aAh + STG_BH;
        uint32_t aBl = aAh + STG_BL;
        MMA_CHUNK3();
        __syncthreads();
    }

#pragma unroll
    for (int mi = 0; mi < 2; mi++) {
        int r0 = m0 + wm * 32 + mi * 16 + (lane >> 2);
#pragma unroll
        for (int nf = 0; nf < 4; nf++) {
            int d0 = n0 + wn * 32 + nf * 8 + (lane & 3) * 2;
#pragma unroll
            for (int half = 0; half < 2; half++) {
                int rr = r0 + half * 8;
                float v0 = acc[mi][nf][half * 2], v1 = acc[mi][nf][half * 2 + 1];
                __nv_bfloat16 h0 = __float2bfloat16(v0), h1 = __float2bfloat16(v1);
                __nv_bfloat16 l0 = __float2bfloat16(v0 - __bfloat162float(h0));
                __nv_bfloat16 l1 = __float2bfloat16(v1 - __bfloat162float(h1));
                *(__nv_bfloat162*)&qh[(size_t)rr * NN + d0] = __halves2bfloat162(h0, h1);
                *(__nv_bfloat162*)&ql[(size_t)rr * NN + d0] = __halves2bfloat162(l0, l1);
            }
        }
    }
}

// ================= paired 4-way mma prop (2 bt per block; rec & AR) ===========
__global__ void __launch_bounds__(256)
k_prop4p(const __nv_bfloat16* __restrict__ a1h, const __nv_bfloat16* __restrict__ a1l,
         const __nv_bfloat16* __restrict__ q1h, const __nv_bfloat16* __restrict__ q1l,
         const __nv_bfloat16* __restrict__ a2h, const __nv_bfloat16* __restrict__ a2l,
         const __nv_bfloat16* __restrict__ q2h, const __nv_bfloat16* __restrict__ q2l,
         const __nv_bfloat16* __restrict__ bTh, const __nv_bfloat16* __restrict__ bTl,
         __nv_bfloat16* __restrict__ s1h, __nv_bfloat16* __restrict__ s1l,
         __nv_bfloat16* __restrict__ s2h, __nv_bfloat16* __restrict__ s2l,
         __nv_bfloat16* __restrict__ t1h, __nv_bfloat16* __restrict__ t1l,
         __nv_bfloat16* __restrict__ t2h, __nv_bfloat16* __restrict__ t2l) {
    int m0 = blockIdx.x * 128;
    int g0 = blockIdx.y * 2;
    int z  = blockIdx.z;
    const __nv_bfloat16 *Ah, *Al;
    __nv_bfloat16 *ohb, *olb;
    if (z == 0)      { Ah = a1h; Al = a1l; ohb = s1h; olb = s1l; }
    else if (z == 1) { Ah = q1h; Al = q1l; ohb = s2h; olb = s2l; }
    else if (z == 2) { Ah = a2h; Al = a2l; ohb = t1h; olb = t1l; }
    else             { Ah = q2h; Al = q2l; ohb = t2h; olb = t2l; }
    const __nv_bfloat16* B0h = bTh + (size_t)g0 * 65536;
    const __nv_bfloat16* B0l = bTl + (size_t)g0 * 65536;
    const __nv_bfloat16* B1h = B0h + 65536;
    const __nv_bfloat16* B1l = B0l + 65536;

    extern __shared__ __nv_bfloat16 sb[];
    uint32_t sbase = smem_u32(sb);
    uint32_t stb[2] = {sbase, sbase + P2_SZ};
    int tid = threadIdx.x, lane = tid & 31, wid = tid >> 5;
    int wm = wid >> 1, wn = wid & 1;
    int lr = lane & 15, lc = (lane >> 4) * 8;

    float acc0[2][4][4], acc1[2][4][4];
#pragma unroll
    for (int i = 0; i < 2; i++)
#pragma unroll
        for (int j = 0; j < 4; j++)
#pragma unroll
            for (int q = 0; q < 4; q++) { acc0[i][j][q] = 0.f; acc1[i][j][q] = 0.f; }

    p2_issue(Ah, Al, B0h, B0l, B1h, B1l, m0, 0, stb[0], tid);
    for (int c = 0; c < 16; c++) {
        if (c + 1 < 16) {
            p2_issue(Ah, Al, B0h, B0l, B1h, B1l, m0, (c + 1) * 64,
                     stb[(c + 1) & 1], tid);
            asm volatile("cp.async.wait_group 1;");
        } else {
            asm volatile("cp.async.wait_group 0;");
        }
        __syncthreads();
        uint32_t s = stb[c & 1];
        uint32_t aAh = s, aAl = s + P2_AL;
        uint32_t aB0h = s + P2_B0H, aB0l = s + P2_B0L;
        uint32_t aB1h = s + P2_B1H, aB1l = s + P2_B1L;
        {
            uint32_t af[2][4][4];
            MMA_ALOAD(aAh);
            MMA_BPASS(aB0h, acc0);
            MMA_BPASS(aB1h, acc1);
            MMA_BPASS(aB0l, acc0);
            MMA_BPASS(aB1l, acc1);
            MMA_ALOAD(aAl);
            MMA_BPASS(aB0h, acc0);
            MMA_BPASS(aB1h, acc1);
        }
        __syncthreads();
    }
    __nv_bfloat16* oh0 = ohb + (size_t)g0 * 65536;
    __nv_bfloat16* ol0 = olb + (size_t)g0 * 65536;
    __nv_bfloat16* oh1 = oh0 + 65536;
    __nv_bfloat16* ol1 = ol0 + 65536;
    PROP_EPI(acc0, oh0, ol0);
    PROP_EPI(acc1, oh1, ol1);
}

// ================= combine conv weights (bsum + transposed bf16) ==============
__global__ void k_comb_w(const float* w0, const float* w1, const float* w2,
                         const float* w3, const float* w4, const float* w5,
                         const float* cb0, const float* cb1, const float* cb2,
                         const float* cb3, const float* cb4, const float* cb5,
                         float* __restrict__ bsum,
                         __nv_bfloat16* __restrict__ wctbh,
                         __nv_bfloat16* __restrict__ wctbl) {
    int idx = blockIdx.x * 256 + threadIdx.x;
    if (idx >= 11 * 64 * 64) return;
    int o = idx & 63;
    int c = (idx >> 6) & 63;
    int dt = idx >> 12;
    int dv = dt - 5;
    int ad = dv < 0 ? -dv : dv;
    const float* ws[6] = {w0, w1, w2, w3, w4, w5};
    float acc = 0.f;
    for (int i = ad; i < 6; i++) {
        int K = 2 * i + 1;
        acc += ws[i][(size_t)(o * 64 + c) * K + (dv + i)];
    }
    __nv_bfloat16 h = __float2bfloat16(acc);
    wctbh[(size_t)dt * 4096 + o * 64 + c] = h;
    wctbl[(size_t)dt * 4096 + o * 64 + c] =
        __float2bfloat16(acc - __bfloat162float(h));
    if (dt == 0 && c == 0)
        bsum[o] = cb0[o] + cb1[o] + cb2[o] + cb3[o] + cb4[o] + cb5[o];
}

// ================= combine mixprop weights (eb + transposed bf16) =============
__global__ void k_comb_g(const float* __restrict__ g1w, const float* __restrict__ g1b,
                         const float* __restrict__ g2w, const float* __restrict__ g2b,
                         float* __restrict__ eb,
                         __nv_bfloat16* __restrict__ ecth,
                         __nv_bfloat16* __restrict__ ectl) {
    int idx = blockIdx.x * 256 + threadIdx.x;
    if (idx >= 5 * 4096) return;
    int term = idx >> 12;
    int co = idx & 4095;
    int c = co >> 6, o = co & 63;
    float v;
    if (term == 0) {
        v = g1w[co] + ALPHA * (g1w[4096 + co] + g1w[8192 + co])
          + g2w[co] + ALPHA * (g2w[4096 + co] + g2w[8192 + co]);
    } else if (term == 1) {
        v = BETA * g1w[4096 + co] + ALPHA * BETA * g1w[8192 + co];
    } else if (term == 2) {
        v = BETA * BETA * g1w[8192 + co];
    } else if (term == 3) {
        v = BETA * g2w[4096 + co] + ALPHA * BETA * g2w[8192 + co];
    } else {
        v = BETA * BETA * g2w[8192 + co];
    }
    __nv_bfloat16 h = __float2bfloat16(v);
    ecth[(size_t)term * 4096 + o * 64 + c] = h;
    ectl[(size_t)term * 4096 + o * 64 + c] =
        __float2bfloat16(v - __bfloat162float(h));
    if (idx < 64) eb[idx] = g1b[idx] + g2b[idx];
}

// ================= encoder MLP (emits fp32 res + bf16 hi/lo mirror) ============
__global__ void __launch_bounds__(256) k_enc2(const float* __restrict__ x,
        const float* __restrict__ w1, const float* __restrict__ b1,
        const float* __restrict__ w2, const float* __restrict__ b2,
        float* __restrict__ out,
        __nv_bfloat16* __restrict__ resbh, __nv_bfloat16* __restrict__ resbl) {
    extern __shared__ float sm[];
    float* xst = sm;
    float* w1s = xst + 8 * 132;
    float* hst = w1s + 1024;
    float* Bs  = hst + 128 * 132;
    int n0 = blockIdx.x * 128;
    int f  = blockIdx.y;
    int b  = blockIdx.z;
    int tid = threadIdx.x, tx = tid & 15, ty = tid >> 4;

#pragma unroll
    for (int it = 0; it < 4; it++) {
        int li = tid + it * 256;
        int s = li >> 7, m = li & 127;
        xst[s * 132 + m] = x[((size_t)b * NT + f * SEG + s) * NN + n0 + m];
        w1s[li] = w1[li];
    }
    __syncthreads();

    float acc1[8][8] = {};
#pragma unroll
    for (int k = 0; k < 8; k++) {
        float a_[8], b_[8];
        *(float4*)&a_[0] = *(const float4*)&w1s[k * 128 + ty * 4];
        *(float4*)&a_[4] = *(const float4*)&w1s[k * 128 + 64 + ty * 4];
        *(float4*)&b_[0] = *(const float4*)&xst[k * 132 + tx * 4];
        *(float4*)&b_[4] = *(const float4*)&xst[k * 132 + 64 + tx * 4];
#pragma unroll
        for (int i = 0; i < 8; i++)
#pragma unroll
            for (int j = 0; j < 8; j++)
                acc1[i][j] = fmaf(a_[i], b_[j], acc1[i][j]);
    }
#pragma unroll
    for (int i = 0; i < 8; i++) {
        int j = (i < 4) ? ty * 4 + i : 64 + ty * 4 + (i - 4);
        float bb = b1[j];
        float4 v0, v1;
        v0.x = fmaxf(acc1[i][0] + bb, 0.f); v0.y = fmaxf(acc1[i][1] + bb, 0.f);
        v0.z = fmaxf(acc1[i][2] + bb, 0.f); v0.w = fmaxf(acc1[i][3] + bb, 0.f);
        v1.x = fmaxf(acc1[i][4] + bb, 0.f); v1.y = fmaxf(acc1[i][5] + bb, 0.f);
        v1.z = fmaxf(acc1[i][6] + bb, 0.f); v1.w = fmaxf(acc1[i][7] + bb, 0.f);
        *(float4*)&hst[j * 132 + tx * 4]      = v0;
        *(float4*)&hst[j * 132 + 64 + tx * 4] = v1;
    }
    __syncthreads();

    float acc2[8][4] = {};
    for (int k0 = 0; k0 < 128; k0 += 16) {
        {
            int kk = tid >> 4, n4 = (tid & 15) * 4;
            *(float4*)&Bs[kk * 68 + n4] = *(const float4*)&w2[(size_t)(k0 + kk) * 64 + n4];
        }
        __syncthreads();
#pragma unroll
        for (int k = 0; k < 16; k++) {
            float a_[8], b_[4];
            *(float4*)&a_[0] = *(const float4*)&hst[(k0 + k) * 132 + ty * 4];
            *(float4*)&a_[4] = *(const float4*)&hst[(k0 + k) * 132 + 64 + ty * 4];
            *(float4*)&b_[0] = *(const float4*)&Bs[k * 68 + tx * 4];
#pragma unroll
            for (int i = 0; i < 8; i++)
#pragma unroll
                for (int j = 0; j < 4; j++)
                    acc2[i][j] = fmaf(a_[i], b_[j], acc2[i][j]);
        }
        __syncthreads();
    }
    float4 b2v = *(const float4*)&b2[tx * 4];
#pragma unroll
    for (int i = 0; i < 8; i++) {
        int m = n0 + ((i < 4) ? ty * 4 + i : 64 + ty * 4 + (i - 4));
        float va[4];
        va[0] = acc2[i][0] + b2v.x; va[1] = acc2[i][1] + b2v.y;
        va[2] = acc2[i][2] + b2v.z; va[3] = acc2[i][3] + b2v.w;
        size_t ri = (((size_t)b * FREQ + f) * NN + m) * 64 + tx * 4;
        *(float4*)&out[ri] = make_float4(va[0], va[1], va[2], va[3]);
        __nv_bfloat16 hh[4], ll[4];
#pragma unroll
        for (int q = 0; q < 4; q++) {
            hh[q] = __float2bfloat16(va[q]);
            ll[q] = __float2bfloat16(va[q] - __bfloat162float(hh[q]));
        }
        *(uint2*)&resbh[ri] = *(uint2*)hh;
        *(uint2*)&resbl[ri] = *(uint2*)ll;
    }
}

// ================= decoder stage-2 macro (FFMA, hst[j][m] in smem) ============
#define DEC_STAGE2(A4, M_, SG_) do {                                           \
    M_ = tid >> 1; SG_ = tid & 1;                                              \
    A4[0] = b2[SG_ * 4 + 0]; A4[1] = b2[SG_ * 4 + 1];                          \
    A4[2] = b2[SG_ * 4 + 2]; A4[3] = b2[SG_ * 4 + 3];                          \
    _Pragma("unroll 4")                                                        \
    for (int j = 0; j < 128; j++) {                                            \
        float h = hst[j * 132 + M_];                                           \
        float4 w = *(const float4*)&w2s[j * 8 + SG_ * 4];                      \
        A4[0] = fmaf(h, w.x, A4[0]); A4[1] = fmaf(h, w.y, A4[1]);              \
        A4[2] = fmaf(h, w.z, A4[2]); A4[3] = fmaf(h, w.w, A4[3]);              \
    }                                                                          \
} while (0)

// ===== decoder stage-1 via mma: hidden = relu(src @ w1 + b1) -> hst[j][m] =====
// Needs: Ah/Al (bf16 src, 128 rows x 64), dw1h/dw1l (128x64 B tiles),
// stage smem at sbase, hst fp32 smem. 256 threads.
#define DEC_STAGE1_MMA() do {                                                  \
    float acc0[2][4][4], acc1[2][4][4];                                        \
    _Pragma("unroll")                                                          \
    for (int i = 0; i < 2; i++)                                                \
        _Pragma("unroll")                                                      \
        for (int j = 0; j < 4; j++)                                            \
            _Pragma("unroll")                                                  \
            for (int q = 0; q < 4; q++) { acc0[i][j][q] = 0.f; acc1[i][j][q] = 0.f; } \
    sk_issue(Ah, Al, dw1h, dw1l, stb[0], tid, true);                           \
    sk_issue(Ah, Al, dw1h + 4096, dw1l + 4096, stb[1], tid, false);            \
    asm volatile("cp.async.wait_group 0;");                                    \
    __syncthreads();                                                           \
    {                                                                          \
        uint32_t af[2][4][4];                                                  \
        uint32_t aAh = stb[0], aAl = stb[0] + STG_AL;                          \
        uint32_t aB0h = stb[0] + STG_BH, aB0l = stb[0] + STG_BL;               \
        uint32_t aB1h = stb[1] + STG_BH, aB1l = stb[1] + STG_BL;               \
        MMA_ALOAD(aAh);                                                        \
        MMA_BPASS(aB0h, acc0);                                                 \
        MMA_BPASS(aB1h, acc1);                                                 \
        MMA_BPASS(aB0l, acc0);                                                 \
        MMA_BPASS(aB1l, acc1);                                                 \
        MMA_ALOAD(aAl);                                                        \
        MMA_BPASS(aB0h, acc0);                                                 \
        MMA_BPASS(aB1h, acc1);                                                 \
    }                                                                          \
    __syncthreads();   /* stage region now dead; reuse as hst */               \
    _Pragma("unroll")                                                          \
    for (int mi = 0; mi < 2; mi++) {                                           \
        int m = wm * 32 + mi * 16 + (lane >> 2);                               \
        _Pragma("unroll")                                                      \
        for (int nf = 0; nf < 4; nf++) {                                       \
            int j0 = wn * 32 + nf * 8 + (lane & 3) * 2;                        \
            _Pragma("unroll")                                                  \
            for (int half = 0; half < 2; half++) {                             \
                int mm = m + half * 8;                                         \
                float v0a = acc0[mi][nf][half * 2]     + b1[j0];               \
                float v1a = acc0[mi][nf][half * 2 + 1] + b1[j0 + 1];           \
                float v0b = acc1[mi][nf][half * 2]     + b1[64 + j0];          \
                float v1b = acc1[mi][nf][half * 2 + 1] + b1[64 + j0 + 1];      \
                hst[j0 * 132 + mm]        = fmaxf(v0a, 0.f);                   \
                hst[(j0 + 1) * 132 + mm]  = fmaxf(v1a, 0.f);                   \
                hst[(64 + j0) * 132 + mm] = fmaxf(v0b, 0.f);                   \
                hst[(65 + j0) * 132 + mm] = fmaxf(v1b, 0.f);                   \
            }                                                                  \
        }                                                                      \
    }                                                                          \
    __syncthreads();                                                           \
} while (0)

// ================= decoder MLP for rec (mma stage 1) =================
__global__ void __launch_bounds__(256) k_dec_rec_mma(
        const __nv_bfloat16* __restrict__ resbh, const __nv_bfloat16* __restrict__ resbl,
        const __nv_bfloat16* __restrict__ stbh, const __nv_bfloat16* __restrict__ stbl,
        const __nv_bfloat16* __restrict__ dw1h, const __nv_bfloat16* __restrict__ dw1l,
        const float* __restrict__ b1,
        const float* __restrict__ w2, const float* __restrict__ b2,
        float* __restrict__ out) {
    int n0 = blockIdx.x * 128;
    int f  = blockIdx.y;
    int b  = blockIdx.z;
    extern __shared__ char dsm[];
    uint32_t sbase = smem_u32(dsm);
    uint32_t stb[2] = {sbase, sbase + STG_SZ};
    float* hst = (float*)dsm;                   // reuse stage region
    float* w2s = (float*)(dsm + 2 * STG_SZ);    // 1024 floats
    int tid = threadIdx.x, lane = tid & 31, wid = tid >> 5;
    int wm = wid >> 1, wn = wid & 1;
    int lr = lane & 15, lc = (lane >> 4) * 8;
#pragma unroll
    for (int it = 0; it < 4; it++) w2s[tid + it * 256] = w2[tid + it * 256];
    const __nv_bfloat16 *Ah, *Al;
    if (f == 0) {
        size_t off = (((size_t)b * FREQ) * NN + n0) * 64;
        Ah = resbh + off; Al = resbl + off;
    } else {
        size_t off = (((size_t)b * TREC + f - 1) * NN + n0) * 64;
        Ah = stbh + off; Al = stbl + off;
    }
    DEC_STAGE1_MMA();
    float a4[4];
    int m, sg;
    DEC_STAGE2(a4, m, sg);
#pragma unroll
    for (int q = 0; q < 4; q++) {
        int s = sg * 4 + q;
        out[((size_t)b * NT + f * SEG + s) * NN + n0 + m] = a4[q];
    }
}

// ================= decoder MLP for pred (mma stage 1) =================
__global__ void __launch_bounds__(256) k_dec_pred_mma(
        const __nv_bfloat16* __restrict__ curbh, const __nv_bfloat16* __restrict__ curbl,
        const __nv_bfloat16* __restrict__ dw1h, const __nv_bfloat16* __restrict__ dw1l,
        const float* __restrict__ b1,
        const float* __restrict__ w2, const float* __restrict__ b2,
        float* __restrict__ out) {
    int n0 = blockIdx.x * 128;
    int t  = blockIdx.y;
    int b  = blockIdx.z;
    extern __shared__ char dsm[];
    uint32_t sbase = smem_u32(dsm);
    uint32_t stb[2] = {sbase, sbase + STG_SZ};
    float* hst = (float*)dsm;
    float* w2s = (float*)(dsm + 2 * STG_SZ);
    int tid = threadIdx.x, lane = tid & 31, wid = tid >> 5;
    int wm = wid >> 1, wn = wid & 1;
    int lr = lane & 15, lc = (lane >> 4) * 8;
#pragma unroll
    for (int it = 0; it < 4; it++) w2s[tid + it * 256] = w2[tid + it * 256];
    size_t off = (((size_t)b * 23 + MAXK + t) * NN + n0) * 64;
    const __nv_bfloat16* Ah = curbh + off;
    const __nv_bfloat16* Al = curbl + off;
    DEC_STAGE1_MMA();
    float a4[4];
    int m, sg;
    DEC_STAGE2(a4, m, sg);
    float4 v = make_float4(a4[0], a4[1], a4[2], a4[3]);
    *(float4*)&out[(size_t)b * (NSTEP * SEG * NN) + (size_t)t * 8192
                   + (size_t)(n0 + m) * 8 + sg * 4] = v;
}

// ================= t_inception rec (mma, bf16 in/out) =================
__global__ void __launch_bounds__(256)
k_tconv_mma(const __nv_bfloat16* __restrict__ resbh, const __nv_bfloat16* __restrict__ resbl,
            const __nv_bfloat16* __restrict__ wctbh, const __nv_bfloat16* __restrict__ wctbl,
            const float* __restrict__ bsum,
            __nv_bfloat16* __restrict__ cvbh, __nv_bfloat16* __restrict__ cvbl,
            __nv_bfloat16* __restrict__ cth, __nv_bfloat16* __restrict__ ctl) {
    int m0 = blockIdx.x * 128;
    int bt = blockIdx.y;
    int b = bt / TREC, t = bt % TREC;
    extern __shared__ char dsm[];
    uint32_t sbase = smem_u32(dsm);
    uint32_t stb[2] = {sbase, sbase + STG_SZ};
    float* tbuf = (float*)dsm;          // reuses stage region after mainloop
    int tid = threadIdx.x, lane = tid & 31, wid = tid >> 5;
    int wm = wid >> 1, wn = wid & 1;
    int lr = lane & 15, lc = (lane >> 4) * 8;

    float acc[2][4][4];
#pragma unroll
    for (int i = 0; i < 2; i++)
#pragma unroll
        for (int j = 0; j < 4; j++)
#pragma unroll
            for (int q = 0; q < 4; q++) acc[i][j][q] = 0.f;

    const __nv_bfloat16 *cah[MAXK], *cal[MAXK], *cbh[MAXK], *cbl[MAXK];
    int NC = 0;
    for (int dt = 0; dt < MAXK; dt++) {
        int ts = t + dt - 5;
        if (ts < 0 || ts >= TREC) continue;
        size_t off = (((size_t)b * FREQ + ts) * NN + m0) * 64;
        cah[NC] = resbh + off;
        cal[NC] = resbl + off;
        cbh[NC] = wctbh + (size_t)dt * 4096;
        cbl[NC] = wctbl + (size_t)dt * 4096;
        NC++;
    }
    MMA_CHUNKLOOP(NC);

    const float inv6 = 1.f / 6.f;
    __nv_bfloat16* oh = cvbh + (size_t)bt * 65536;
    __nv_bfloat16* ol = cvbl + (size_t)bt * 65536;
#pragma unroll
    for (int mi = 0; mi < 2; mi++) {
        int rl0 = wm * 32 + mi * 16 + (lane >> 2);
#pragma unroll
        for (int nf = 0; nf < 4; nf++) {
            int d0 = wn * 32 + nf * 8 + (lane & 3) * 2;
            float bs0 = bsum[d0], bs1 = bsum[d0 + 1];
#pragma unroll
            for (int half = 0; half < 2; half++) {
                int rl = rl0 + half * 8;
                float v0 = (acc[mi][nf][half * 2]     + bs0) * inv6;
                float v1 = (acc[mi][nf][half * 2 + 1] + bs1) * inv6;
                tbuf[rl * 65 + d0] = v0; tbuf[rl * 65 + d0 + 1] = v1;
                __nv_bfloat16 h0 = __float2bfloat16(v0);
                __nv_bfloat16 h1 = __float2bfloat16(v1);
                __nv_bfloat16 l0 = __float2bfloat16(v0 - __bfloat162float(h0));
                __nv_bfloat16 l1 = __float2bfloat16(v1 - __bfloat162float(h1));
                size_t oi = (size_t)(m0 + rl) * 64 + d0;
                *(__nv_bfloat162*)&oh[oi] = __halves2bfloat162(h0, h1);
                *(__nv_bfloat162*)&ol[oi] = __halves2bfloat162(l0, l1);
            }
        }
    }
    __syncthreads();
    __nv_bfloat16* toh = cth + (size_t)bt * 65536;
    __nv_bfloat16* tol = ctl + (size_t)bt * 65536;
    TPLANE_WRITE_PTR(tbuf, toh, tol);
}

// ================= combine rec (mma, + bf16 stout mirror) =================
__global__ void __launch_bounds__(256)
k_combine_mma(const __nv_bfloat16* __restrict__ xh, const __nv_bfloat16* __restrict__ xl,
              const __nv_bfloat16* __restrict__ s1h, const __nv_bfloat16* __restrict__ s1l,
              const __nv_bfloat16* __restrict__ s2h, const __nv_bfloat16* __restrict__ s2l,
              const __nv_bfloat16* __restrict__ t1h, const __nv_bfloat16* __restrict__ t1l,
              const __nv_bfloat16* __restrict__ t2h, const __nv_bfloat16* __restrict__ t2l,
              const __nv_bfloat16* __restrict__ ecth, const __nv_bfloat16* __restrict__ ectl,
              const float* __restrict__ eb,
              const float* __restrict__ res, float* __restrict__ stout,
              __nv_bfloat16* __restrict__ stbh, __nv_bfloat16* __restrict__ stbl) {
    int m0 = blockIdx.x * 128;
    int bt = blockIdx.y;
    extern __shared__ char dsm[];
    uint32_t sbase = smem_u32(dsm);
    uint32_t stb[2] = {sbase, sbase + STG_SZ};
    int tid = threadIdx.x, lane = tid & 31, wid = tid >> 5;
    int wm = wid >> 1, wn = wid & 1;
    int lr = lane & 15, lc = (lane >> 4) * 8;

    float acc[2][4][4];
#pragma unroll
    for (int i = 0; i < 2; i++)
#pragma unroll
        for (int j = 0; j < 4; j++)
#pragma unroll
            for (int q = 0; q < 4; q++) acc[i][j][q] = 0.f;

    const __nv_bfloat16 *cah[5], *cal[5], *cbh[5], *cbl[5];
    size_t xb = ((size_t)bt * NN + m0) * 64;
    cah[0] = xh  + xb; cal[0] = xl  + xb;
    cah[1] = s1h + xb; cal[1] = s1l + xb;
    cah[2] = s2h + xb; cal[2] = s2l + xb;
    cah[3] = t1h + xb; cal[3] = t1l + xb;
    cah[4] = t2h + xb; cal[4] = t2l + xb;
#pragma unroll
    for (int j = 0; j < 5; j++) {
        cbh[j] = ecth + (size_t)j * 4096;
        cbl[j] = ectl + (size_t)j * 4096;
    }
    MMA_CHUNKLOOP(5);

    int rrow = (bt / TREC) * FREQ + (bt % TREC);   // resid row = b*42 + t
#pragma unroll
    for (int mi = 0; mi < 2; mi++) {
        int rl0 = wm * 32 + mi * 16 + (lane >> 2);
#pragma unroll
        for (int nf = 0; nf < 4; nf++) {
            int d0 = wn * 32 + nf * 8 + (lane & 3) * 2;
            float e0 = eb[d0], e1 = eb[d0 + 1];
#pragma unroll
            for (int half = 0; half < 2; half++) {
                int m = m0 + rl0 + half * 8;
                float2 rv = *(const float2*)&res[((size_t)rrow * NN + m) * 64 + d0];
                float v0 = acc[mi][nf][half * 2]     + e0 + rv.x;
                float v1 = acc[mi][nf][half * 2 + 1] + e1 + rv.y;
                size_t oi = ((size_t)bt * NN + m) * 64 + d0;
                *(float2*)&stout[oi] = make_float2(v0, v1);
                __nv_bfloat16 h0 = __float2bfloat16(v0);
                __nv_bfloat16 h1 = __float2bfloat16(v1);
                __nv_bfloat16 l0 = __float2bfloat16(v0 - __bfloat162float(h0));
                __nv_bfloat16 l1 = __float2bfloat16(v1 - __bfloat162float(h1));
                *(__nv_bfloat162*)&stbh[oi] = __halves2bfloat162(h0, h1);
                *(__nv_bfloat162*)&stbl[oi] = __halves2bfloat162(l0, l1);
            }
        }
    }
}

// ===== shared epilogue2 for mma tcl =====
#define TCL_EPI2() do {                                                        \
    const float inv6_ = 1.f / 6.f;                                             \
    __nv_bfloat16* xho_ = xoh + (size_t)b * 65536;                             \
    __nv_bfloat16* xlo_ = xol + (size_t)b * 65536;                             \
    _Pragma("unroll")                                                          \
    for (int mi = 0; mi < 2; mi++) {                                           \
        int rl0 = wm * 32 + mi * 16 + (lane >> 2);                             \
        _Pragma("unroll")                                                      \
        for (int nf = 0; nf < 4; nf++) {                                       \
            int d0 = wn * 32 + nf * 8 + (lane & 3) * 2;                        \
            float bs0 = bsum[d0], bs1 = bsum[d0 + 1];                          \
            _Pragma("unroll")                                                  \
            for (int half = 0; half < 2; half++) {                             \
                int rl = rl0 + half * 8;                                       \
                float v0 = (acc[mi][nf][half * 2]     + bs0) * inv6_;          \
                float v1 = (acc[mi][nf][half * 2 + 1] + bs1) * inv6_;          \
                tbuf[rl * 65 + d0] = v0; tbuf[rl * 65 + d0 + 1] = v1;          \
                __nv_bfloat16 h0 = __float2bfloat16(v0);                       \
                __nv_bfloat16 h1 = __float2bfloat16(v1);                       \
                __nv_bfloat16 l0 = __float2bfloat16(v0 - __bfloat162float(h0));\
                __nv_bfloat16 l1 = __float2bfloat16(v1 - __bfloat162float(h1));\
                size_t oi = (size_t)(m0 + rl) * 64 + d0;                       \
                *(__nv_bfloat162*)&xho_[oi] = __halves2bfloat162(h0, h1);      \
                *(__nv_bfloat162*)&xlo_[oi] = __halves2bfloat162(l0, l1);      \
            }                                                                  \
        }                                                                      \
    }                                                                          \
    __syncthreads();                                                           \
    __nv_bfloat16* toh_ = tclth + (size_t)b * 65536;                           \
    __nv_bfloat16* tol_ = tcltl + (size_t)b * 65536;                           \
    TPLANE_WRITE_PTR(tbuf, toh_, tol_);                                        \
} while (0)

// ================= AR tcl step 0 (mma) =================
__global__ void __launch_bounds__(256)
k_tcl0_mma(const __nv_bfloat16* __restrict__ curbh, const __nv_bfloat16* __restrict__ curbl,
           const __nv_bfloat16* __restrict__ wctbh, const __nv_bfloat16* __restrict__ wctbl,
           const float* __restrict__ bsum,
           __nv_bfloat16* __restrict__ tclth, __nv_bfloat16* __restrict__ tcltl,
           __nv_bfloat16* __restrict__ xoh, __nv_bfloat16* __restrict__ xol) {
    int m0 = blockIdx.x * 128;
    int b  = blockIdx.y;
    extern __shared__ char dsm[];
    uint32_t sbase = smem_u32(dsm);
    uint32_t stb[2] = {sbase, sbase + STG_SZ};
    float* tbuf = (float*)dsm;
    int tid = threadIdx.x, lane = tid & 31, wid = tid >> 5;
    int wm = wid >> 1, wn = wid & 1;
    int lr = lane & 15, lc = (lane >> 4) * 8;

    float acc[2][4][4];
#pragma unroll
    for (int i = 0; i < 2; i++)
#pragma unroll
        for (int j = 0; j < 4; j++)
#pragma unroll
            for (int q = 0; q < 4; q++) acc[i][j][q] = 0.f;

    const __nv_bfloat16 *cah[6], *cal[6], *cbh[6], *cbl[6];
#pragma unroll
    for (int j = 0; j < 6; j++) {
        size_t off = ((size_t)(b * 23 + 5 + j) * NN + m0) * 64;
        cah[j] = curbh + off;
        cal[j] = curbl + off;
        cbh[j] = wctbh + (size_t)j * 4096;
        cbl[j] = wctbl + (size_t)j * 4096;
    }
    MMA_CHUNKLOOP(6);
    TCL_EPI2();
}

// ================= fused AR combine(step s) + tcl(step s+1) (mma) =============
__global__ void __launch_bounds__(256)
k_comb_tcl_mma(const __nv_bfloat16* __restrict__ xh, const __nv_bfloat16* __restrict__ xl,
               const __nv_bfloat16* __restrict__ s1h, const __nv_bfloat16* __restrict__ s1l,
               const __nv_bfloat16* __restrict__ s2h, const __nv_bfloat16* __restrict__ s2l,
               const __nv_bfloat16* __restrict__ t1h, const __nv_bfloat16* __restrict__ t1l,
               const __nv_bfloat16* __restrict__ t2h, const __nv_bfloat16* __restrict__ t2l,
               const __nv_bfloat16* __restrict__ ecth, const __nv_bfloat16* __restrict__ ectl,
               const float* __restrict__ eb,
               const __nv_bfloat16* __restrict__ wctbh, const __nv_bfloat16* __restrict__ wctbl,
               const float* __restrict__ bsum,
               float* __restrict__ cur,
               __nv_bfloat16* __restrict__ curbh, __nv_bfloat16* __restrict__ curbl,
               __nv_bfloat16* __restrict__ tclth, __nv_bfloat16* __restrict__ tcltl,
               __nv_bfloat16* __restrict__ xoh, __nv_bfloat16* __restrict__ xol,
               int s) {
    int m0 = blockIdx.x * 128;
    int b  = blockIdx.y;
    extern __shared__ char dsm[];
    uint32_t sbase = smem_u32(dsm);
    uint32_t stb[2] = {sbase, sbase + STG_SZ};
    __nv_bfloat16* xsh = (__nv_bfloat16*)(dsm + 2 * STG_SZ);
    __nv_bfloat16* xsl = (__nv_bfloat16*)(dsm + 2 * STG_SZ + 18432);
    uint32_t axsh = sbase + 2 * STG_SZ;
    uint32_t axsl = axsh + 18432;
    float* tbuf = (float*)dsm;           // reuse stage region after mainloop
    int tid = threadIdx.x, lane = tid & 31, wid = tid >> 5;
    int wm = wid >> 1, wn = wid & 1;
    int lr = lane & 15, lc = (lane >> 4) * 8;

    float acc[2][4][4];
#pragma unroll
    for (int i = 0; i < 2; i++)
#pragma unroll
        for (int j = 0; j < 4; j++)
#pragma unroll
            for (int q = 0; q < 4; q++) acc[i][j][q] = 0.f;

    const __nv_bfloat16* cah[10];
    const __nv_bfloat16* cal[10];
    size_t xb = ((size_t)b * NN + m0) * 64;
    cah[0] = xh  + xb; cal[0] = xl  + xb;
    cah[1] = s1h + xb; cal[1] = s1l + xb;
    cah[2] = s2h + xb; cal[2] = s2l + xb;
    cah[3] = t1h + xb; cal[3] = t1l + xb;
    cah[4] = t2h + xb; cal[4] = t2l + xb;
#pragma unroll
    for (int j = 0; j < 5; j++) {
        size_t off = ((size_t)(b * 23 + s + 6 + j) * NN + m0) * 64;
        cah[5 + j] = curbh + off;
        cal[5 + j] = curbl + off;
    }
    const int NC = (s == NSTEP - 1) ? 5 : 11;

    sk_issue(cah[0], cal[0], ecth, ectl, stb[0], tid, true);
    for (int c = 0; c < NC; c++) {
        if (c + 1 < NC) {
            const __nv_bfloat16 *nbh, *nbl;
            int cn = c + 1;
            if (cn < 5) { nbh = ecth + (size_t)cn * 4096; nbl = ectl + (size_t)cn * 4096; }
            else        { nbh = wctbh + (size_t)(cn - 5) * 4096; nbl = wctbl + (size_t)(cn - 5) * 4096; }
            bool withA = (cn != 10);
            sk_issue(withA ? cah[cn] : cah[0], withA ? cal[cn] : cal[0],
                     nbh, nbl, stb[cn & 1], tid, withA);
            asm volatile("cp.async.wait_group 1;");
        } else {
            asm volatile("cp.async.wait_group 0;");
        }
        __syncthreads();
        uint32_t aAh = (c == 10) ? axsh : stb[c & 1];
        uint32_t aAl = (c == 10) ? axsl : (stb[c & 1] + STG_AL);
        uint32_t aBh = stb[c & 1] + STG_BH;
        uint32_t aBl = stb[c & 1] + STG_BL;
        MMA_CHUNK3();
        __syncthreads();
        if (c == 4) {
            const float* curr = cur + (size_t)(b * 23 + s + 10) * NN * 64;
            float* curw = cur + (size_t)(b * 23 + s + 11) * NN * 64;
            __nv_bfloat16* cbh2 = curbh + (size_t)(b * 23 + s + 11) * NN * 64;
            __nv_bfloat16* cbl2 = curbl + (size_t)(b * 23 + s + 11) * NN * 64;
#pragma unroll
            for (int mi = 0; mi < 2; mi++) {
                int rl0 = wm * 32 + mi * 16 + (lane >> 2);
#pragma unroll
                for (int nf = 0; nf < 4; nf++) {
                    int d0 = wn * 32 + nf * 8 + (lane & 3) * 2;
                    float e0 = eb[d0], e1 = eb[d0 + 1];
#pragma unroll
                    for (int half = 0; half < 2; half++) {
                        int rl = rl0 + half * 8;
                        int m = m0 + rl;
                        float2 rv = *(const float2*)&curr[(size_t)m * 64 + d0];
                        float v0 = acc[mi][nf][half * 2]     + e0 + rv.x;
                        float v1 = acc[mi][nf][half * 2 + 1] + e1 + rv.y;
                        *(float2*)&curw[(size_t)m * 64 + d0] = make_float2(v0, v1);
                        __nv_bfloat16 h0 = __float2bfloat16(v0);
                        __nv_bfloat16 h1 = __float2bfloat16(v1);
                        __nv_bfloat16 l0 = __float2bfloat16(v0 - __bfloat162float(h0));
                        __nv_bfloat16 l1 = __float2bfloat16(v1 - __bfloat162float(h1));
                        *(__nv_bfloat162*)&cbh2[(size_t)m * 64 + d0] = __halves2bfloat162(h0, h1);
                        *(__nv_bfloat162*)&cbl2[(size_t)m * 64 + d0] = __halves2bfloat162(l0, l1);
                        *(__nv_bfloat162*)&xsh[rl * SAS + d0] = __halves2bfloat162(h0, h1);
                        *(__nv_bfloat162*)&xsl[rl * SAS + d0] = __halves2bfloat162(l0, l1);
                    }
                }
            }
#pragma unroll
            for (int i = 0; i < 2; i++)
#pragma unroll
                for (int j = 0; j < 4; j++)
#pragma unroll
                    for (int q = 0; q < 4; q++) acc[i][j][q] = 0.f;
            __syncthreads();
        }
    }
    if (NC == 11) {
        TCL_EPI2();
    }
}

// ================= AR cur-buffer init (+ bf16 mirror) =================
__global__ void k_cur_init(const float* __restrict__ res, float* __restrict__ cur,
                           __nv_bfloat16* __restrict__ curbh,
                           __nv_bfloat16* __restrict__ curbl) {
    size_t total = (size_t)NB * MAXK * NN * 64;
    for (size_t idx = (size_t)blockIdx.x * blockDim.x + threadIdx.x; idx < total;
         idx += (size_t)gridDim.x * blockDim.x) {
        int d = idx & 63;
        int n = (idx >> 6) & 1023;
        int j = (int)((idx >> 16) % MAXK);
        int b = (int)(idx / ((size_t)MAXK << 16));
        float v = res[(((size_t)b * FREQ + 31 + j) * NN + n) * 64 + d];
        size_t dst = (((size_t)b * 23 + j) * NN + n) * 64 + d;
        cur[dst] = v;
        __nv_bfloat16 h = __float2bfloat16(v);
        curbh[dst] = h;
        curbl[dst] = __float2bfloat16(v - __bfloat162float(h));
    }
}

// ================= host launcher =================
extern "C" void kernel_launch(void* const* d_in, const int* in_sizes, int n_in,
                              void* d_out, int out_size) {
    (void)in_sizes; (void)n_in; (void)out_size;
    const float* x_diff = (const float*)d_in[0];
    const float* adj    = (const float*)d_in[1];
    const float* enc_w1 = (const float*)d_in[2];
    const float* enc_b1 = (const float*)d_in[3];
    const float* enc_w2 = (const float*)d_in[4];
    const float* enc_b2 = (const float*)d_in[5];
    const float* dec_w1 = (const float*)d_in[6];
    const float* dec_b1 = (const float*)d_in[7];
    const float* dec_w2 = (const float*)d_in[8];
    const float* dec_b2 = (const float*)d_in[9];
    const float* g1_w   = (const float*)d_in[10];
    const float* g1_b   = (const float*)d_in[11];
    const float* g2_w   = (const float*)d_in[12];
    const float* g2_b   = (const float*)d_in[13];
    const float* cw[6], *cb[6];
    for (int i = 0; i < 6; i++) {
        cw[i] = (const float*)d_in[14 + 2 * i];
        cb[i] = (const float*)d_in[15 + 2 * i];
    }

    float* scratch = nullptr;
    cudaGetSymbolAddress((void**)&scratch, g_scratch);
    float* bsum  = scratch + OFF_BSUM;
    float* eb    = scratch + OFF_EB;
    __nv_bfloat16* a1h  = (__nv_bfloat16*)(scratch + OFF_A1H);
    __nv_bfloat16* a1l  = (__nv_bfloat16*)(scratch + OFF_A1L);
    __nv_bfloat16* a2h  = (__nv_bfloat16*)(scratch + OFF_A2H);
    __nv_bfloat16* a2l  = (__nv_bfloat16*)(scratch + OFF_A2L);
    __nv_bfloat16* a1th = (__nv_bfloat16*)(scratch + OFF_A1TH);
    __nv_bfloat16* a1tl = (__nv_bfloat16*)(scratch + OFF_A1TL);
    __nv_bfloat16* a2th = (__nv_bfloat16*)(scratch + OFF_A2TH);
    __nv_bfloat16* a2tl = (__nv_bfloat16*)(scratch + OFF_A2TL);
    __nv_bfloat16* q1h  = (__nv_bfloat16*)(scratch + OFF_Q1H);
    __nv_bfloat16* q1l  = (__nv_bfloat16*)(scratch + OFF_Q1L);
    __nv_bfloat16* q2h  = (__nv_bfloat16*)(scratch + OFF_Q2H);
    __nv_bfloat16* q2l  = (__nv_bfloat16*)(scratch + OFF_Q2L);
    float* res   = scratch + OFF_RES;
    float* stout = scratch + OFF_STOUT;
    float* cur   = scratch + OFF_CUR;
    __nv_bfloat16* resbh = (__nv_bfloat16*)(scratch + OFF_RESBH);
    __nv_bfloat16* resbl = (__nv_bfloat16*)(scratch + OFF_RESBL);
    __nv_bfloat16* cvbh  = (__nv_bfloat16*)(scratch + OFF_CVBH);
    __nv_bfloat16* cvbl  = (__nv_bfloat16*)(scratch + OFF_CVBL);
    __nv_bfloat16* cth   = (__nv_bfloat16*)(scratch + OFF_CTH);
    __nv_bfloat16* ctl   = (__nv_bfloat16*)(scratch + OFF_CTL);
    __nv_bfloat16* rs1h  = (__nv_bfloat16*)(scratch + OFF_RS1H);
    __nv_bfloat16* rs1l  = (__nv_bfloat16*)(scratch + OFF_RS1L);
    __nv_bfloat16* rs2h  = (__nv_bfloat16*)(scratch + OFF_RS2H);
    __nv_bfloat16* rs2l  = (__nv_bfloat16*)(scratch + OFF_RS2L);
    __nv_bfloat16* rt1h  = (__nv_bfloat16*)(scratch + OFF_RT1H);
    __nv_bfloat16* rt1l  = (__nv_bfloat16*)(scratch + OFF_RT1L);
    __nv_bfloat16* rt2h  = (__nv_bfloat16*)(scratch + OFF_RT2H);
    __nv_bfloat16* rt2l  = (__nv_bfloat16*)(scratch + OFF_RT2L);
    __nv_bfloat16* tclth = (__nv_bfloat16*)(scratch + OFF_TCTH);
    __nv_bfloat16* tcltl = (__nv_bfloat16*)(scratch + OFF_TCTL);
    __nv_bfloat16* ecth  = (__nv_bfloat16*)(scratch + OFF_ECTH);
    __nv_bfloat16* ectl  = (__nv_bfloat16*)(scratch + OFF_ECTL);
    __nv_bfloat16* wctbh = (__nv_bfloat16*)(scratch + OFF_WCTBH);
    __nv_bfloat16* wctbl = (__nv_bfloat16*)(scratch + OFF_WCTBL);
    __nv_bfloat16* curbh = (__nv_bfloat16*)(scratch + OFF_CURBH);
    __nv_bfloat16* curbl = (__nv_bfloat16*)(scratch + OFF_CURBL);
    __nv_bfloat16* xoh   = (__nv_bfloat16*)(scratch + OFF_XOH);
    __nv_bfloat16* xol   = (__nv_bfloat16*)(scratch + OFF_XOL);
    __nv_bfloat16* s1h   = (__nv_bfloat16*)(scratch + OFF_S1H);
    __nv_bfloat16* s1l   = (__nv_bfloat16*)(scratch + OFF_S1L);
    __nv_bfloat16* s2h   = (__nv_bfloat16*)(scratch + OFF_S2H);
    __nv_bfloat16* s2l   = (__nv_bfloat16*)(scratch + OFF_S2L);
    __nv_bfloat16* t1h   = (__nv_bfloat16*)(scratch + OFF_T1H);
    __nv_bfloat16* t1l   = (__nv_bfloat16*)(scratch + OFF_T1L);
    __nv_bfloat16* t2h   = (__nv_bfloat16*)(scratch + OFF_T2H);
    __nv_bfloat16* t2l   = (__nv_bfloat16*)(scratch + OFF_T2L);
    __nv_bfloat16* stbh  = (__nv_bfloat16*)(scratch + OFF_STBH);
    __nv_bfloat16* stbl  = (__nv_bfloat16*)(scratch + OFF_STBL);
    __nv_bfloat16* dw1h  = (__nv_bfloat16*)(scratch + OFF_DW1H);
    __nv_bfloat16* dw1l  = (__nv_bfloat16*)(scratch + OFF_DW1L);

    float* rec_out  = (float*)d_out;
    float* pred_out = rec_out + (size_t)NB * NT * NN;

    const int ENC_SMEM  = (8 * 132 + 1024 + 128 * 132 + 16 * 68) * 4;
    const int MMA_SMEM  = 2 * STG_SZ;                 // 110592
    const int P2_SMEM   = 2 * P2_SZ;                  // 147456 (paired prop)
    const int CT_SMEM   = 2 * STG_SZ + 36864;         // 147456 (comb_tcl)
    const int DECM_SMEM = 2 * STG_SZ + 4096;          // 114688 (dec mma)
    cudaFuncSetAttribute(k_enc2, cudaFuncAttributeMaxDynamicSharedMemorySize, ENC_SMEM);
    cudaFuncSetAttribute(k_dec_rec_mma, cudaFuncAttributeMaxDynamicSharedMemorySize, DECM_SMEM);
    cudaFuncSetAttribute(k_dec_pred_mma, cudaFuncAttributeMaxDynamicSharedMemorySize, DECM_SMEM);
    cudaFuncSetAttribute(k_prop4p, cudaFuncAttributeMaxDynamicSharedMemorySize, P2_SMEM);
    cudaFuncSetAttribute(k_asq, cudaFuncAttributeMaxDynamicSharedMemorySize, MMA_SMEM);
    cudaFuncSetAttribute(k_tconv_mma, cudaFuncAttributeMaxDynamicSharedMemorySize, MMA_SMEM);
    cudaFuncSetAttribute(k_combine_mma, cudaFuncAttributeMaxDynamicSharedMemorySize, MMA_SMEM);
    cudaFuncSetAttribute(k_tcl0_mma, cudaFuncAttributeMaxDynamicSharedMemorySize, MMA_SMEM);
    cudaFuncSetAttribute(k_comb_tcl_mma, cudaFuncAttributeMaxDynamicSharedMemorySize, CT_SMEM);

    // ---- preprocessing ----
    k_norm_adj<<<NN, 256>>>(adj, a1h, a1l, a2h, a2l);
    k_btrans<<<dim3(16, 16, 4), 256>>>(a1h, a1th, a1l, a1tl, a2h, a2th, a2l, a2tl);
    k_comb_w<<<(11 * 64 * 64 + 255) / 256, 256>>>(cw[0], cw[1], cw[2], cw[3], cw[4], cw[5],
                                                  cb[0], cb[1], cb[2], cb[3], cb[4], cb[5],
                                                  bsum, wctbh, wctbl);
    k_comb_g<<<80, 256>>>(g1_w, g1_b, g2_w, g2_b, eb, ecth, ectl);
    k_dec_w1t<<<32, 256>>>(dec_w1, dw1h, dw1l);
    k_asq<<<dim3(8, 16, 2), 256, MMA_SMEM>>>(a1h, a1l, a1th, a1tl,
                                             a2h, a2l, a2th, a2tl,
                                             q1h, q1l, q2h, q2l);

    // ---- encoder ----
    k_enc2<<<dim3(8, FREQ, NB), 256, ENC_SMEM>>>(x_diff, enc_w1, enc_b1, enc_w2, enc_b2,
                                                 res, resbh, resbl);

    // ---- rec-path stconv (all mma) ----
    k_tconv_mma<<<dim3(8, NB * TREC), 256, MMA_SMEM>>>(resbh, resbl, wctbh, wctbl, bsum,
                                                       cvbh, cvbl, cth, ctl);
    k_prop4p<<<dim3(8, NB * TREC / 2, 4), 256, P2_SMEM>>>(
        a1h, a1l, q1h, q1l, a2h, a2l, q2h, q2l,
        cth, ctl, rs1h, rs1l, rs2h, rs2l, rt1h, rt1l, rt2h, rt2l);
    k_combine_mma<<<dim3(8, NB * TREC), 256, MMA_SMEM>>>(
        cvbh, cvbl, rs1h, rs1l, rs2h, rs2l, rt1h, rt1l, rt2h, rt2l,
        ecth, ectl, eb, res, stout, stbh, stbl);
    // ---- rec decoder (mma stage 1) ----
    k_dec_rec_mma<<<dim3(8, FREQ, NB), 256, DECM_SMEM>>>(
        resbh, resbl, stbh, stbl, dw1h, dw1l, dec_b1, dec_w2, dec_b2, rec_out);

    // ---- autoregressive loop ----
    k_cur_init<<<4096, 256>>>(res, cur, curbh, curbl);
    k_tcl0_mma<<<dim3(8, NB), 256, MMA_SMEM>>>(curbh, curbl, wctbh, wctbl, bsum,
                                               tclth, tcltl, xoh, xol);
    for (int s = 0; s < NSTEP; s++) {
        k_prop4p<<<dim3(8, NB / 2, 4), 256, P2_SMEM>>>(
            a1h, a1l, q1h, q1l, a2h, a2l, q2h, q2l,
            tclth, tcltl, s1h, s1l, s2h, s2l, t1h, t1l, t2h, t2l);
        k_comb_tcl_mma<<<dim3(8, NB), 256, CT_SMEM>>>(
            xoh, xol, s1h, s1l, s2h, s2l, t1h, t1l, t2h, t2l,
            ecth, ectl, eb, wctbh, wctbl, bsum,
            cur, curbh, curbl, tclth, tcltl, xoh, xol, s);
    }
    // ---- pred decoder (mma stage 1) ----
    k_dec_pred_mma<<<dim3(8, NSTEP, NB), 256, DECM_SMEM>>>(
        curbh, curbl, dw1h, dw1l, dec_b1, dec_w2, dec_b2, pred_out);
}